// round 1
// baseline (speedup 1.0000x reference)
#include <cuda_runtime.h>
#include <math.h>

// Problem constants
#define B_   8
#define N_   1024
#define C_   768
#define H_   12
#define HD_  64
#define BH_  (B_*H_)                       // 96
#define TWO_C_ (2*C_)                      // 1536
#define M_ROWS (B_*N_)                     // 8192

static const size_t KV_ELEMS   = (size_t)BH_ * N_ * HD_;   // 6,291,456
static const size_t OUT_ELEMS  = (size_t)B_ * N_ * C_;     // 6,291,456
static const size_t ATTN_ELEMS = (size_t)BH_ * N_ * N_;    // 100,663,296

#define SCALE_ 0.125f
#define LAMBD_ 4.0f

// ---------------- device scratch (static allocation: allowed) ----------------
__device__ float g_k [6291456];
__device__ float g_v [6291456];
__device__ float g_l [6291456];
__device__ float g_y [6291456];
__device__ float g_s [6291456];
__device__ float g_k2[6291456];
__device__ float g_obnc[6291456];
__device__ float g_mu[96];
__device__ float g_attn_fallback[100663296];  // only used if d_out doesn't hold attn

// ---------------- elementwise ----------------
__global__ void zero_ly_kernel() {
    size_t i = (size_t)blockIdx.x * 256 + threadIdx.x;
    if (i < KV_ELEMS) { g_l[i] = 0.f; g_y[i] = 0.f; }
}

__global__ void k2_kernel() {
    size_t i = (size_t)blockIdx.x * 256 + threadIdx.x;
    if (i >= KV_ELEMS) return;
    int bh = (int)(i / ((size_t)N_ * HD_));
    float mu  = g_mu[bh];
    float kk  = g_k[i];
    float l   = g_l[i];
    float ymu = g_y[i] / mu;
    float t   = kk - l + ymu;
    float lm  = LAMBD_ * mu;
    float s   = (t >= lm) ? (t - lm) : ((t <= -lm) ? (t + lm) : 0.f);
    g_s[i]  = s;
    g_k2[i] = kk - s - ymu;
}

__global__ void y_update_kernel() {
    size_t i = (size_t)blockIdx.x * 256 + threadIdx.x;
    if (i >= KV_ELEMS) return;
    int bh = (int)(i / ((size_t)N_ * HD_));
    float mu = g_mu[bh];
    g_y[i] += mu * (g_k[i] - g_l[i] - g_s[i]);
}

// ---------------- mu reduction: one block per (b,h) ----------------
__global__ void mu_kernel() {
    __shared__ float red[256];
    int bh = blockIdx.x;
    const float* p = g_k + (size_t)bh * N_ * HD_;
    float s = 0.f;
    for (int i = threadIdx.x; i < N_ * HD_; i += 256) s += fabsf(p[i]);
    red[threadIdx.x] = s;
    __syncthreads();
    for (int st = 128; st > 0; st >>= 1) {
        if (threadIdx.x < st) red[threadIdx.x] += red[threadIdx.x + st];
        __syncthreads();
    }
    if (threadIdx.x == 0) g_mu[bh] = ((float)N_ * (float)C_ / 4.0f) / red[0];
}

// ---------------- softmax over rows of attn (row length 1024) ----------------
__global__ void softmax_rows_kernel(float* __restrict__ attn) {
    __shared__ float red[256];
    size_t row = blockIdx.x;
    float4* p = reinterpret_cast<float4*>(attn + row * (size_t)N_);
    int tid = threadIdx.x;
    float4 v = p[tid];
    float m = fmaxf(fmaxf(v.x, v.y), fmaxf(v.z, v.w));
    red[tid] = m;
    __syncthreads();
    for (int st = 128; st > 0; st >>= 1) {
        if (tid < st) red[tid] = fmaxf(red[tid], red[tid + st]);
        __syncthreads();
    }
    m = red[0];
    __syncthreads();
    v.x = __expf(v.x - m); v.y = __expf(v.y - m);
    v.z = __expf(v.z - m); v.w = __expf(v.w - m);
    float s = v.x + v.y + v.z + v.w;
    red[tid] = s;
    __syncthreads();
    for (int st = 128; st > 0; st >>= 1) {
        if (tid < st) red[tid] += red[tid + st];
        __syncthreads();
    }
    float inv = 1.0f / red[0];
    v.x *= inv; v.y *= inv; v.z *= inv; v.w *= inv;
    p[tid] = v;
}

// ---------------- GEMM 1: qkv = x @ W_qkv + b, scattered into g_k / g_v ----------------
// x: [8192, 768], W: [768, 1536]. 64x64 tile per block, 4x4 per thread.
__global__ void qkv_gemm_kernel(const float* __restrict__ x,
                                const float* __restrict__ W,
                                const float* __restrict__ bias) {
    __shared__ float As[16][64];
    __shared__ float Bs[16][64];
    const int bx = blockIdx.x * 64;   // output column
    const int by = blockIdx.y * 64;   // output row
    const int tid = threadIdx.x;
    const int tx = tid & 15, ty = tid >> 4;
    float acc[4][4] = {};
    for (int k0 = 0; k0 < C_; k0 += 16) {
        #pragma unroll
        for (int i = 0; i < 4; i++) {
            int idx = tid + i * 256;
            int m = idx >> 4, kk = idx & 15;
            As[kk][m] = x[(size_t)(by + m) * C_ + k0 + kk];
            int kk2 = idx >> 6, n = idx & 63;
            Bs[kk2][n] = W[(size_t)(k0 + kk2) * TWO_C_ + bx + n];
        }
        __syncthreads();
        #pragma unroll
        for (int kk = 0; kk < 16; kk++) {
            float a[4], b[4];
            #pragma unroll
            for (int i = 0; i < 4; i++) a[i] = As[kk][ty * 4 + i];
            #pragma unroll
            for (int j = 0; j < 4; j++) b[j] = Bs[kk][tx * 4 + j];
            #pragma unroll
            for (int i = 0; i < 4; i++)
                #pragma unroll
                for (int j = 0; j < 4; j++) acc[i][j] += a[i] * b[j];
        }
        __syncthreads();
    }
    #pragma unroll
    for (int i = 0; i < 4; i++) {
        int m = by + ty * 4 + i;
        int b = m >> 10, n = m & 1023;
        #pragma unroll
        for (int j = 0; j < 4; j++) {
            int col = bx + tx * 4 + j;
            float val = acc[i][j] + bias[col];
            int which = col / C_;
            int h  = (col % C_) / HD_;
            int hd = col % HD_;
            float* dst = which ? g_v : g_k;
            dst[(((size_t)(b * H_ + h)) * N_ + n) * HD_ + hd] = val;
        }
    }
}

// ---------------- GEMM 2: S = scale * k2 @ k2^T per (b,h) ----------------
__global__ void s_gemm_kernel(float* __restrict__ attn) {
    __shared__ float As[16][64];
    __shared__ float Bs[16][64];
    const int bh = blockIdx.z;
    const float* A = g_k2 + (size_t)bh * N_ * HD_;
    const int by = blockIdx.y * 64;   // row i
    const int bx = blockIdx.x * 64;   // col j
    const int tid = threadIdx.x;
    const int tx = tid & 15, ty = tid >> 4;
    float acc[4][4] = {};
    #pragma unroll
    for (int k0 = 0; k0 < HD_; k0 += 16) {
        #pragma unroll
        for (int i = 0; i < 4; i++) {
            int idx = tid + i * 256;
            int m = idx >> 4, kk = idx & 15;
            As[kk][m] = A[(size_t)(by + m) * HD_ + k0 + kk];
            Bs[kk][m] = A[(size_t)(bx + m) * HD_ + k0 + kk];
        }
        __syncthreads();
        #pragma unroll
        for (int kk = 0; kk < 16; kk++) {
            float a[4], b[4];
            #pragma unroll
            for (int i = 0; i < 4; i++) a[i] = As[kk][ty * 4 + i];
            #pragma unroll
            for (int j = 0; j < 4; j++) b[j] = Bs[kk][tx * 4 + j];
            #pragma unroll
            for (int i = 0; i < 4; i++)
                #pragma unroll
                for (int j = 0; j < 4; j++) acc[i][j] += a[i] * b[j];
        }
        __syncthreads();
    }
    float* Sp = attn + (size_t)bh * N_ * N_;
    #pragma unroll
    for (int i = 0; i < 4; i++)
        #pragma unroll
        for (int j = 0; j < 4; j++)
            Sp[(size_t)(by + ty * 4 + i) * N_ + bx + tx * 4 + j] = acc[i][j] * SCALE_;
}

// ---------------- GEMM 3: L = P @ V per (b,h) ----------------
// final_mode: 0 -> g_l [bh,n,hd]; 1 -> g_obnc [b, n, h*64+hd]
__global__ void pv_gemm_kernel(const float* __restrict__ attn, int final_mode) {
    __shared__ float As[16][64];
    __shared__ float Bs[16][64];
    const int bh = blockIdx.y;
    const int by = blockIdx.x * 64;   // row block of P / output rows
    const float* P = attn + (size_t)bh * N_ * N_;
    const float* V = g_v  + (size_t)bh * N_ * HD_;
    const int tid = threadIdx.x;
    const int tx = tid & 15, ty = tid >> 4;
    float acc[4][4] = {};
    for (int k0 = 0; k0 < N_; k0 += 16) {
        #pragma unroll
        for (int i = 0; i < 4; i++) {
            int idx = tid + i * 256;
            int m = idx >> 4, kk = idx & 15;
            As[kk][m] = P[(size_t)(by + m) * N_ + k0 + kk];
            int kk2 = idx >> 6, n = idx & 63;
            Bs[kk2][n] = V[(size_t)(k0 + kk2) * HD_ + n];
        }
        __syncthreads();
        #pragma unroll
        for (int kk = 0; kk < 16; kk++) {
            float a[4], b[4];
            #pragma unroll
            for (int i = 0; i < 4; i++) a[i] = As[kk][ty * 4 + i];
            #pragma unroll
            for (int j = 0; j < 4; j++) b[j] = Bs[kk][tx * 4 + j];
            #pragma unroll
            for (int i = 0; i < 4; i++)
                #pragma unroll
                for (int j = 0; j < 4; j++) acc[i][j] += a[i] * b[j];
        }
        __syncthreads();
    }
    int b = bh / H_, h = bh % H_;
    #pragma unroll
    for (int i = 0; i < 4; i++) {
        int m = by + ty * 4 + i;
        #pragma unroll
        for (int j = 0; j < 4; j++) {
            int n = tx * 4 + j;  // 0..63 (HD)
            if (final_mode)
                g_obnc[((size_t)(b * N_ + m)) * C_ + h * HD_ + n] = acc[i][j];
            else
                g_l[((size_t)bh * N_ + m) * HD_ + n] = acc[i][j];
        }
    }
}

// ---------------- GEMM 4: out = obnc @ W_proj + b_proj ----------------
__global__ void proj_gemm_kernel(const float* __restrict__ W,
                                 const float* __restrict__ bias,
                                 float* __restrict__ out) {
    __shared__ float As[16][64];
    __shared__ float Bs[16][64];
    const int bx = blockIdx.x * 64;
    const int by = blockIdx.y * 64;
    const int tid = threadIdx.x;
    const int tx = tid & 15, ty = tid >> 4;
    float acc[4][4] = {};
    for (int k0 = 0; k0 < C_; k0 += 16) {
        #pragma unroll
        for (int i = 0; i < 4; i++) {
            int idx = tid + i * 256;
            int m = idx >> 4, kk = idx & 15;
            As[kk][m] = g_obnc[(size_t)(by + m) * C_ + k0 + kk];
            int kk2 = idx >> 6, n = idx & 63;
            Bs[kk2][n] = W[(size_t)(k0 + kk2) * C_ + bx + n];
        }
        __syncthreads();
        #pragma unroll
        for (int kk = 0; kk < 16; kk++) {
            float a[4], b[4];
            #pragma unroll
            for (int i = 0; i < 4; i++) a[i] = As[kk][ty * 4 + i];
            #pragma unroll
            for (int j = 0; j < 4; j++) b[j] = Bs[kk][tx * 4 + j];
            #pragma unroll
            for (int i = 0; i < 4; i++)
                #pragma unroll
                for (int j = 0; j < 4; j++) acc[i][j] += a[i] * b[j];
        }
        __syncthreads();
    }
    #pragma unroll
    for (int i = 0; i < 4; i++) {
        int m = by + ty * 4 + i;
        #pragma unroll
        for (int j = 0; j < 4; j++) {
            int col = bx + tx * 4 + j;
            out[(size_t)m * C_ + col] = acc[i][j] + bias[col];
        }
    }
}

// ---------------- launch ----------------
extern "C" void kernel_launch(void* const* d_in, const int* in_sizes, int n_in,
                              void* d_out, int out_size) {
    const float* x     = (const float*)d_in[0];
    const float* Wqkv  = (const float*)d_in[1];
    const float* bqkv  = (const float*)d_in[2];
    const float* Wproj = (const float*)d_in[3];
    const float* bproj = (const float*)d_in[4];
    float* out = (float*)d_out;

    // attn scratch: use d_out's attn region when it holds (out, attn); else fallback
    float* attn;
    if ((size_t)out_size >= OUT_ELEMS + ATTN_ELEMS) {
        attn = out + OUT_ELEMS;
    } else {
        void* p = nullptr;
        cudaGetSymbolAddress(&p, g_attn_fallback);
        attn = (float*)p;
    }

    const int eblocks = (int)((KV_ELEMS + 255) / 256);

    zero_ly_kernel<<<eblocks, 256>>>();
    qkv_gemm_kernel<<<dim3(TWO_C_ / 64, M_ROWS / 64), 256>>>(x, Wqkv, bqkv);
    mu_kernel<<<BH_, 256>>>();

    for (int it = 0; it < 6; ++it) {
        k2_kernel<<<eblocks, 256>>>();
        s_gemm_kernel<<<dim3(N_ / 64, N_ / 64, BH_), 256>>>(attn);
        softmax_rows_kernel<<<BH_ * N_, 256>>>(attn);
        pv_gemm_kernel<<<dim3(N_ / 64, BH_), 256>>>(attn, it == 5 ? 1 : 0);
        if (it < 5) y_update_kernel<<<eblocks, 256>>>();
    }

    proj_gemm_kernel<<<dim3(C_ / 64, M_ROWS / 64), 256>>>(Wproj, bproj, out);
}

// round 2
// speedup vs baseline: 1.7540x; 1.7540x over previous
#include <cuda_runtime.h>
#include <math.h>

// Problem constants
#define B_   8
#define N_   1024
#define C_   768
#define H_   12
#define HD_  64
#define BH_  (B_*H_)                       // 96
#define TWO_C_ (2*C_)                      // 1536
#define M_ROWS (B_*N_)                     // 8192

static const size_t KV_ELEMS   = (size_t)BH_ * N_ * HD_;   // 6,291,456
static const size_t OUT_ELEMS  = (size_t)B_ * N_ * C_;     // 6,291,456
static const size_t ATTN_ELEMS = (size_t)BH_ * N_ * N_;    // 100,663,296

#define SCALE_ 0.125f
#define LAMBD_ 4.0f

// ---------------- device scratch ----------------
__device__ float g_k [6291456];
__device__ float g_v [6291456];
__device__ float g_l [6291456];
__device__ float g_y [6291456];
__device__ float g_s [6291456];
__device__ float g_k2[6291456];
__device__ float g_obnc[6291456];
__device__ float g_mu[96];
__device__ float g_attn_fallback[100663296];  // only if d_out doesn't hold attn

// ---------------- elementwise ----------------
__global__ void zero_ly_kernel() {
    size_t i = (size_t)blockIdx.x * 256 + threadIdx.x;
    if (i < KV_ELEMS) { g_l[i] = 0.f; g_y[i] = 0.f; }
}

// Fused: (optional y update from previous iter) + soft-threshold + k2
__global__ void iter_pre_kernel(int first) {
    size_t i = (size_t)blockIdx.x * 256 + threadIdx.x;
    if (i >= KV_ELEMS) return;
    int bh = (int)(i / ((size_t)N_ * HD_));
    float mu = g_mu[bh];
    float kk = g_k[i];
    float l  = g_l[i];
    float y  = g_y[i];
    if (!first) {
        y += mu * (kk - l - g_s[i]);
        g_y[i] = y;
    }
    float ymu = y / mu;
    float t   = kk - l + ymu;
    float lm  = LAMBD_ * mu;
    float s   = (t >= lm) ? (t - lm) : ((t <= -lm) ? (t + lm) : 0.f);
    g_s[i]  = s;
    g_k2[i] = kk - s - ymu;
}

// ---------------- mu reduction: one block per (b,h) ----------------
__global__ void mu_kernel() {
    __shared__ float red[256];
    int bh = blockIdx.x;
    const float* p = g_k + (size_t)bh * N_ * HD_;
    float s = 0.f;
    for (int i = threadIdx.x; i < N_ * HD_; i += 256) s += fabsf(p[i]);
    red[threadIdx.x] = s;
    __syncthreads();
    for (int st = 128; st > 0; st >>= 1) {
        if (threadIdx.x < st) red[threadIdx.x] += red[threadIdx.x + st];
        __syncthreads();
    }
    if (threadIdx.x == 0) g_mu[bh] = ((float)N_ * (float)C_ / 4.0f) / red[0];
}

// ---------------- S = scale * k2 @ k2^T  (symmetric: 36 tile-pairs/head) ----------------
__global__ void __launch_bounds__(256, 2) s_gemm_kernel(float* __restrict__ attn) {
    __shared__ float As[16][132];
    __shared__ float Bs[16][132];
    const int bh = blockIdx.z;
    const float* __restrict__ A = g_k2 + (size_t)bh * N_ * HD_;

    // decode triangular pair index -> (bi, bj), bi <= bj, 8x8 tile grid
    int p = blockIdx.x;
    int bi = 0;
    while (p >= 8 - bi) { p -= 8 - bi; bi++; }
    int bj = bi + p;
    const int by = bi * 128, bx = bj * 128;

    const int tid = threadIdx.x;
    const int tx = tid & 15, ty = tid >> 4;
    float acc[8][8] = {};

    for (int k0 = 0; k0 < HD_; k0 += 16) {
        #pragma unroll
        for (int i = 0; i < 2; i++) {
            int idx = tid + i * 256;
            int m  = idx >> 2;
            int kq = (idx & 3) * 4;
            float4 a = *(const float4*)&A[(size_t)(by + m) * HD_ + k0 + kq];
            As[kq + 0][m] = a.x; As[kq + 1][m] = a.y;
            As[kq + 2][m] = a.z; As[kq + 3][m] = a.w;
            float4 b = *(const float4*)&A[(size_t)(bx + m) * HD_ + k0 + kq];
            Bs[kq + 0][m] = b.x; Bs[kq + 1][m] = b.y;
            Bs[kq + 2][m] = b.z; Bs[kq + 3][m] = b.w;
        }
        __syncthreads();
        #pragma unroll
        for (int kk = 0; kk < 16; kk++) {
            float4 a0 = *(const float4*)&As[kk][ty * 8];
            float4 a1 = *(const float4*)&As[kk][ty * 8 + 4];
            float4 b0 = *(const float4*)&Bs[kk][tx * 8];
            float4 b1 = *(const float4*)&Bs[kk][tx * 8 + 4];
            float a[8] = {a0.x, a0.y, a0.z, a0.w, a1.x, a1.y, a1.z, a1.w};
            float b[8] = {b0.x, b0.y, b0.z, b0.w, b1.x, b1.y, b1.z, b1.w};
            #pragma unroll
            for (int i = 0; i < 8; i++)
                #pragma unroll
                for (int j = 0; j < 8; j++) acc[i][j] += a[i] * b[j];
        }
        __syncthreads();
    }

    float* __restrict__ Sp = attn + (size_t)bh * N_ * N_;
    #pragma unroll
    for (int i = 0; i < 8; i++)
        #pragma unroll
        for (int j = 0; j < 8; j++) acc[i][j] *= SCALE_;

    // main tile
    #pragma unroll
    for (int i = 0; i < 8; i++) {
        int r = by + ty * 8 + i;
        float4 v0 = make_float4(acc[i][0], acc[i][1], acc[i][2], acc[i][3]);
        float4 v1 = make_float4(acc[i][4], acc[i][5], acc[i][6], acc[i][7]);
        *(float4*)&Sp[(size_t)r * N_ + bx + tx * 8]     = v0;
        *(float4*)&Sp[(size_t)r * N_ + bx + tx * 8 + 4] = v1;
    }
    // mirrored tile
    if (bi != bj) {
        #pragma unroll
        for (int j = 0; j < 8; j++) {
            int r = bx + tx * 8 + j;
            float4 v0 = make_float4(acc[0][j], acc[1][j], acc[2][j], acc[3][j]);
            float4 v1 = make_float4(acc[4][j], acc[5][j], acc[6][j], acc[7][j]);
            *(float4*)&Sp[(size_t)r * N_ + by + ty * 8]     = v0;
            *(float4*)&Sp[(size_t)r * N_ + by + ty * 8 + 4] = v1;
        }
    }
}

// ---------------- fused softmax + PV: L = softmax(S) @ V per (b,h) ----------------
// Reads raw logits from attn; pass1 computes row max/sumexp; pass2 applies
// exp-normalize at tile load and GEMMs with V. final_mode: writes normalized P
// back into attn (in place) and output into g_obnc; else writes g_l.
__global__ void __launch_bounds__(256, 2) pv_kernel(float* __restrict__ attn, int final_mode) {
    __shared__ float As[32][132];
    __shared__ float Bs[32][68];
    __shared__ float sm_m[128], sm_inv[128];
    __shared__ float red_m[256], red_s[256];

    const int bh = blockIdx.y;
    const int by = blockIdx.x * 128;
    float* __restrict__ Sp = attn + (size_t)bh * N_ * N_;
    const float* __restrict__ V = g_v + (size_t)bh * N_ * HD_;
    const int tid = threadIdx.x;

    // ---- pass 1: per-row online max / sum(exp) (2 threads per row) ----
    {
        int r    = tid >> 1;
        int half = tid & 1;
        const float* row = Sp + (size_t)(by + r) * N_ + half * 512;
        float m = -1e30f, s = 0.f;
        for (int c = 0; c < 512; c += 4) {
            float4 v = *(const float4*)&row[c];
            float xs[4] = {v.x, v.y, v.z, v.w};
            #pragma unroll
            for (int q = 0; q < 4; q++) {
                float x = xs[q];
                if (x > m) { s = s * __expf(m - x) + 1.f; m = x; }
                else       { s += __expf(x - m); }
            }
        }
        red_m[tid] = m; red_s[tid] = s;
        __syncthreads();
        if (half == 0) {
            float m2 = red_m[tid + 1], s2 = red_s[tid + 1];
            float M  = fmaxf(m, m2);
            float S  = s * __expf(m - M) + s2 * __expf(m2 - M);
            sm_m[r]   = M;
            sm_inv[r] = 1.0f / S;
        }
        __syncthreads();
    }

    // ---- pass 2: tiled GEMM with exp-normalization on load ----
    const int tx = tid & 15, ty = tid >> 4;
    float acc[8][4] = {};
    for (int k0 = 0; k0 < N_; k0 += 32) {
        #pragma unroll
        for (int i = 0; i < 4; i++) {
            int idx = tid + i * 256;       // 0..1023
            int m   = idx >> 3;            // row 0..127
            int kq  = (idx & 7) * 4;       // 0..28
            float* src = &Sp[(size_t)(by + m) * N_ + k0 + kq];
            float4 v = *(const float4*)src;
            float mm = sm_m[m], inv = sm_inv[m];
            v.x = __expf(v.x - mm) * inv;
            v.y = __expf(v.y - mm) * inv;
            v.z = __expf(v.z - mm) * inv;
            v.w = __expf(v.w - mm) * inv;
            if (final_mode) *(float4*)src = v;   // materialize normalized attn
            As[kq + 0][m] = v.x; As[kq + 1][m] = v.y;
            As[kq + 2][m] = v.z; As[kq + 3][m] = v.w;
        }
        #pragma unroll
        for (int i = 0; i < 2; i++) {
            int idx = tid + i * 256;       // 0..511
            int r   = idx >> 4;            // 0..31
            int cq  = (idx & 15) * 4;      // 0..60
            *(float4*)&Bs[r][cq] = *(const float4*)&V[(size_t)(k0 + r) * HD_ + cq];
        }
        __syncthreads();
        #pragma unroll
        for (int kk = 0; kk < 32; kk++) {
            float4 a0 = *(const float4*)&As[kk][ty * 8];
            float4 a1 = *(const float4*)&As[kk][ty * 8 + 4];
            float4 b4 = *(const float4*)&Bs[kk][tx * 4];
            float a[8] = {a0.x, a0.y, a0.z, a0.w, a1.x, a1.y, a1.z, a1.w};
            float b[4] = {b4.x, b4.y, b4.z, b4.w};
            #pragma unroll
            for (int i = 0; i < 8; i++)
                #pragma unroll
                for (int j = 0; j < 4; j++) acc[i][j] += a[i] * b[j];
        }
        __syncthreads();
    }

    int b = bh / H_, h = bh % H_;
    #pragma unroll
    for (int i = 0; i < 8; i++) {
        int r = by + ty * 8 + i;
        float4 v0 = make_float4(acc[i][0], acc[i][1], acc[i][2], acc[i][3]);
        if (final_mode)
            *(float4*)&g_obnc[((size_t)(b * N_ + r)) * C_ + h * HD_ + tx * 4] = v0;
        else
            *(float4*)&g_l[((size_t)bh * N_ + r) * HD_ + tx * 4] = v0;
    }
}

// ---------------- qkv = x @ W_qkv + b, scattered into g_k / g_v ----------------
__global__ void __launch_bounds__(256, 2) qkv_gemm_kernel(const float* __restrict__ x,
                                                          const float* __restrict__ W,
                                                          const float* __restrict__ bias) {
    __shared__ float As[16][132];
    __shared__ float Bs[16][132];
    const int bx = blockIdx.x * 128;
    const int by = blockIdx.y * 128;
    const int tid = threadIdx.x;
    const int tx = tid & 15, ty = tid >> 4;
    float acc[8][8] = {};

    for (int k0 = 0; k0 < C_; k0 += 16) {
        #pragma unroll
        for (int i = 0; i < 2; i++) {
            int idx = tid + i * 256;
            int m  = idx >> 2;
            int kq = (idx & 3) * 4;
            float4 a = *(const float4*)&x[(size_t)(by + m) * C_ + k0 + kq];
            As[kq + 0][m] = a.x; As[kq + 1][m] = a.y;
            As[kq + 2][m] = a.z; As[kq + 3][m] = a.w;
            int r  = idx >> 5;            // 0..15
            int cq = (idx & 31) * 4;      // 0..124
            *(float4*)&Bs[r][cq] = *(const float4*)&W[(size_t)(k0 + r) * TWO_C_ + bx + cq];
        }
        __syncthreads();
        #pragma unroll
        for (int kk = 0; kk < 16; kk++) {
            float4 a0 = *(const float4*)&As[kk][ty * 8];
            float4 a1 = *(const float4*)&As[kk][ty * 8 + 4];
            float4 b0 = *(const float4*)&Bs[kk][tx * 8];
            float4 b1 = *(const float4*)&Bs[kk][tx * 8 + 4];
            float a[8] = {a0.x, a0.y, a0.z, a0.w, a1.x, a1.y, a1.z, a1.w};
            float b[8] = {b0.x, b0.y, b0.z, b0.w, b1.x, b1.y, b1.z, b1.w};
            #pragma unroll
            for (int i = 0; i < 8; i++)
                #pragma unroll
                for (int j = 0; j < 8; j++) acc[i][j] += a[i] * b[j];
        }
        __syncthreads();
    }

    #pragma unroll
    for (int i = 0; i < 8; i++) {
        int mrow = by + ty * 8 + i;
        int b = mrow >> 10, n = mrow & 1023;
        #pragma unroll
        for (int jj = 0; jj < 2; jj++) {
            int col0 = bx + tx * 8 + jj * 4;
            int which = col0 / C_;
            int h  = (col0 % C_) / HD_;
            int hd = col0 % HD_;
            float* dst = which ? g_v : g_k;
            float4 v = make_float4(acc[i][jj*4+0] + bias[col0+0],
                                   acc[i][jj*4+1] + bias[col0+1],
                                   acc[i][jj*4+2] + bias[col0+2],
                                   acc[i][jj*4+3] + bias[col0+3]);
            *(float4*)&dst[(((size_t)(b * H_ + h)) * N_ + n) * HD_ + hd] = v;
        }
    }
}

// ---------------- out = obnc @ W_proj + b_proj ----------------
__global__ void __launch_bounds__(256, 2) proj_gemm_kernel(const float* __restrict__ W,
                                                           const float* __restrict__ bias,
                                                           float* __restrict__ out) {
    __shared__ float As[16][132];
    __shared__ float Bs[16][132];
    const int bx = blockIdx.x * 128;
    const int by = blockIdx.y * 128;
    const int tid = threadIdx.x;
    const int tx = tid & 15, ty = tid >> 4;
    float acc[8][8] = {};

    for (int k0 = 0; k0 < C_; k0 += 16) {
        #pragma unroll
        for (int i = 0; i < 2; i++) {
            int idx = tid + i * 256;
            int m  = idx >> 2;
            int kq = (idx & 3) * 4;
            float4 a = *(const float4*)&g_obnc[(size_t)(by + m) * C_ + k0 + kq];
            As[kq + 0][m] = a.x; As[kq + 1][m] = a.y;
            As[kq + 2][m] = a.z; As[kq + 3][m] = a.w;
            int r  = idx >> 5;
            int cq = (idx & 31) * 4;
            *(float4*)&Bs[r][cq] = *(const float4*)&W[(size_t)(k0 + r) * C_ + bx + cq];
        }
        __syncthreads();
        #pragma unroll
        for (int kk = 0; kk < 16; kk++) {
            float4 a0 = *(const float4*)&As[kk][ty * 8];
            float4 a1 = *(const float4*)&As[kk][ty * 8 + 4];
            float4 b0 = *(const float4*)&Bs[kk][tx * 8];
            float4 b1 = *(const float4*)&Bs[kk][tx * 8 + 4];
            float a[8] = {a0.x, a0.y, a0.z, a0.w, a1.x, a1.y, a1.z, a1.w};
            float b[8] = {b0.x, b0.y, b0.z, b0.w, b1.x, b1.y, b1.z, b1.w};
            #pragma unroll
            for (int i = 0; i < 8; i++)
                #pragma unroll
                for (int j = 0; j < 8; j++) acc[i][j] += a[i] * b[j];
        }
        __syncthreads();
    }

    #pragma unroll
    for (int i = 0; i < 8; i++) {
        int m = by + ty * 8 + i;
        #pragma unroll
        for (int jj = 0; jj < 2; jj++) {
            int col0 = bx + tx * 8 + jj * 4;
            float4 v = make_float4(acc[i][jj*4+0] + bias[col0+0],
                                   acc[i][jj*4+1] + bias[col0+1],
                                   acc[i][jj*4+2] + bias[col0+2],
                                   acc[i][jj*4+3] + bias[col0+3]);
            *(float4*)&out[(size_t)m * C_ + col0] = v;
        }
    }
}

// ---------------- launch ----------------
extern "C" void kernel_launch(void* const* d_in, const int* in_sizes, int n_in,
                              void* d_out, int out_size) {
    const float* x     = (const float*)d_in[0];
    const float* Wqkv  = (const float*)d_in[1];
    const float* bqkv  = (const float*)d_in[2];
    const float* Wproj = (const float*)d_in[3];
    const float* bproj = (const float*)d_in[4];
    float* out = (float*)d_out;

    float* attn;
    if ((size_t)out_size >= OUT_ELEMS + ATTN_ELEMS) {
        attn = out + OUT_ELEMS;
    } else {
        void* p = nullptr;
        cudaGetSymbolAddress(&p, g_attn_fallback);
        attn = (float*)p;
    }

    const int eblocks = (int)((KV_ELEMS + 255) / 256);

    zero_ly_kernel<<<eblocks, 256>>>();
    qkv_gemm_kernel<<<dim3(TWO_C_ / 128, M_ROWS / 128), 256>>>(x, Wqkv, bqkv);
    mu_kernel<<<BH_, 256>>>();

    for (int it = 0; it < 6; ++it) {
        iter_pre_kernel<<<eblocks, 256>>>(it == 0 ? 1 : 0);
        s_gemm_kernel<<<dim3(36, 1, BH_), 256>>>(attn);
        pv_kernel<<<dim3(N_ / 128, BH_), 256>>>(attn, it == 5 ? 1 : 0);
    }

    proj_gemm_kernel<<<dim3(C_ / 128, M_ROWS / 128), 256>>>(Wproj, bproj, out);
}

// round 4
// speedup vs baseline: 1.8195x; 1.0374x over previous
#include <cuda_runtime.h>
#include <cuda_bf16.h>
#include <math.h>
#include <stdint.h>

// Problem constants
#define B_   8
#define N_   1024
#define C_   768
#define H_   12
#define HD_  64
#define BH_  (B_*H_)                       // 96
#define TWO_C_ (2*C_)                      // 1536
#define M_ROWS (B_*N_)                     // 8192

static const size_t KV_ELEMS   = (size_t)BH_ * N_ * HD_;   // 6,291,456
static const size_t OUT_ELEMS  = (size_t)B_ * N_ * C_;     // 6,291,456
static const size_t ATTN_ELEMS = (size_t)BH_ * N_ * N_;    // 100,663,296

#define SCALE_ 0.125f
#define LAMBD_ 4.0f

// ---------------- device scratch ----------------
__device__ float g_k [6291456];
__device__ float g_v [6291456];
__device__ float g_l [6291456];
__device__ float g_y [6291456];
__device__ float g_s [6291456];
__device__ __nv_bfloat16 g_k2h[6291456];
__device__ __nv_bfloat16 g_k2l[6291456];
__device__ float g_obnc[6291456];
__device__ float g_mu[96];
__device__ float g_attn_fallback[100663296];  // only if d_out doesn't hold attn

// ---------------- warp mma helpers (sm_80+ PTX, no 'a' features) ----------------
__device__ __forceinline__ uint32_t smem_u32(const void* p) {
    uint32_t a;
    asm("{ .reg .u64 t; cvta.to.shared.u64 t, %1; cvt.u32.u64 %0, t; }" : "=r"(a) : "l"(p));
    return a;
}
__device__ __forceinline__ void ldsm4(uint32_t r[4], uint32_t addr) {
    asm volatile("ldmatrix.sync.aligned.m8n8.x4.shared.b16 {%0,%1,%2,%3}, [%4];"
        : "=r"(r[0]), "=r"(r[1]), "=r"(r[2]), "=r"(r[3]) : "r"(addr));
}
__device__ __forceinline__ void mma_bf16(float c[4], const uint32_t a[4], const uint32_t* b) {
    asm volatile("mma.sync.aligned.m16n8k16.row.col.f32.bf16.bf16.f32 "
        "{%0,%1,%2,%3}, {%4,%5,%6,%7}, {%8,%9}, {%0,%1,%2,%3};"
        : "+f"(c[0]), "+f"(c[1]), "+f"(c[2]), "+f"(c[3])
        : "r"(a[0]), "r"(a[1]), "r"(a[2]), "r"(a[3]), "r"(b[0]), "r"(b[1]));
}

// ---------------- elementwise ----------------
__global__ void zero_ly_kernel() {
    size_t i = (size_t)blockIdx.x * 256 + threadIdx.x;
    if (i < KV_ELEMS) { g_l[i] = 0.f; g_y[i] = 0.f; }
}

// Fused: (optional y update) + soft-threshold + k2 (bf16 hi/lo split)
__global__ void iter_pre_kernel(int first) {
    size_t i = (size_t)blockIdx.x * 256 + threadIdx.x;
    if (i >= KV_ELEMS) return;
    int bh = (int)(i / ((size_t)N_ * HD_));
    float mu = g_mu[bh];
    float kk = g_k[i];
    float l  = g_l[i];
    float y  = g_y[i];
    if (!first) {
        y += mu * (kk - l - g_s[i]);
        g_y[i] = y;
    }
    float ymu = y / mu;
    float t   = kk - l + ymu;
    float lm  = LAMBD_ * mu;
    float s   = (t >= lm) ? (t - lm) : ((t <= -lm) ? (t + lm) : 0.f);
    g_s[i] = s;
    float k2 = kk - s - ymu;
    __nv_bfloat16 hi = __float2bfloat16(k2);
    __nv_bfloat16 lo = __float2bfloat16(k2 - __bfloat162float(hi));
    g_k2h[i] = hi;
    g_k2l[i] = lo;
}

// ---------------- mu reduction: one block per (b,h) ----------------
__global__ void mu_kernel() {
    __shared__ float red[256];
    int bh = blockIdx.x;
    const float* p = g_k + (size_t)bh * N_ * HD_;
    float s = 0.f;
    for (int i = threadIdx.x; i < N_ * HD_; i += 256) s += fabsf(p[i]);
    red[threadIdx.x] = s;
    __syncthreads();
    for (int st = 128; st > 0; st >>= 1) {
        if (threadIdx.x < st) red[threadIdx.x] += red[threadIdx.x + st];
        __syncthreads();
    }
    if (threadIdx.x == 0) g_mu[bh] = ((float)N_ * (float)C_ / 4.0f) / red[0];
}

// ---------------- S = scale * k2 @ k2^T via HMMA bf16x3 ----------------
// grid (8, 8, 96); 256 threads = 8 warps; CTA tile 128x128; warp tile 64x32.
// acc = Ah*Bh + Ah*Bl + Al*Bh (fp32 accumulate), dropping lo*lo (~4e-6).
// SMEM: 4 tiles of 128 rows x 72 bf16 (stride-72 padding -> conflict-free ldmatrix).
#define SPAD 72
__global__ void __launch_bounds__(256, 1) s_mma_kernel(float* __restrict__ attn) {
    extern __shared__ __nv_bfloat16 sm[];
    const int bh = blockIdx.z;
    const int bx = blockIdx.x * 128;   // output cols
    const int by = blockIdx.y * 128;   // output rows
    const int tid  = threadIdx.x;
    const int wid  = tid >> 5;
    const int lane = tid & 31;

    __nv_bfloat16* sAh = sm;
    __nv_bfloat16* sAl = sm + 128 * SPAD;
    __nv_bfloat16* sBh = sm + 2 * 128 * SPAD;
    __nv_bfloat16* sBl = sm + 3 * 128 * SPAD;

    const __nv_bfloat16* Gh = g_k2h + (size_t)bh * N_ * HD_;
    const __nv_bfloat16* Gl = g_k2l + (size_t)bh * N_ * HD_;

    // load tiles: A rows [by..by+128), B rows [bx..bx+128), 16B chunks
    #pragma unroll
    for (int i = 0; i < 4; i++) {
        int idx = tid + i * 256;           // 0..1023
        int row = idx >> 3, c = idx & 7;   // chunk c of 8 per row
        *(uint4*)(sAh + row * SPAD + c * 8) = *(const uint4*)(Gh + (size_t)(by + row) * HD_ + c * 8);
        *(uint4*)(sAl + row * SPAD + c * 8) = *(const uint4*)(Gl + (size_t)(by + row) * HD_ + c * 8);
        *(uint4*)(sBh + row * SPAD + c * 8) = *(const uint4*)(Gh + (size_t)(bx + row) * HD_ + c * 8);
        *(uint4*)(sBl + row * SPAD + c * 8) = *(const uint4*)(Gl + (size_t)(bx + row) * HD_ + c * 8);
    }
    __syncthreads();

    const int wm = wid & 1;    // 2 warp rows of 64
    const int wn = wid >> 1;   // 4 warp cols of 32
    float acc[4][4][4] = {};   // [m-tile][n-tile][frag]

    // ldmatrix lane address components
    const int a_r8   = lane & 7;
    const int a_roff = ((lane >> 3) & 1) * 8;   // A: +8 rows for mats 1,3
    const int a_koff = (lane >> 4) * 8;         // A: +8 k for mats 2,3
    const int b_noff = (lane >> 4) * 8;         // B: +8 n for mats 2,3
    const int b_koff = ((lane >> 3) & 1) * 8;   // B: +8 k for mats 1,3

    #pragma unroll
    for (int ks = 0; ks < 4; ks++) {
        uint32_t aH[4][4], aL[4][4], bH[2][4], bL[2][4];
        #pragma unroll
        for (int mt = 0; mt < 4; mt++) {
            int row = wm * 64 + mt * 16 + a_r8 + a_roff;
            int kc  = ks * 16 + a_koff;
            ldsm4(aH[mt], smem_u32(sAh + row * SPAD + kc));
            ldsm4(aL[mt], smem_u32(sAl + row * SPAD + kc));
        }
        #pragma unroll
        for (int p = 0; p < 2; p++) {
            int nrow = wn * 32 + p * 16 + a_r8 + b_noff;
            int kc   = ks * 16 + b_koff;
            ldsm4(bH[p], smem_u32(sBh + nrow * SPAD + kc));
            ldsm4(bL[p], smem_u32(sBl + nrow * SPAD + kc));
        }
        #pragma unroll
        for (int mt = 0; mt < 4; mt++)
            #pragma unroll
            for (int nt = 0; nt < 4; nt++) {
                const uint32_t* bh_f = &bH[nt >> 1][(nt & 1) * 2];
                const uint32_t* bl_f = &bL[nt >> 1][(nt & 1) * 2];
                mma_bf16(acc[mt][nt], aH[mt], bh_f);
                mma_bf16(acc[mt][nt], aH[mt], bl_f);
                mma_bf16(acc[mt][nt], aL[mt], bh_f);
            }
    }
    __syncthreads();   // tiles dead; reuse smem as epilogue buffer

    // epilogue: acc -> smem [128][132] fp32 -> coalesced float4 stores
    float* ep = (float*)sm;
    const int erow = lane >> 2;
    const int ecol = (lane & 3) * 2;
    #pragma unroll
    for (int mt = 0; mt < 4; mt++)
        #pragma unroll
        for (int nt = 0; nt < 4; nt++) {
            int r = wm * 64 + mt * 16 + erow;
            int c = wn * 32 + nt * 8 + ecol;
            ep[r * 132 + c]           = acc[mt][nt][0] * SCALE_;
            ep[r * 132 + c + 1]       = acc[mt][nt][1] * SCALE_;
            ep[(r + 8) * 132 + c]     = acc[mt][nt][2] * SCALE_;
            ep[(r + 8) * 132 + c + 1] = acc[mt][nt][3] * SCALE_;
        }
    __syncthreads();

    float* Sp = attn + (size_t)bh * N_ * N_;
    #pragma unroll
    for (int i = 0; i < 16; i++) {
        int idx = tid + i * 256;       // 0..4095 float4s
        int rr  = idx >> 5;
        int c4  = idx & 31;
        float4 v = *(const float4*)&ep[rr * 132 + c4 * 4];
        *(float4*)&Sp[(size_t)(by + rr) * N_ + bx + c4 * 4] = v;
    }
}

// ---------------- fused softmax + PV: L = softmax(S) @ V per (b,h) ----------------
__global__ void __launch_bounds__(256, 2) pv_kernel(float* __restrict__ attn, int final_mode) {
    __shared__ float As[32][132];
    __shared__ float Bs[32][68];
    __shared__ float sm_m[128], sm_inv[128];
    __shared__ float red_m[256], red_s[256];

    const int bh = blockIdx.y;
    const int by = blockIdx.x * 128;
    float* __restrict__ Sp = attn + (size_t)bh * N_ * N_;
    const float* __restrict__ V = g_v + (size_t)bh * N_ * HD_;
    const int tid = threadIdx.x;

    // pass 1: per-row online max / sum(exp) (2 threads per row)
    {
        int r    = tid >> 1;
        int half = tid & 1;
        const float* row = Sp + (size_t)(by + r) * N_ + half * 512;
        float m = -1e30f, s = 0.f;
        for (int c = 0; c < 512; c += 4) {
            float4 v = *(const float4*)&row[c];
            float xs[4] = {v.x, v.y, v.z, v.w};
            #pragma unroll
            for (int q = 0; q < 4; q++) {
                float x = xs[q];
                if (x > m) { s = s * __expf(m - x) + 1.f; m = x; }
                else       { s += __expf(x - m); }
            }
        }
        red_m[tid] = m; red_s[tid] = s;
        __syncthreads();
        if (half == 0) {
            float m2 = red_m[tid + 1], s2 = red_s[tid + 1];
            float M  = fmaxf(m, m2);
            float S  = s * __expf(m - M) + s2 * __expf(m2 - M);
            sm_m[r]   = M;
            sm_inv[r] = 1.0f / S;
        }
        __syncthreads();
    }

    // pass 2: tiled GEMM with exp-normalization on load
    const int tx = tid & 15, ty = tid >> 4;
    float acc[8][4] = {};
    for (int k0 = 0; k0 < N_; k0 += 32) {
        #pragma unroll
        for (int i = 0; i < 4; i++) {
            int idx = tid + i * 256;
            int m   = idx >> 3;
            int kq  = (idx & 7) * 4;
            float* src = &Sp[(size_t)(by + m) * N_ + k0 + kq];
            float4 v = *(const float4*)src;
            float mm = sm_m[m], inv = sm_inv[m];
            v.x = __expf(v.x - mm) * inv;
            v.y = __expf(v.y - mm) * inv;
            v.z = __expf(v.z - mm) * inv;
            v.w = __expf(v.w - mm) * inv;
            if (final_mode) *(float4*)src = v;
            As[kq + 0][m] = v.x; As[kq + 1][m] = v.y;
            As[kq + 2][m] = v.z; As[kq + 3][m] = v.w;
        }
        #pragma unroll
        for (int i = 0; i < 2; i++) {
            int idx = tid + i * 256;
            int r   = idx >> 4;
            int cq  = (idx & 15) * 4;
            *(float4*)&Bs[r][cq] = *(const float4*)&V[(size_t)(k0 + r) * HD_ + cq];
        }
        __syncthreads();
        #pragma unroll
        for (int kk = 0; kk < 32; kk++) {
            float4 a0 = *(const float4*)&As[kk][ty * 8];
            float4 a1 = *(const float4*)&As[kk][ty * 8 + 4];
            float4 b4 = *(const float4*)&Bs[kk][tx * 4];
            float a[8] = {a0.x, a0.y, a0.z, a0.w, a1.x, a1.y, a1.z, a1.w};
            float b[4] = {b4.x, b4.y, b4.z, b4.w};
            #pragma unroll
            for (int i = 0; i < 8; i++)
                #pragma unroll
                for (int j = 0; j < 4; j++) acc[i][j] += a[i] * b[j];
        }
        __syncthreads();
    }

    int b = bh / H_, h = bh % H_;
    #pragma unroll
    for (int i = 0; i < 8; i++) {
        int r = by + ty * 8 + i;
        float4 v0 = make_float4(acc[i][0], acc[i][1], acc[i][2], acc[i][3]);
        if (final_mode)
            *(float4*)&g_obnc[((size_t)(b * N_ + r)) * C_ + h * HD_ + tx * 4] = v0;
        else
            *(float4*)&g_l[((size_t)bh * N_ + r) * HD_ + tx * 4] = v0;
    }
}

// ---------------- qkv = x @ W_qkv + b, scattered into g_k / g_v ----------------
__global__ void __launch_bounds__(256, 2) qkv_gemm_kernel(const float* __restrict__ x,
                                                          const float* __restrict__ W,
                                                          const float* __restrict__ bias) {
    __shared__ float As[16][132];
    __shared__ float Bs[16][132];
    const int bx = blockIdx.x * 128;
    const int by = blockIdx.y * 128;
    const int tid = threadIdx.x;
    const int tx = tid & 15, ty = tid >> 4;
    float acc[8][8] = {};

    for (int k0 = 0; k0 < C_; k0 += 16) {
        #pragma unroll
        for (int i = 0; i < 2; i++) {
            int idx = tid + i * 256;
            int m  = idx >> 2;
            int kq = (idx & 3) * 4;
            float4 a = *(const float4*)&x[(size_t)(by + m) * C_ + k0 + kq];
            As[kq + 0][m] = a.x; As[kq + 1][m] = a.y;
            As[kq + 2][m] = a.z; As[kq + 3][m] = a.w;
            int r  = idx >> 5;
            int cq = (idx & 31) * 4;
            *(float4*)&Bs[r][cq] = *(const float4*)&W[(size_t)(k0 + r) * TWO_C_ + bx + cq];
        }
        __syncthreads();
        #pragma unroll
        for (int kk = 0; kk < 16; kk++) {
            float4 a0 = *(const float4*)&As[kk][ty * 8];
            float4 a1 = *(const float4*)&As[kk][ty * 8 + 4];
            float4 b0 = *(const float4*)&Bs[kk][tx * 8];
            float4 b1 = *(const float4*)&Bs[kk][tx * 8 + 4];
            float a[8] = {a0.x, a0.y, a0.z, a0.w, a1.x, a1.y, a1.z, a1.w};
            float b[8] = {b0.x, b0.y, b0.z, b0.w, b1.x, b1.y, b1.z, b1.w};
            #pragma unroll
            for (int i = 0; i < 8; i++)
                #pragma unroll
                for (int j = 0; j < 8; j++) acc[i][j] += a[i] * b[j];
        }
        __syncthreads();
    }

    #pragma unroll
    for (int i = 0; i < 8; i++) {
        int mrow = by + ty * 8 + i;
        int b = mrow >> 10, n = mrow & 1023;
        #pragma unroll
        for (int jj = 0; jj < 2; jj++) {
            int col0 = bx + tx * 8 + jj * 4;
            int which = col0 / C_;
            int h  = (col0 % C_) / HD_;
            int hd = col0 % HD_;
            float* dst = which ? g_v : g_k;
            float4 v = make_float4(acc[i][jj*4+0] + bias[col0+0],
                                   acc[i][jj*4+1] + bias[col0+1],
                                   acc[i][jj*4+2] + bias[col0+2],
                                   acc[i][jj*4+3] + bias[col0+3]);
            *(float4*)&dst[(((size_t)(b * H_ + h)) * N_ + n) * HD_ + hd] = v;
        }
    }
}

// ---------------- out = obnc @ W_proj + b_proj ----------------
__global__ void __launch_bounds__(256, 2) proj_gemm_kernel(const float* __restrict__ W,
                                                           const float* __restrict__ bias,
                                                           float* __restrict__ out) {
    __shared__ float As[16][132];
    __shared__ float Bs[16][132];
    const int bx = blockIdx.x * 128;
    const int by = blockIdx.y * 128;
    const int tid = threadIdx.x;
    const int tx = tid & 15, ty = tid >> 4;
    float acc[8][8] = {};

    for (int k0 = 0; k0 < C_; k0 += 16) {
        #pragma unroll
        for (int i = 0; i < 2; i++) {
            int idx = tid + i * 256;
            int m  = idx >> 2;
            int kq = (idx & 3) * 4;
            float4 a = *(const float4*)&g_obnc[(size_t)(by + m) * C_ + k0 + kq];
            As[kq + 0][m] = a.x; As[kq + 1][m] = a.y;
            As[kq + 2][m] = a.z; As[kq + 3][m] = a.w;
            int r  = idx >> 5;
            int cq = (idx & 31) * 4;
            *(float4*)&Bs[r][cq] = *(const float4*)&W[(size_t)(k0 + r) * C_ + bx + cq];
        }
        __syncthreads();
        #pragma unroll
        for (int kk = 0; kk < 16; kk++) {
            float4 a0 = *(const float4*)&As[kk][ty * 8];
            float4 a1 = *(const float4*)&As[kk][ty * 8 + 4];
            float4 b0 = *(const float4*)&Bs[kk][tx * 8];
            float4 b1 = *(const float4*)&Bs[kk][tx * 8 + 4];
            float a[8] = {a0.x, a0.y, a0.z, a0.w, a1.x, a1.y, a1.z, a1.w};
            float b[8] = {b0.x, b0.y, b0.z, b0.w, b1.x, b1.y, b1.z, b1.w};
            #pragma unroll
            for (int i = 0; i < 8; i++)
                #pragma unroll
                for (int j = 0; j < 8; j++) acc[i][j] += a[i] * b[j];
        }
        __syncthreads();
    }

    #pragma unroll
    for (int i = 0; i < 8; i++) {
        int m = by + ty * 8 + i;
        #pragma unroll
        for (int jj = 0; jj < 2; jj++) {
            int col0 = bx + tx * 8 + jj * 4;
            float4 v = make_float4(acc[i][jj*4+0] + bias[col0+0],
                                   acc[i][jj*4+1] + bias[col0+1],
                                   acc[i][jj*4+2] + bias[col0+2],
                                   acc[i][jj*4+3] + bias[col0+3]);
            *(float4*)&out[(size_t)m * C_ + col0] = v;
        }
    }
}

// ---------------- launch ----------------
extern "C" void kernel_launch(void* const* d_in, const int* in_sizes, int n_in,
                              void* d_out, int out_size) {
    const float* x     = (const float*)d_in[0];
    const float* Wqkv  = (const float*)d_in[1];
    const float* bqkv  = (const float*)d_in[2];
    const float* Wproj = (const float*)d_in[3];
    const float* bproj = (const float*)d_in[4];
    float* out = (float*)d_out;

    float* attn;
    if ((size_t)out_size >= OUT_ELEMS + ATTN_ELEMS) {
        attn = out + OUT_ELEMS;
    } else {
        void* p = nullptr;
        cudaGetSymbolAddress(&p, g_attn_fallback);
        attn = (float*)p;
    }

    const int S_MMA_SMEM = 4 * 128 * SPAD * 2;   // 73,728 B
    cudaFuncSetAttribute(s_mma_kernel, cudaFuncAttributeMaxDynamicSharedMemorySize, S_MMA_SMEM);

    const int eblocks = (int)((KV_ELEMS + 255) / 256);

    zero_ly_kernel<<<eblocks, 256>>>();
    qkv_gemm_kernel<<<dim3(TWO_C_ / 128, M_ROWS / 128), 256>>>(x, Wqkv, bqkv);
    mu_kernel<<<BH_, 256>>>();

    for (int it = 0; it < 6; ++it) {
        iter_pre_kernel<<<eblocks, 256>>>(it == 0 ? 1 : 0);
        s_mma_kernel<<<dim3(8, 8, BH_), 256, S_MMA_SMEM>>>(attn);
        pv_kernel<<<dim3(N_ / 128, BH_), 256>>>(attn, it == 5 ? 1 : 0);
    }

    proj_gemm_kernel<<<dim3(C_ / 128, M_ROWS / 128), 256>>>(Wproj, bproj, out);
}

// round 5
// speedup vs baseline: 3.2892x; 1.8077x over previous
#include <cuda_runtime.h>
#include <cuda_bf16.h>
#include <math.h>
#include <stdint.h>

// Problem constants
#define B_   8
#define N_   1024
#define C_   768
#define H_   12
#define HD_  64
#define BH_  (B_*H_)
#define TWO_C_ (2*C_)
#define M_ROWS (B_*N_)

static const size_t KV_ELEMS   = (size_t)BH_ * N_ * HD_;
static const size_t OUT_ELEMS  = (size_t)B_ * N_ * C_;
static const size_t ATTN_ELEMS = (size_t)BH_ * N_ * N_;

#define SCALE_ 0.125f
#define LAMBD_ 4.0f

// ---------------- device scratch ----------------
__device__ float g_k [6291456];
__device__ float g_v [6291456];
__device__ float g_l [6291456];
__device__ float g_y [6291456];
__device__ float g_s [6291456];
__device__ __nv_bfloat16 g_k2h[6291456];
__device__ __nv_bfloat16 g_k2l[6291456];
__device__ __nv_bfloat16 g_vh [6291456];
__device__ __nv_bfloat16 g_vl [6291456];
__device__ float g_obnc[6291456];
__device__ float g_mu[96];
__device__ float g_attn_fallback[100663296];

// ---------------- warp mma helpers (sm_80+ PTX) ----------------
__device__ __forceinline__ uint32_t smem_u32(const void* p) {
    uint32_t a;
    asm("{ .reg .u64 t; cvta.to.shared.u64 t, %1; cvt.u32.u64 %0, t; }" : "=r"(a) : "l"(p));
    return a;
}
__device__ __forceinline__ void ldsm4(uint32_t r[4], uint32_t addr) {
    asm volatile("ldmatrix.sync.aligned.m8n8.x4.shared.b16 {%0,%1,%2,%3}, [%4];"
        : "=r"(r[0]), "=r"(r[1]), "=r"(r[2]), "=r"(r[3]) : "r"(addr));
}
__device__ __forceinline__ void ldsm4t(uint32_t r[4], uint32_t addr) {
    asm volatile("ldmatrix.sync.aligned.m8n8.x4.trans.shared.b16 {%0,%1,%2,%3}, [%4];"
        : "=r"(r[0]), "=r"(r[1]), "=r"(r[2]), "=r"(r[3]) : "r"(addr));
}
__device__ __forceinline__ void mma_bf16(float c[4], const uint32_t a[4], const uint32_t* b) {
    asm volatile("mma.sync.aligned.m16n8k16.row.col.f32.bf16.bf16.f32 "
        "{%0,%1,%2,%3}, {%4,%5,%6,%7}, {%8,%9}, {%0,%1,%2,%3};"
        : "+f"(c[0]), "+f"(c[1]), "+f"(c[2]), "+f"(c[3])
        : "r"(a[0]), "r"(a[1]), "r"(a[2]), "r"(a[3]), "r"(b[0]), "r"(b[1]));
}
__device__ __forceinline__ void split2(float x, float y, uint32_t& hi, uint32_t& lo) {
    __nv_bfloat16 hx = __float2bfloat16(x), hy = __float2bfloat16(y);
    __nv_bfloat162 h2; h2.x = hx; h2.y = hy;
    __nv_bfloat162 l2;
    l2.x = __float2bfloat16(x - __bfloat162float(hx));
    l2.y = __float2bfloat16(y - __bfloat162float(hy));
    hi = *reinterpret_cast<uint32_t*>(&h2);
    lo = *reinterpret_cast<uint32_t*>(&l2);
}

// ---------------- elementwise ----------------
__global__ void zero_ly_kernel() {
    size_t i = (size_t)blockIdx.x * 256 + threadIdx.x;
    if (i < KV_ELEMS) { g_l[i] = 0.f; g_y[i] = 0.f; }
}

__global__ void v_split_kernel() {
    size_t i = (size_t)blockIdx.x * 256 + threadIdx.x;
    if (i >= KV_ELEMS) return;
    float v = g_v[i];
    __nv_bfloat16 hi = __float2bfloat16(v);
    g_vh[i] = hi;
    g_vl[i] = __float2bfloat16(v - __bfloat162float(hi));
}

__global__ void iter_pre_kernel(int first) {
    size_t i = (size_t)blockIdx.x * 256 + threadIdx.x;
    if (i >= KV_ELEMS) return;
    int bh = (int)(i / ((size_t)N_ * HD_));
    float mu = g_mu[bh];
    float kk = g_k[i];
    float l  = g_l[i];
    float y  = g_y[i];
    if (!first) {
        y += mu * (kk - l - g_s[i]);
        g_y[i] = y;
    }
    float ymu = y / mu;
    float t   = kk - l + ymu;
    float lm  = LAMBD_ * mu;
    float s   = (t >= lm) ? (t - lm) : ((t <= -lm) ? (t + lm) : 0.f);
    g_s[i] = s;
    float k2 = kk - s - ymu;
    __nv_bfloat16 hi = __float2bfloat16(k2);
    g_k2h[i] = hi;
    g_k2l[i] = __float2bfloat16(k2 - __bfloat162float(hi));
}

__global__ void mu_kernel() {
    __shared__ float red[256];
    int bh = blockIdx.x;
    const float* p = g_k + (size_t)bh * N_ * HD_;
    float s = 0.f;
    for (int i = threadIdx.x; i < N_ * HD_; i += 256) s += fabsf(p[i]);
    red[threadIdx.x] = s;
    __syncthreads();
    for (int st = 128; st > 0; st >>= 1) {
        if (threadIdx.x < st) red[threadIdx.x] += red[threadIdx.x + st];
        __syncthreads();
    }
    if (threadIdx.x == 0) g_mu[bh] = ((float)N_ * (float)C_ / 4.0f) / red[0];
}

// =================== fused flash iteration (iters 0..4) ===================
// grid (8, 96), 256 threads = 8 warps. Warp w owns rows i0 + w*16 .. +16.
// SMEM (bf16 elems): A_hi [0,9216), A_lo [9216,18432),
// stage s at 18432 + s*36864: {Bh, Bl, Vh, Vl} each 9216 (128 rows x 72 pad).
#define FSPAD 72
#define FA_H  0
#define FA_L  9216
#define FSTG  18432
#define FS_BH 0
#define FS_BL 9216
#define FS_VH 18432
#define FS_VL 27648

__global__ void __launch_bounds__(256, 1) flash_iter_kernel() {
    extern __shared__ __nv_bfloat16 fsm[];
    const int bh = blockIdx.y;
    const int i0 = blockIdx.x * 128;
    const int tid = threadIdx.x, wid = tid >> 5, lane = tid & 31;

    const size_t hbase = (size_t)bh * N_ * HD_;
    const __nv_bfloat16* Gh = g_k2h + hbase;
    const __nv_bfloat16* Gl = g_k2l + hbase;
    const __nv_bfloat16* Vh = g_vh + hbase;
    const __nv_bfloat16* Vl = g_vl + hbase;

    // A tile (rows i0..i0+128) regular loads
    #pragma unroll
    for (int i = 0; i < 8; i++) {
        int idx = tid + i * 256;
        int arr = idx >> 10, rem = idx & 1023, row = rem >> 3, c = rem & 7;
        const __nv_bfloat16* src = (arr ? Gl : Gh) + (size_t)(i0 + row) * HD_ + c * 8;
        *(uint4*)(fsm + (arr ? FA_L : FA_H) + row * FSPAD + c * 8) = *(const uint4*)src;
    }

    // cp.async tile prefetch
    auto cp_tile = [&](int stage, int j) {
        int sbase = FSTG + stage * 36864;
        #pragma unroll
        for (int i = 0; i < 16; i++) {
            int idx = tid + i * 256;
            int arr = idx >> 10, rem = idx & 1023, row = rem >> 3, c = rem & 7;
            const __nv_bfloat16* src;
            int off;
            if      (arr == 0) { src = Gh; off = FS_BH; }
            else if (arr == 1) { src = Gl; off = FS_BL; }
            else if (arr == 2) { src = Vh; off = FS_VH; }
            else               { src = Vl; off = FS_VL; }
            src += (size_t)(j * 128 + row) * HD_ + c * 8;
            uint32_t dst = smem_u32(fsm + sbase + off + row * FSPAD + c * 8);
            asm volatile("cp.async.cg.shared.global [%0], [%1], 16;" :: "r"(dst), "l"(src));
        }
    };

    cp_tile(0, 0);
    asm volatile("cp.async.commit_group;" ::: "memory");
    asm volatile("cp.async.wait_group 0;" ::: "memory");
    __syncthreads();

    float m0 = -1e30f, m1 = -1e30f, l0 = 0.f, l1 = 0.f;
    float acco[8][4] = {};

    for (int j = 0; j < 8; j++) {
        if (j < 7) {
            cp_tile((j + 1) & 1, j + 1);
            asm volatile("cp.async.commit_group;" ::: "memory");
        }
        const __nv_bfloat16* sb = fsm + FSTG + (j & 1) * 36864;

        // ---- S = A (k2 hi/lo) x B^T, bf16x3, warp tile 16x128 ----
        float accs[16][4] = {};
        #pragma unroll
        for (int ks = 0; ks < 4; ks++) {
            uint32_t aH[4], aL[4];
            {
                int ar = wid * 16 + (lane & 15);
                int ac = ks * 16 + ((lane >> 4) << 3);
                ldsm4(aH, smem_u32(fsm + FA_H + ar * FSPAD + ac));
                ldsm4(aL, smem_u32(fsm + FA_L + ar * FSPAD + ac));
            }
            #pragma unroll
            for (int ng = 0; ng < 4; ng++) {
                uint32_t bh2[2][4], bl2[2][4];
                #pragma unroll
                for (int p = 0; p < 2; p++) {
                    int nr = ng * 32 + p * 16 + (lane & 7) + ((lane >> 4) << 3);
                    int kc = ks * 16 + (((lane >> 3) & 1) << 3);
                    ldsm4(bh2[p], smem_u32(sb + FS_BH + nr * FSPAD + kc));
                    ldsm4(bl2[p], smem_u32(sb + FS_BL + nr * FSPAD + kc));
                }
                #pragma unroll
                for (int t = 0; t < 4; t++) {
                    float* c = accs[ng * 4 + t];
                    const uint32_t* bhf = &bh2[t >> 1][(t & 1) * 2];
                    const uint32_t* blf = &bl2[t >> 1][(t & 1) * 2];
                    mma_bf16(c, aH, bhf);
                    mma_bf16(c, aH, blf);
                    mma_bf16(c, aL, bhf);
                }
            }
        }

        // ---- online softmax (rows: lane>>2 and +8 within warp stripe) ----
        #pragma unroll
        for (int t = 0; t < 16; t++) {
            accs[t][0] *= SCALE_; accs[t][1] *= SCALE_;
            accs[t][2] *= SCALE_; accs[t][3] *= SCALE_;
        }
        float tm0 = -1e30f, tm1 = -1e30f;
        #pragma unroll
        for (int t = 0; t < 16; t++) {
            tm0 = fmaxf(tm0, fmaxf(accs[t][0], accs[t][1]));
            tm1 = fmaxf(tm1, fmaxf(accs[t][2], accs[t][3]));
        }
        tm0 = fmaxf(tm0, __shfl_xor_sync(0xFFFFFFFF, tm0, 1));
        tm0 = fmaxf(tm0, __shfl_xor_sync(0xFFFFFFFF, tm0, 2));
        tm1 = fmaxf(tm1, __shfl_xor_sync(0xFFFFFFFF, tm1, 1));
        tm1 = fmaxf(tm1, __shfl_xor_sync(0xFFFFFFFF, tm1, 2));
        float mn0 = fmaxf(m0, tm0), mn1 = fmaxf(m1, tm1);
        float sc0 = __expf(m0 - mn0), sc1 = __expf(m1 - mn1);
        m0 = mn0; m1 = mn1;
        float rs0 = 0.f, rs1 = 0.f;
        #pragma unroll
        for (int t = 0; t < 16; t++) {
            accs[t][0] = __expf(accs[t][0] - m0);
            accs[t][1] = __expf(accs[t][1] - m0);
            accs[t][2] = __expf(accs[t][2] - m1);
            accs[t][3] = __expf(accs[t][3] - m1);
            rs0 += accs[t][0] + accs[t][1];
            rs1 += accs[t][2] + accs[t][3];
        }
        rs0 += __shfl_xor_sync(0xFFFFFFFF, rs0, 1);
        rs0 += __shfl_xor_sync(0xFFFFFFFF, rs0, 2);
        rs1 += __shfl_xor_sync(0xFFFFFFFF, rs1, 1);
        rs1 += __shfl_xor_sync(0xFFFFFFFF, rs1, 2);
        l0 = l0 * sc0 + rs0;
        l1 = l1 * sc1 + rs1;
        #pragma unroll
        for (int o = 0; o < 8; o++) {
            acco[o][0] *= sc0; acco[o][1] *= sc0;
            acco[o][2] *= sc1; acco[o][3] *= sc1;
        }

        // ---- PV: P (hi/lo from regs) x V (hi/lo), bf16x3 ----
        #pragma unroll
        for (int kt = 0; kt < 8; kt++) {
            uint32_t pH[4], pL[4];
            split2(accs[2*kt][0],   accs[2*kt][1],   pH[0], pL[0]);
            split2(accs[2*kt][2],   accs[2*kt][3],   pH[1], pL[1]);
            split2(accs[2*kt+1][0], accs[2*kt+1][1], pH[2], pL[2]);
            split2(accs[2*kt+1][2], accs[2*kt+1][3], pH[3], pL[3]);
            #pragma unroll
            for (int vg = 0; vg < 2; vg++) {
                uint32_t vh2[2][4], vl2[2][4];
                #pragma unroll
                for (int q = 0; q < 2; q++) {
                    int vr = kt * 16 + (lane & 15);
                    int vc = vg * 32 + q * 16 + ((lane >> 4) << 3);
                    ldsm4t(vh2[q], smem_u32(sb + FS_VH + vr * FSPAD + vc));
                    ldsm4t(vl2[q], smem_u32(sb + FS_VL + vr * FSPAD + vc));
                }
                #pragma unroll
                for (int t = 0; t < 4; t++) {
                    float* o = acco[vg * 4 + t];
                    const uint32_t* vhf = &vh2[t >> 1][(t & 1) * 2];
                    const uint32_t* vlf = &vl2[t >> 1][(t & 1) * 2];
                    mma_bf16(o, pH, vhf);
                    mma_bf16(o, pH, vlf);
                    mma_bf16(o, pL, vhf);
                }
            }
        }

        if (j < 7) asm volatile("cp.async.wait_group 0;" ::: "memory");
        __syncthreads();
    }

    // ---- finalize: O /= l, write to g_l ----
    float inv0 = 1.f / l0, inv1 = 1.f / l1;
    float* dst = g_l + hbase;
    int row0 = i0 + wid * 16 + (lane >> 2);
    #pragma unroll
    for (int o = 0; o < 8; o++) {
        int col = o * 8 + (lane & 3) * 2;
        float2 v0 = make_float2(acco[o][0] * inv0, acco[o][1] * inv0);
        float2 v1 = make_float2(acco[o][2] * inv1, acco[o][3] * inv1);
        *(float2*)&dst[(size_t)row0 * HD_ + col]       = v0;
        *(float2*)&dst[(size_t)(row0 + 8) * HD_ + col] = v1;
    }
}

// ---------------- S = scale * k2 @ k2^T via HMMA bf16x3 (final iter) ----------------
#define SPAD 72
__global__ void __launch_bounds__(256, 1) s_mma_kernel(float* __restrict__ attn) {
    extern __shared__ __nv_bfloat16 sm[];
    const int bh = blockIdx.z;
    const int bx = blockIdx.x * 128;
    const int by = blockIdx.y * 128;
    const int tid  = threadIdx.x;
    const int wid  = tid >> 5;
    const int lane = tid & 31;

    __nv_bfloat16* sAh = sm;
    __nv_bfloat16* sAl = sm + 128 * SPAD;
    __nv_bfloat16* sBh = sm + 2 * 128 * SPAD;
    __nv_bfloat16* sBl = sm + 3 * 128 * SPAD;

    const __nv_bfloat16* Gh = g_k2h + (size_t)bh * N_ * HD_;
    const __nv_bfloat16* Gl = g_k2l + (size_t)bh * N_ * HD_;

    #pragma unroll
    for (int i = 0; i < 4; i++) {
        int idx = tid + i * 256;
        int row = idx >> 3, c = idx & 7;
        *(uint4*)(sAh + row * SPAD + c * 8) = *(const uint4*)(Gh + (size_t)(by + row) * HD_ + c * 8);
        *(uint4*)(sAl + row * SPAD + c * 8) = *(const uint4*)(Gl + (size_t)(by + row) * HD_ + c * 8);
        *(uint4*)(sBh + row * SPAD + c * 8) = *(const uint4*)(Gh + (size_t)(bx + row) * HD_ + c * 8);
        *(uint4*)(sBl + row * SPAD + c * 8) = *(const uint4*)(Gl + (size_t)(bx + row) * HD_ + c * 8);
    }
    __syncthreads();

    const int wm = wid & 1;
    const int wn = wid >> 1;
    float acc[4][4][4] = {};

    const int a_r8   = lane & 7;
    const int a_roff = ((lane >> 3) & 1) * 8;
    const int a_koff = (lane >> 4) * 8;
    const int b_noff = (lane >> 4) * 8;
    const int b_koff = ((lane >> 3) & 1) * 8;

    #pragma unroll
    for (int ks = 0; ks < 4; ks++) {
        uint32_t aH[4][4], aL[4][4], bH[2][4], bL[2][4];
        #pragma unroll
        for (int mt = 0; mt < 4; mt++) {
            int row = wm * 64 + mt * 16 + a_r8 + a_roff;
            int kc  = ks * 16 + a_koff;
            ldsm4(aH[mt], smem_u32(sAh + row * SPAD + kc));
            ldsm4(aL[mt], smem_u32(sAl + row * SPAD + kc));
        }
        #pragma unroll
        for (int p = 0; p < 2; p++) {
            int nrow = wn * 32 + p * 16 + a_r8 + b_noff;
            int kc   = ks * 16 + b_koff;
            ldsm4(bH[p], smem_u32(sBh + nrow * SPAD + kc));
            ldsm4(bL[p], smem_u32(sBl + nrow * SPAD + kc));
        }
        #pragma unroll
        for (int mt = 0; mt < 4; mt++)
            #pragma unroll
            for (int nt = 0; nt < 4; nt++) {
                const uint32_t* bh_f = &bH[nt >> 1][(nt & 1) * 2];
                const uint32_t* bl_f = &bL[nt >> 1][(nt & 1) * 2];
                mma_bf16(acc[mt][nt], aH[mt], bh_f);
                mma_bf16(acc[mt][nt], aH[mt], bl_f);
                mma_bf16(acc[mt][nt], aL[mt], bh_f);
            }
    }
    __syncthreads();

    float* ep = (float*)sm;
    const int erow = lane >> 2;
    const int ecol = (lane & 3) * 2;
    #pragma unroll
    for (int mt = 0; mt < 4; mt++)
        #pragma unroll
        for (int nt = 0; nt < 4; nt++) {
            int r = wm * 64 + mt * 16 + erow;
            int c = wn * 32 + nt * 8 + ecol;
            ep[r * 132 + c]           = acc[mt][nt][0] * SCALE_;
            ep[r * 132 + c + 1]       = acc[mt][nt][1] * SCALE_;
            ep[(r + 8) * 132 + c]     = acc[mt][nt][2] * SCALE_;
            ep[(r + 8) * 132 + c + 1] = acc[mt][nt][3] * SCALE_;
        }
    __syncthreads();

    float* Sp = attn + (size_t)bh * N_ * N_;
    #pragma unroll
    for (int i = 0; i < 16; i++) {
        int idx = tid + i * 256;
        int rr  = idx >> 5;
        int c4  = idx & 31;
        float4 v = *(const float4*)&ep[rr * 132 + c4 * 4];
        *(float4*)&Sp[(size_t)(by + rr) * N_ + bx + c4 * 4] = v;
    }
}

// ---------------- fused softmax + PV (final iter; materializes attn) ----------------
__global__ void __launch_bounds__(256, 2) pv_kernel(float* __restrict__ attn, int final_mode) {
    __shared__ float As[32][132];
    __shared__ float Bs[32][68];
    __shared__ float sm_m[128], sm_inv[128];
    __shared__ float red_m[256], red_s[256];

    const int bh = blockIdx.y;
    const int by = blockIdx.x * 128;
    float* __restrict__ Sp = attn + (size_t)bh * N_ * N_;
    const float* __restrict__ V = g_v + (size_t)bh * N_ * HD_;
    const int tid = threadIdx.x;

    {
        int r    = tid >> 1;
        int half = tid & 1;
        const float* row = Sp + (size_t)(by + r) * N_ + half * 512;
        float m = -1e30f, s = 0.f;
        for (int c = 0; c < 512; c += 4) {
            float4 v = *(const float4*)&row[c];
            float xs[4] = {v.x, v.y, v.z, v.w};
            #pragma unroll
            for (int q = 0; q < 4; q++) {
                float x = xs[q];
                if (x > m) { s = s * __expf(m - x) + 1.f; m = x; }
                else       { s += __expf(x - m); }
            }
        }
        red_m[tid] = m; red_s[tid] = s;
        __syncthreads();
        if (half == 0) {
            float m2 = red_m[tid + 1], s2 = red_s[tid + 1];
            float M  = fmaxf(m, m2);
            float S  = s * __expf(m - M) + s2 * __expf(m2 - M);
            sm_m[r]   = M;
            sm_inv[r] = 1.0f / S;
        }
        __syncthreads();
    }

    const int tx = tid & 15, ty = tid >> 4;
    float acc[8][4] = {};
    for (int k0 = 0; k0 < N_; k0 += 32) {
        #pragma unroll
        for (int i = 0; i < 4; i++) {
            int idx = tid + i * 256;
            int m   = idx >> 3;
            int kq  = (idx & 7) * 4;
            float* src = &Sp[(size_t)(by + m) * N_ + k0 + kq];
            float4 v = *(const float4*)src;
            float mm = sm_m[m], inv = sm_inv[m];
            v.x = __expf(v.x - mm) * inv;
            v.y = __expf(v.y - mm) * inv;
            v.z = __expf(v.z - mm) * inv;
            v.w = __expf(v.w - mm) * inv;
            if (final_mode) *(float4*)src = v;
            As[kq + 0][m] = v.x; As[kq + 1][m] = v.y;
            As[kq + 2][m] = v.z; As[kq + 3][m] = v.w;
        }
        #pragma unroll
        for (int i = 0; i < 2; i++) {
            int idx = tid + i * 256;
            int r   = idx >> 4;
            int cq  = (idx & 15) * 4;
            *(float4*)&Bs[r][cq] = *(const float4*)&V[(size_t)(k0 + r) * HD_ + cq];
        }
        __syncthreads();
        #pragma unroll
        for (int kk = 0; kk < 32; kk++) {
            float4 a0 = *(const float4*)&As[kk][ty * 8];
            float4 a1 = *(const float4*)&As[kk][ty * 8 + 4];
            float4 b4 = *(const float4*)&Bs[kk][tx * 4];
            float a[8] = {a0.x, a0.y, a0.z, a0.w, a1.x, a1.y, a1.z, a1.w};
            float b[4] = {b4.x, b4.y, b4.z, b4.w};
            #pragma unroll
            for (int i = 0; i < 8; i++)
                #pragma unroll
                for (int j = 0; j < 4; j++) acc[i][j] += a[i] * b[j];
        }
        __syncthreads();
    }

    int b = bh / H_, h = bh % H_;
    #pragma unroll
    for (int i = 0; i < 8; i++) {
        int r = by + ty * 8 + i;
        float4 v0 = make_float4(acc[i][0], acc[i][1], acc[i][2], acc[i][3]);
        if (final_mode)
            *(float4*)&g_obnc[((size_t)(b * N_ + r)) * C_ + h * HD_ + tx * 4] = v0;
        else
            *(float4*)&g_l[((size_t)bh * N_ + r) * HD_ + tx * 4] = v0;
    }
}

// ---------------- qkv = x @ W_qkv + b ----------------
__global__ void __launch_bounds__(256, 2) qkv_gemm_kernel(const float* __restrict__ x,
                                                          const float* __restrict__ W,
                                                          const float* __restrict__ bias) {
    __shared__ float As[16][132];
    __shared__ float Bs[16][132];
    const int bx = blockIdx.x * 128;
    const int by = blockIdx.y * 128;
    const int tid = threadIdx.x;
    const int tx = tid & 15, ty = tid >> 4;
    float acc[8][8] = {};

    for (int k0 = 0; k0 < C_; k0 += 16) {
        #pragma unroll
        for (int i = 0; i < 2; i++) {
            int idx = tid + i * 256;
            int m  = idx >> 2;
            int kq = (idx & 3) * 4;
            float4 a = *(const float4*)&x[(size_t)(by + m) * C_ + k0 + kq];
            As[kq + 0][m] = a.x; As[kq + 1][m] = a.y;
            As[kq + 2][m] = a.z; As[kq + 3][m] = a.w;
            int r  = idx >> 5;
            int cq = (idx & 31) * 4;
            *(float4*)&Bs[r][cq] = *(const float4*)&W[(size_t)(k0 + r) * TWO_C_ + bx + cq];
        }
        __syncthreads();
        #pragma unroll
        for (int kk = 0; kk < 16; kk++) {
            float4 a0 = *(const float4*)&As[kk][ty * 8];
            float4 a1 = *(const float4*)&As[kk][ty * 8 + 4];
            float4 b0 = *(const float4*)&Bs[kk][tx * 8];
            float4 b1 = *(const float4*)&Bs[kk][tx * 8 + 4];
            float a[8] = {a0.x, a0.y, a0.z, a0.w, a1.x, a1.y, a1.z, a1.w};
            float b[8] = {b0.x, b0.y, b0.z, b0.w, b1.x, b1.y, b1.z, b1.w};
            #pragma unroll
            for (int i = 0; i < 8; i++)
                #pragma unroll
                for (int j = 0; j < 8; j++) acc[i][j] += a[i] * b[j];
        }
        __syncthreads();
    }

    #pragma unroll
    for (int i = 0; i < 8; i++) {
        int mrow = by + ty * 8 + i;
        int b = mrow >> 10, n = mrow & 1023;
        #pragma unroll
        for (int jj = 0; jj < 2; jj++) {
            int col0 = bx + tx * 8 + jj * 4;
            int which = col0 / C_;
            int h  = (col0 % C_) / HD_;
            int hd = col0 % HD_;
            float* dst = which ? g_v : g_k;
            float4 v = make_float4(acc[i][jj*4+0] + bias[col0+0],
                                   acc[i][jj*4+1] + bias[col0+1],
                                   acc[i][jj*4+2] + bias[col0+2],
                                   acc[i][jj*4+3] + bias[col0+3]);
            *(float4*)&dst[(((size_t)(b * H_ + h)) * N_ + n) * HD_ + hd] = v;
        }
    }
}

// ---------------- out = obnc @ W_proj + b_proj ----------------
__global__ void __launch_bounds__(256, 2) proj_gemm_kernel(const float* __restrict__ W,
                                                           const float* __restrict__ bias,
                                                           float* __restrict__ out) {
    __shared__ float As[16][132];
    __shared__ float Bs[16][132];
    const int bx = blockIdx.x * 128;
    const int by = blockIdx.y * 128;
    const int tid = threadIdx.x;
    const int tx = tid & 15, ty = tid >> 4;
    float acc[8][8] = {};

    for (int k0 = 0; k0 < C_; k0 += 16) {
        #pragma unroll
        for (int i = 0; i < 2; i++) {
            int idx = tid + i * 256;
            int m  = idx >> 2;
            int kq = (idx & 3) * 4;
            float4 a = *(const float4*)&g_obnc[(size_t)(by + m) * C_ + k0 + kq];
            As[kq + 0][m] = a.x; As[kq + 1][m] = a.y;
            As[kq + 2][m] = a.z; As[kq + 3][m] = a.w;
            int r  = idx >> 5;
            int cq = (idx & 31) * 4;
            *(float4*)&Bs[r][cq] = *(const float4*)&W[(size_t)(k0 + r) * C_ + bx + cq];
        }
        __syncthreads();
        #pragma unroll
        for (int kk = 0; kk < 16; kk++) {
            float4 a0 = *(const float4*)&As[kk][ty * 8];
            float4 a1 = *(const float4*)&As[kk][ty * 8 + 4];
            float4 b0 = *(const float4*)&Bs[kk][tx * 8];
            float4 b1 = *(const float4*)&Bs[kk][tx * 8 + 4];
            float a[8] = {a0.x, a0.y, a0.z, a0.w, a1.x, a1.y, a1.z, a1.w};
            float b[8] = {b0.x, b0.y, b0.z, b0.w, b1.x, b1.y, b1.z, b1.w};
            #pragma unroll
            for (int i = 0; i < 8; i++)
                #pragma unroll
                for (int j = 0; j < 8; j++) acc[i][j] += a[i] * b[j];
        }
        __syncthreads();
    }

    #pragma unroll
    for (int i = 0; i < 8; i++) {
        int m = by + ty * 8 + i;
        #pragma unroll
        for (int jj = 0; jj < 2; jj++) {
            int col0 = bx + tx * 8 + jj * 4;
            float4 v = make_float4(acc[i][jj*4+0] + bias[col0+0],
                                   acc[i][jj*4+1] + bias[col0+1],
                                   acc[i][jj*4+2] + bias[col0+2],
                                   acc[i][jj*4+3] + bias[col0+3]);
            *(float4*)&out[(size_t)m * C_ + col0] = v;
        }
    }
}

// ---------------- launch ----------------
extern "C" void kernel_launch(void* const* d_in, const int* in_sizes, int n_in,
                              void* d_out, int out_size) {
    const float* x     = (const float*)d_in[0];
    const float* Wqkv  = (const float*)d_in[1];
    const float* bqkv  = (const float*)d_in[2];
    const float* Wproj = (const float*)d_in[3];
    const float* bproj = (const float*)d_in[4];
    float* out = (float*)d_out;

    float* attn;
    if ((size_t)out_size >= OUT_ELEMS + ATTN_ELEMS) {
        attn = out + OUT_ELEMS;
    } else {
        void* p = nullptr;
        cudaGetSymbolAddress(&p, g_attn_fallback);
        attn = (float*)p;
    }

    const int S_MMA_SMEM  = 4 * 128 * SPAD * 2;          // 73,728 B
    const int FLASH_SMEM  = (18432 + 2 * 36864) * 2;     // 184,320 B
    cudaFuncSetAttribute(s_mma_kernel, cudaFuncAttributeMaxDynamicSharedMemorySize, S_MMA_SMEM);
    cudaFuncSetAttribute(flash_iter_kernel, cudaFuncAttributeMaxDynamicSharedMemorySize, FLASH_SMEM);

    const int eblocks = (int)((KV_ELEMS + 255) / 256);

    zero_ly_kernel<<<eblocks, 256>>>();
    qkv_gemm_kernel<<<dim3(TWO_C_ / 128, M_ROWS / 128), 256>>>(x, Wqkv, bqkv);
    v_split_kernel<<<eblocks, 256>>>();
    mu_kernel<<<BH_, 256>>>();

    for (int it = 0; it < 6; ++it) {
        iter_pre_kernel<<<eblocks, 256>>>(it == 0 ? 1 : 0);
        if (it < 5) {
            flash_iter_kernel<<<dim3(N_ / 128, BH_), 256, FLASH_SMEM>>>();
        } else {
            s_mma_kernel<<<dim3(8, 8, BH_), 256, S_MMA_SMEM>>>(attn);
            pv_kernel<<<dim3(N_ / 128, BH_), 256>>>(attn, 1);
        }
    }

    proj_gemm_kernel<<<dim3(C_ / 128, M_ROWS / 128), 256>>>(Wproj, bproj, out);
}

// round 6
// speedup vs baseline: 4.5260x; 1.3760x over previous
#include <cuda_runtime.h>
#include <cuda_bf16.h>
#include <math.h>
#include <stdint.h>

#define B_   8
#define N_   1024
#define C_   768
#define H_   12
#define HD_  64
#define BH_  (B_*H_)
#define TWO_C_ (2*C_)
#define M_ROWS (B_*N_)

static const size_t KV_ELEMS   = (size_t)BH_ * N_ * HD_;
static const size_t OUT_ELEMS  = (size_t)B_ * N_ * C_;
static const size_t ATTN_ELEMS = (size_t)BH_ * N_ * N_;

#define SCALE_ 0.125f
#define LAMBD_ 4.0f

// ---------------- device scratch ----------------
__device__ float g_k [6291456];
__device__ float g_l [6291456];
__device__ float g_y [6291456];
__device__ float g_s [6291456];
__device__ __nv_bfloat16 g_k2h[6291456];
__device__ __nv_bfloat16 g_k2l[6291456];
__device__ __nv_bfloat16 g_vh [6291456];
__device__ __nv_bfloat16 g_vl [6291456];
__device__ __nv_bfloat16 g_xh [6291456];
__device__ __nv_bfloat16 g_xl [6291456];
__device__ __nv_bfloat16 g_wqh[1179648];
__device__ __nv_bfloat16 g_wql[1179648];
__device__ __nv_bfloat16 g_wph[589824];
__device__ __nv_bfloat16 g_wpl[589824];
__device__ __nv_bfloat16 g_och[6291456];
__device__ __nv_bfloat16 g_ocl[6291456];
__device__ float g_mu[96];
__device__ float g_attn_fallback[100663296];

// ---------------- warp mma helpers ----------------
__device__ __forceinline__ uint32_t smem_u32(const void* p) {
    uint32_t a;
    asm("{ .reg .u64 t; cvta.to.shared.u64 t, %1; cvt.u32.u64 %0, t; }" : "=r"(a) : "l"(p));
    return a;
}
__device__ __forceinline__ void ldsm4(uint32_t r[4], uint32_t addr) {
    asm volatile("ldmatrix.sync.aligned.m8n8.x4.shared.b16 {%0,%1,%2,%3}, [%4];"
        : "=r"(r[0]), "=r"(r[1]), "=r"(r[2]), "=r"(r[3]) : "r"(addr));
}
__device__ __forceinline__ void ldsm4t(uint32_t r[4], uint32_t addr) {
    asm volatile("ldmatrix.sync.aligned.m8n8.x4.trans.shared.b16 {%0,%1,%2,%3}, [%4];"
        : "=r"(r[0]), "=r"(r[1]), "=r"(r[2]), "=r"(r[3]) : "r"(addr));
}
__device__ __forceinline__ void mma_bf16(float c[4], const uint32_t a[4], const uint32_t* b) {
    asm volatile("mma.sync.aligned.m16n8k16.row.col.f32.bf16.bf16.f32 "
        "{%0,%1,%2,%3}, {%4,%5,%6,%7}, {%8,%9}, {%0,%1,%2,%3};"
        : "+f"(c[0]), "+f"(c[1]), "+f"(c[2]), "+f"(c[3])
        : "r"(a[0]), "r"(a[1]), "r"(a[2]), "r"(a[3]), "r"(b[0]), "r"(b[1]));
}
__device__ __forceinline__ void split2(float x, float y, uint32_t& hi, uint32_t& lo) {
    __nv_bfloat16 hx = __float2bfloat16(x), hy = __float2bfloat16(y);
    __nv_bfloat162 h2; h2.x = hx; h2.y = hy;
    __nv_bfloat162 l2;
    l2.x = __float2bfloat16(x - __bfloat162float(hx));
    l2.y = __float2bfloat16(y - __bfloat162float(hy));
    hi = *reinterpret_cast<uint32_t*>(&h2);
    lo = *reinterpret_cast<uint32_t*>(&l2);
}
__device__ __forceinline__ void cp16(uint32_t dst, const void* src) {
    asm volatile("cp.async.cg.shared.global [%0], [%1], 16;" :: "r"(dst), "l"(src));
}
#define CP_COMMIT() asm volatile("cp.async.commit_group;" ::: "memory")
#define CP_WAIT0()  asm volatile("cp.async.wait_group 0;" ::: "memory")

// ---------------- elementwise ----------------
__global__ void zero_ly_kernel() {
    size_t i = (size_t)blockIdx.x * 256 + threadIdx.x;
    if (i < KV_ELEMS) { g_l[i] = 0.f; g_y[i] = 0.f; }
}

__global__ void split_kernel(const float* __restrict__ src, __nv_bfloat16* __restrict__ h,
                             __nv_bfloat16* __restrict__ l, int n) {
    int i = blockIdx.x * 256 + threadIdx.x;
    if (i >= n) return;
    float v = src[i];
    __nv_bfloat16 hi = __float2bfloat16(v);
    h[i] = hi;
    l[i] = __float2bfloat16(v - __bfloat162float(hi));
}

__global__ void iter_pre_kernel(int first) {
    size_t i = (size_t)blockIdx.x * 256 + threadIdx.x;
    if (i >= KV_ELEMS) return;
    int bh = (int)(i / ((size_t)N_ * HD_));
    float mu = g_mu[bh];
    float kk = g_k[i];
    float l  = g_l[i];
    float y  = g_y[i];
    if (!first) {
        y += mu * (kk - l - g_s[i]);
        g_y[i] = y;
    }
    float ymu = y / mu;
    float t   = kk - l + ymu;
    float lm  = LAMBD_ * mu;
    float s   = (t >= lm) ? (t - lm) : ((t <= -lm) ? (t + lm) : 0.f);
    g_s[i] = s;
    float k2 = kk - s - ymu;
    __nv_bfloat16 hi = __float2bfloat16(k2);
    g_k2h[i] = hi;
    g_k2l[i] = __float2bfloat16(k2 - __bfloat162float(hi));
}

__global__ void mu_kernel() {
    __shared__ float red[256];
    int bh = blockIdx.x;
    const float* p = g_k + (size_t)bh * N_ * HD_;
    float s = 0.f;
    for (int i = threadIdx.x; i < N_ * HD_; i += 256) s += fabsf(p[i]);
    red[threadIdx.x] = s;
    __syncthreads();
    for (int st = 128; st > 0; st >>= 1) {
        if (threadIdx.x < st) red[threadIdx.x] += red[threadIdx.x + st];
        __syncthreads();
    }
    if (threadIdx.x == 0) g_mu[bh] = ((float)N_ * (float)C_ / 4.0f) / red[0];
}

// =================== flash iteration (iters 0..4) ===================
#define FSPAD 72
#define FA_H  0
#define FA_L  9216
#define FSTG  18432
#define FS_BH 0
#define FS_BL 9216
#define FS_VH 18432
#define FS_VL 27648

__global__ void __launch_bounds__(256, 1) flash_iter_kernel() {
    extern __shared__ __nv_bfloat16 fsm[];
    const int bh = blockIdx.y;
    const int i0 = blockIdx.x * 128;
    const int tid = threadIdx.x, wid = tid >> 5, lane = tid & 31;

    const size_t hbase = (size_t)bh * N_ * HD_;
    const __nv_bfloat16* Gh = g_k2h + hbase;
    const __nv_bfloat16* Gl = g_k2l + hbase;
    const __nv_bfloat16* Vh = g_vh + hbase;
    const __nv_bfloat16* Vl = g_vl + hbase;

    #pragma unroll
    for (int i = 0; i < 8; i++) {
        int idx = tid + i * 256;
        int arr = idx >> 10, rem = idx & 1023, row = rem >> 3, c = rem & 7;
        const __nv_bfloat16* src = (arr ? Gl : Gh) + (size_t)(i0 + row) * HD_ + c * 8;
        *(uint4*)(fsm + (arr ? FA_L : FA_H) + row * FSPAD + c * 8) = *(const uint4*)src;
    }

    auto cp_tile = [&](int stage, int j) {
        int sbase = FSTG + stage * 36864;
        #pragma unroll
        for (int i = 0; i < 16; i++) {
            int idx = tid + i * 256;
            int arr = idx >> 10, rem = idx & 1023, row = rem >> 3, c = rem & 7;
            const __nv_bfloat16* src;
            int off;
            if      (arr == 0) { src = Gh; off = FS_BH; }
            else if (arr == 1) { src = Gl; off = FS_BL; }
            else if (arr == 2) { src = Vh; off = FS_VH; }
            else               { src = Vl; off = FS_VL; }
            src += (size_t)(j * 128 + row) * HD_ + c * 8;
            cp16(smem_u32(fsm + sbase + off + row * FSPAD + c * 8), src);
        }
    };

    cp_tile(0, 0);
    CP_COMMIT(); CP_WAIT0();
    __syncthreads();

    float m0 = -1e30f, m1 = -1e30f, l0 = 0.f, l1 = 0.f;
    float acco[8][4] = {};

    for (int j = 0; j < 8; j++) {
        if (j < 7) { cp_tile((j + 1) & 1, j + 1); CP_COMMIT(); }
        const __nv_bfloat16* sb = fsm + FSTG + (j & 1) * 36864;

        float accs[16][4] = {};
        #pragma unroll
        for (int ks = 0; ks < 4; ks++) {
            uint32_t aH[4], aL[4];
            {
                int ar = wid * 16 + (lane & 15);
                int ac = ks * 16 + ((lane >> 4) << 3);
                ldsm4(aH, smem_u32(fsm + FA_H + ar * FSPAD + ac));
                ldsm4(aL, smem_u32(fsm + FA_L + ar * FSPAD + ac));
            }
            #pragma unroll
            for (int ng = 0; ng < 4; ng++) {
                uint32_t bh2[2][4], bl2[2][4];
                #pragma unroll
                for (int p = 0; p < 2; p++) {
                    int nr = ng * 32 + p * 16 + (lane & 7) + ((lane >> 4) << 3);
                    int kc = ks * 16 + (((lane >> 3) & 1) << 3);
                    ldsm4(bh2[p], smem_u32(sb + FS_BH + nr * FSPAD + kc));
                    ldsm4(bl2[p], smem_u32(sb + FS_BL + nr * FSPAD + kc));
                }
                #pragma unroll
                for (int t = 0; t < 4; t++) {
                    float* c = accs[ng * 4 + t];
                    const uint32_t* bhf = &bh2[t >> 1][(t & 1) * 2];
                    const uint32_t* blf = &bl2[t >> 1][(t & 1) * 2];
                    mma_bf16(c, aH, bhf);
                    mma_bf16(c, aH, blf);
                    mma_bf16(c, aL, bhf);
                }
            }
        }

        #pragma unroll
        for (int t = 0; t < 16; t++) {
            accs[t][0] *= SCALE_; accs[t][1] *= SCALE_;
            accs[t][2] *= SCALE_; accs[t][3] *= SCALE_;
        }
        float tm0 = -1e30f, tm1 = -1e30f;
        #pragma unroll
        for (int t = 0; t < 16; t++) {
            tm0 = fmaxf(tm0, fmaxf(accs[t][0], accs[t][1]));
            tm1 = fmaxf(tm1, fmaxf(accs[t][2], accs[t][3]));
        }
        tm0 = fmaxf(tm0, __shfl_xor_sync(0xFFFFFFFF, tm0, 1));
        tm0 = fmaxf(tm0, __shfl_xor_sync(0xFFFFFFFF, tm0, 2));
        tm1 = fmaxf(tm1, __shfl_xor_sync(0xFFFFFFFF, tm1, 1));
        tm1 = fmaxf(tm1, __shfl_xor_sync(0xFFFFFFFF, tm1, 2));
        float mn0 = fmaxf(m0, tm0), mn1 = fmaxf(m1, tm1);
        float sc0 = __expf(m0 - mn0), sc1 = __expf(m1 - mn1);
        m0 = mn0; m1 = mn1;
        float rs0 = 0.f, rs1 = 0.f;
        #pragma unroll
        for (int t = 0; t < 16; t++) {
            accs[t][0] = __expf(accs[t][0] - m0);
            accs[t][1] = __expf(accs[t][1] - m0);
            accs[t][2] = __expf(accs[t][2] - m1);
            accs[t][3] = __expf(accs[t][3] - m1);
            rs0 += accs[t][0] + accs[t][1];
            rs1 += accs[t][2] + accs[t][3];
        }
        rs0 += __shfl_xor_sync(0xFFFFFFFF, rs0, 1);
        rs0 += __shfl_xor_sync(0xFFFFFFFF, rs0, 2);
        rs1 += __shfl_xor_sync(0xFFFFFFFF, rs1, 1);
        rs1 += __shfl_xor_sync(0xFFFFFFFF, rs1, 2);
        l0 = l0 * sc0 + rs0;
        l1 = l1 * sc1 + rs1;
        #pragma unroll
        for (int o = 0; o < 8; o++) {
            acco[o][0] *= sc0; acco[o][1] *= sc0;
            acco[o][2] *= sc1; acco[o][3] *= sc1;
        }

        #pragma unroll
        for (int kt = 0; kt < 8; kt++) {
            uint32_t pH[4], pL[4];
            split2(accs[2*kt][0],   accs[2*kt][1],   pH[0], pL[0]);
            split2(accs[2*kt][2],   accs[2*kt][3],   pH[1], pL[1]);
            split2(accs[2*kt+1][0], accs[2*kt+1][1], pH[2], pL[2]);
            split2(accs[2*kt+1][2], accs[2*kt+1][3], pH[3], pL[3]);
            #pragma unroll
            for (int vg = 0; vg < 2; vg++) {
                uint32_t vh2[2][4], vl2[2][4];
                #pragma unroll
                for (int q = 0; q < 2; q++) {
                    int vr = kt * 16 + (lane & 15);
                    int vc = vg * 32 + q * 16 + ((lane >> 4) << 3);
                    ldsm4t(vh2[q], smem_u32(sb + FS_VH + vr * FSPAD + vc));
                    ldsm4t(vl2[q], smem_u32(sb + FS_VL + vr * FSPAD + vc));
                }
                #pragma unroll
                for (int t = 0; t < 4; t++) {
                    float* o = acco[vg * 4 + t];
                    const uint32_t* vhf = &vh2[t >> 1][(t & 1) * 2];
                    const uint32_t* vlf = &vl2[t >> 1][(t & 1) * 2];
                    mma_bf16(o, pH, vhf);
                    mma_bf16(o, pH, vlf);
                    mma_bf16(o, pL, vhf);
                }
            }
        }

        if (j < 7) CP_WAIT0();
        __syncthreads();
    }

    float inv0 = 1.f / l0, inv1 = 1.f / l1;
    float* dst = g_l + hbase;
    int row0 = i0 + wid * 16 + (lane >> 2);
    #pragma unroll
    for (int o = 0; o < 8; o++) {
        int col = o * 8 + (lane & 3) * 2;
        float2 v0 = make_float2(acco[o][0] * inv0, acco[o][1] * inv0);
        float2 v1 = make_float2(acco[o][2] * inv1, acco[o][3] * inv1);
        *(float2*)&dst[(size_t)row0 * HD_ + col]       = v0;
        *(float2*)&dst[(size_t)(row0 + 8) * HD_ + col] = v1;
    }
}

// =================== final iteration: 2-pass flash, materializes attn + obnc ===================
__global__ void __launch_bounds__(256, 1) final_flash_kernel(float* __restrict__ attn) {
    extern __shared__ __nv_bfloat16 fsm[];
    const int bh = blockIdx.y;
    const int i0 = blockIdx.x * 128;
    const int tid = threadIdx.x, wid = tid >> 5, lane = tid & 31;

    const size_t hbase = (size_t)bh * N_ * HD_;
    const __nv_bfloat16* Gh = g_k2h + hbase;
    const __nv_bfloat16* Gl = g_k2l + hbase;
    const __nv_bfloat16* Vh = g_vh + hbase;
    const __nv_bfloat16* Vl = g_vl + hbase;

    #pragma unroll
    for (int i = 0; i < 8; i++) {
        int idx = tid + i * 256;
        int arr = idx >> 10, rem = idx & 1023, row = rem >> 3, c = rem & 7;
        const __nv_bfloat16* src = (arr ? Gl : Gh) + (size_t)(i0 + row) * HD_ + c * 8;
        *(uint4*)(fsm + (arr ? FA_L : FA_H) + row * FSPAD + c * 8) = *(const uint4*)src;
    }

    auto cp_tile = [&](int stage, int j, bool withV) {
        int sbase = FSTG + stage * 36864;
        #pragma unroll
        for (int i = 0; i < 16; i++) {
            int idx = tid + i * 256;
            int arr = idx >> 10, rem = idx & 1023, row = rem >> 3, c = rem & 7;
            if (!withV && arr >= 2) continue;
            const __nv_bfloat16* src;
            int off;
            if      (arr == 0) { src = Gh; off = FS_BH; }
            else if (arr == 1) { src = Gl; off = FS_BL; }
            else if (arr == 2) { src = Vh; off = FS_VH; }
            else               { src = Vl; off = FS_VL; }
            src += (size_t)(j * 128 + row) * HD_ + c * 8;
            cp16(smem_u32(fsm + sbase + off + row * FSPAD + c * 8), src);
        }
    };

    // S-tile compute into accs (shared by both passes)
    auto compute_S = [&](const __nv_bfloat16* sb, float accs[16][4]) {
        #pragma unroll
        for (int ks = 0; ks < 4; ks++) {
            uint32_t aH[4], aL[4];
            {
                int ar = wid * 16 + (lane & 15);
                int ac = ks * 16 + ((lane >> 4) << 3);
                ldsm4(aH, smem_u32(fsm + FA_H + ar * FSPAD + ac));
                ldsm4(aL, smem_u32(fsm + FA_L + ar * FSPAD + ac));
            }
            #pragma unroll
            for (int ng = 0; ng < 4; ng++) {
                uint32_t bh2[2][4], bl2[2][4];
                #pragma unroll
                for (int p = 0; p < 2; p++) {
                    int nr = ng * 32 + p * 16 + (lane & 7) + ((lane >> 4) << 3);
                    int kc = ks * 16 + (((lane >> 3) & 1) << 3);
                    ldsm4(bh2[p], smem_u32(sb + FS_BH + nr * FSPAD + kc));
                    ldsm4(bl2[p], smem_u32(sb + FS_BL + nr * FSPAD + kc));
                }
                #pragma unroll
                for (int t = 0; t < 4; t++) {
                    float* c = accs[ng * 4 + t];
                    const uint32_t* bhf = &bh2[t >> 1][(t & 1) * 2];
                    const uint32_t* blf = &bl2[t >> 1][(t & 1) * 2];
                    mma_bf16(c, aH, bhf);
                    mma_bf16(c, aH, blf);
                    mma_bf16(c, aL, bhf);
                }
            }
        }
        #pragma unroll
        for (int t = 0; t < 16; t++) {
            accs[t][0] *= SCALE_; accs[t][1] *= SCALE_;
            accs[t][2] *= SCALE_; accs[t][3] *= SCALE_;
        }
    };

    // ---------- PASS A: row stats ----------
    cp_tile(0, 0, false);
    CP_COMMIT(); CP_WAIT0();
    __syncthreads();

    float m0 = -1e30f, m1 = -1e30f, l0 = 0.f, l1 = 0.f;
    for (int j = 0; j < 8; j++) {
        if (j < 7) { cp_tile((j + 1) & 1, j + 1, false); CP_COMMIT(); }
        const __nv_bfloat16* sb = fsm + FSTG + (j & 1) * 36864;
        float accs[16][4] = {};
        compute_S(sb, accs);

        float tm0 = -1e30f, tm1 = -1e30f;
        #pragma unroll
        for (int t = 0; t < 16; t++) {
            tm0 = fmaxf(tm0, fmaxf(accs[t][0], accs[t][1]));
            tm1 = fmaxf(tm1, fmaxf(accs[t][2], accs[t][3]));
        }
        tm0 = fmaxf(tm0, __shfl_xor_sync(0xFFFFFFFF, tm0, 1));
        tm0 = fmaxf(tm0, __shfl_xor_sync(0xFFFFFFFF, tm0, 2));
        tm1 = fmaxf(tm1, __shfl_xor_sync(0xFFFFFFFF, tm1, 1));
        tm1 = fmaxf(tm1, __shfl_xor_sync(0xFFFFFFFF, tm1, 2));
        float mn0 = fmaxf(m0, tm0), mn1 = fmaxf(m1, tm1);
        float sc0 = __expf(m0 - mn0), sc1 = __expf(m1 - mn1);
        m0 = mn0; m1 = mn1;
        float rs0 = 0.f, rs1 = 0.f;
        #pragma unroll
        for (int t = 0; t < 16; t++) {
            rs0 += __expf(accs[t][0] - m0) + __expf(accs[t][1] - m0);
            rs1 += __expf(accs[t][2] - m1) + __expf(accs[t][3] - m1);
        }
        rs0 += __shfl_xor_sync(0xFFFFFFFF, rs0, 1);
        rs0 += __shfl_xor_sync(0xFFFFFFFF, rs0, 2);
        rs1 += __shfl_xor_sync(0xFFFFFFFF, rs1, 1);
        rs1 += __shfl_xor_sync(0xFFFFFFFF, rs1, 2);
        l0 = l0 * sc0 + rs0;
        l1 = l1 * sc1 + rs1;
        if (j < 7) CP_WAIT0();
        __syncthreads();
    }
    float inv0 = 1.f / l0, inv1 = 1.f / l1;

    // ---------- PASS B: normalized P -> attn, PV ----------
    cp_tile(0, 0, true);
    CP_COMMIT(); CP_WAIT0();
    __syncthreads();

    float* Sp = attn + (size_t)bh * N_ * N_;
    const int prow = i0 + wid * 16 + (lane >> 2);
    float acco[8][4] = {};

    for (int j = 0; j < 8; j++) {
        if (j < 7) { cp_tile((j + 1) & 1, j + 1, true); CP_COMMIT(); }
        const __nv_bfloat16* sb = fsm + FSTG + (j & 1) * 36864;
        float accs[16][4] = {};
        compute_S(sb, accs);

        // normalize + write attn
        #pragma unroll
        for (int t = 0; t < 16; t++) {
            accs[t][0] = __expf(accs[t][0] - m0) * inv0;
            accs[t][1] = __expf(accs[t][1] - m0) * inv0;
            accs[t][2] = __expf(accs[t][2] - m1) * inv1;
            accs[t][3] = __expf(accs[t][3] - m1) * inv1;
            int col = j * 128 + (t >> 2) * 32 + (t & 3) * 8 + (lane & 3) * 2;
            *(float2*)&Sp[(size_t)prow * N_ + col]       = make_float2(accs[t][0], accs[t][1]);
            *(float2*)&Sp[(size_t)(prow + 8) * N_ + col] = make_float2(accs[t][2], accs[t][3]);
        }

        // PV (P already normalized)
        #pragma unroll
        for (int kt = 0; kt < 8; kt++) {
            uint32_t pH[4], pL[4];
            split2(accs[2*kt][0],   accs[2*kt][1],   pH[0], pL[0]);
            split2(accs[2*kt][2],   accs[2*kt][3],   pH[1], pL[1]);
            split2(accs[2*kt+1][0], accs[2*kt+1][1], pH[2], pL[2]);
            split2(accs[2*kt+1][2], accs[2*kt+1][3], pH[3], pL[3]);
            #pragma unroll
            for (int vg = 0; vg < 2; vg++) {
                uint32_t vh2[2][4], vl2[2][4];
                #pragma unroll
                for (int q = 0; q < 2; q++) {
                    int vr = kt * 16 + (lane & 15);
                    int vc = vg * 32 + q * 16 + ((lane >> 4) << 3);
                    ldsm4t(vh2[q], smem_u32(sb + FS_VH + vr * FSPAD + vc));
                    ldsm4t(vl2[q], smem_u32(sb + FS_VL + vr * FSPAD + vc));
                }
                #pragma unroll
                for (int t = 0; t < 4; t++) {
                    float* o = acco[vg * 4 + t];
                    const uint32_t* vhf = &vh2[t >> 1][(t & 1) * 2];
                    const uint32_t* vlf = &vl2[t >> 1][(t & 1) * 2];
                    mma_bf16(o, pH, vhf);
                    mma_bf16(o, pH, vlf);
                    mma_bf16(o, pL, vhf);
                }
            }
        }

        if (j < 7) CP_WAIT0();
        __syncthreads();
    }

    // obnc (already normalized) -> bf16 hi/lo split at [b, n, h*64+hd]
    int b = bh / H_, h = bh % H_;
    #pragma unroll
    for (int o = 0; o < 8; o++) {
        int col = o * 8 + (lane & 3) * 2;
        uint32_t h0, l0b, h1, l1b;
        split2(acco[o][0], acco[o][1], h0, l0b);
        split2(acco[o][2], acco[o][3], h1, l1b);
        size_t idx0 = ((size_t)(b * N_ + prow)) * C_ + h * HD_ + col;
        size_t idx1 = ((size_t)(b * N_ + prow + 8)) * C_ + h * HD_ + col;
        *(uint32_t*)&g_och[idx0] = h0;
        *(uint32_t*)&g_ocl[idx0] = l0b;
        *(uint32_t*)&g_och[idx1] = h1;
        *(uint32_t*)&g_ocl[idx1] = l1b;
    }
}

// =================== bf16x3 HMMA GEMM: qkv and proj ===================
// CTA 128x128, 8 warps (2x4), K in chunks of 64, cp.async double buffer.
// smem per stage (bf16 elems): A_h 9216, A_l 9216, B_h 8704 (64x136), B_l 8704 -> 35840
#define QA_H 0
#define QA_L 9216
#define QB_H 18432
#define QB_L 27136
#define QSTG 35840
#define WPAD 136

// generic mainloop writing acc[4][4][4]; A: rows x K, B(W): K x ncols
template<int NCOLS, int KDIM>
__device__ __forceinline__ void mma_gemm_main(
    const __nv_bfloat16* __restrict__ Ah, const __nv_bfloat16* __restrict__ Al,
    const __nv_bfloat16* __restrict__ Wh, const __nv_bfloat16* __restrict__ Wl,
    __nv_bfloat16* sm, int by, int bx, float acc[4][4][4])
{
    const int tid = threadIdx.x, wid = tid >> 5, lane = tid & 31;
    const int wm = wid & 1, wn = wid >> 1;

    auto cp_stage = [&](int stage, int k0) {
        int sb = stage * QSTG;
        #pragma unroll
        for (int i = 0; i < 8; i++) {     // A: 2 arrays x 128 rows x 8 chunks = 2048 / 256
            int idx = tid + i * 256;
            int arr = idx >> 10, rem = idx & 1023, row = rem >> 3, c = rem & 7;
            const __nv_bfloat16* src = (arr ? Al : Ah) + (size_t)(by + row) * KDIM + k0 + c * 8;
            cp16(smem_u32(sm + sb + (arr ? QA_L : QA_H) + row * FSPAD + c * 8), src);
        }
        #pragma unroll
        for (int i = 0; i < 8; i++) {     // B: 2 arrays x 64 rows x 16 chunks = 2048 / 256
            int idx = tid + i * 256;
            int arr = idx >> 10, rem = idx & 1023, row = rem >> 4, c = rem & 15;
            const __nv_bfloat16* src = (arr ? Wl : Wh) + (size_t)(k0 + row) * NCOLS + bx + c * 8;
            cp16(smem_u32(sm + sb + (arr ? QB_L : QB_H) + row * WPAD + c * 8), src);
        }
    };

    cp_stage(0, 0);
    CP_COMMIT(); CP_WAIT0();
    __syncthreads();

    const int NCHUNK = KDIM / 64;
    for (int ch = 0; ch < NCHUNK; ch++) {
        if (ch < NCHUNK - 1) { cp_stage((ch + 1) & 1, (ch + 1) * 64); CP_COMMIT(); }
        __nv_bfloat16* sb = sm + (ch & 1) * QSTG;
        #pragma unroll
        for (int ks = 0; ks < 4; ks++) {
            uint32_t aH[4][4], aL[4][4];
            #pragma unroll
            for (int mt = 0; mt < 4; mt++) {
                int ar = wm * 64 + mt * 16 + (lane & 15);
                int ac = ks * 16 + ((lane >> 4) << 3);
                ldsm4(aH[mt], smem_u32(sb + QA_H + ar * FSPAD + ac));
                ldsm4(aL[mt], smem_u32(sb + QA_L + ar * FSPAD + ac));
            }
            uint32_t bh2[2][4], bl2[2][4];
            #pragma unroll
            for (int q = 0; q < 2; q++) {
                int vr = ks * 16 + (lane & 15);
                int vc = wn * 32 + q * 16 + ((lane >> 4) << 3);
                ldsm4t(bh2[q], smem_u32(sb + QB_H + vr * WPAD + vc));
                ldsm4t(bl2[q], smem_u32(sb + QB_L + vr * WPAD + vc));
            }
            #pragma unroll
            for (int mt = 0; mt < 4; mt++)
                #pragma unroll
                for (int nt = 0; nt < 4; nt++) {
                    const uint32_t* bhf = &bh2[nt >> 1][(nt & 1) * 2];
                    const uint32_t* blf = &bl2[nt >> 1][(nt & 1) * 2];
                    mma_bf16(acc[mt][nt], aH[mt], bhf);
                    mma_bf16(acc[mt][nt], aH[mt], blf);
                    mma_bf16(acc[mt][nt], aL[mt], bhf);
                }
        }
        if (ch < NCHUNK - 1) CP_WAIT0();
        __syncthreads();
    }
}

__global__ void __launch_bounds__(256, 1) qkv_mma_kernel(const float* __restrict__ bias) {
    extern __shared__ __nv_bfloat16 qsm[];
    const int bx = blockIdx.x * 128;
    const int by = blockIdx.y * 128;
    const int wid = threadIdx.x >> 5, lane = threadIdx.x & 31;
    const int wm = wid & 1, wn = wid >> 1;

    float acc[4][4][4] = {};
    mma_gemm_main<TWO_C_, C_>(g_xh, g_xl, g_wqh, g_wql, qsm, by, bx, acc);

    #pragma unroll
    for (int mt = 0; mt < 4; mt++) {
        int r0 = by + wm * 64 + mt * 16 + (lane >> 2);
        #pragma unroll
        for (int nt = 0; nt < 4; nt++) {
            int col = bx + wn * 32 + nt * 8 + (lane & 3) * 2;
            float b0 = bias[col], b1 = bias[col + 1];
            #pragma unroll
            for (int half = 0; half < 2; half++) {
                int r = r0 + half * 8;
                float v0 = acc[mt][nt][half * 2]     + b0;
                float v1 = acc[mt][nt][half * 2 + 1] + b1;
                int bb = r >> 10, n = r & 1023;
                int which = col >= C_;
                int cc = col - which * C_;
                int hh = cc / HD_, hd = cc % HD_;
                size_t idx = (((size_t)(bb * H_ + hh)) * N_ + n) * HD_ + hd;
                if (!which) {
                    *(float2*)&g_k[idx] = make_float2(v0, v1);
                } else {
                    uint32_t h2, l2;
                    split2(v0, v1, h2, l2);
                    *(uint32_t*)&g_vh[idx] = h2;
                    *(uint32_t*)&g_vl[idx] = l2;
                }
            }
        }
    }
}

__global__ void __launch_bounds__(256, 1) proj_mma_kernel(const float* __restrict__ bias,
                                                          float* __restrict__ out) {
    extern __shared__ __nv_bfloat16 qsm[];
    const int bx = blockIdx.x * 128;
    const int by = blockIdx.y * 128;
    const int wid = threadIdx.x >> 5, lane = threadIdx.x & 31;
    const int wm = wid & 1, wn = wid >> 1;

    float acc[4][4][4] = {};
    mma_gemm_main<C_, C_>(g_och, g_ocl, g_wph, g_wpl, qsm, by, bx, acc);

    #pragma unroll
    for (int mt = 0; mt < 4; mt++) {
        int r0 = by + wm * 64 + mt * 16 + (lane >> 2);
        #pragma unroll
        for (int nt = 0; nt < 4; nt++) {
            int col = bx + wn * 32 + nt * 8 + (lane & 3) * 2;
            float b0 = bias[col], b1 = bias[col + 1];
            *(float2*)&out[(size_t)r0 * C_ + col] =
                make_float2(acc[mt][nt][0] + b0, acc[mt][nt][1] + b1);
            *(float2*)&out[(size_t)(r0 + 8) * C_ + col] =
                make_float2(acc[mt][nt][2] + b0, acc[mt][nt][3] + b1);
        }
    }
}

// ---------------- launch ----------------
extern "C" void kernel_launch(void* const* d_in, const int* in_sizes, int n_in,
                              void* d_out, int out_size) {
    const float* x     = (const float*)d_in[0];
    const float* Wqkv  = (const float*)d_in[1];
    const float* bqkv  = (const float*)d_in[2];
    const float* Wproj = (const float*)d_in[3];
    const float* bproj = (const float*)d_in[4];
    float* out = (float*)d_out;

    float* attn;
    if ((size_t)out_size >= OUT_ELEMS + ATTN_ELEMS) {
        attn = out + OUT_ELEMS;
    } else {
        void* p = nullptr;
        cudaGetSymbolAddress(&p, g_attn_fallback);
        attn = (float*)p;
    }

    const int FLASH_SMEM = (18432 + 2 * 36864) * 2;   // 184,320 B
    const int GEMM_SMEM  = 2 * QSTG * 2;              // 143,360 B
    cudaFuncSetAttribute(flash_iter_kernel, cudaFuncAttributeMaxDynamicSharedMemorySize, FLASH_SMEM);
    cudaFuncSetAttribute(final_flash_kernel, cudaFuncAttributeMaxDynamicSharedMemorySize, FLASH_SMEM);
    cudaFuncSetAttribute(qkv_mma_kernel, cudaFuncAttributeMaxDynamicSharedMemorySize, GEMM_SMEM);
    cudaFuncSetAttribute(proj_mma_kernel, cudaFuncAttributeMaxDynamicSharedMemorySize, GEMM_SMEM);

    __nv_bfloat16 *xh, *xl, *wqh, *wql, *wph, *wpl;
    { void* p; cudaGetSymbolAddress(&p, g_xh);  xh  = (__nv_bfloat16*)p; }
    { void* p; cudaGetSymbolAddress(&p, g_xl);  xl  = (__nv_bfloat16*)p; }
    { void* p; cudaGetSymbolAddress(&p, g_wqh); wqh = (__nv_bfloat16*)p; }
    { void* p; cudaGetSymbolAddress(&p, g_wql); wql = (__nv_bfloat16*)p; }
    { void* p; cudaGetSymbolAddress(&p, g_wph); wph = (__nv_bfloat16*)p; }
    { void* p; cudaGetSymbolAddress(&p, g_wpl); wpl = (__nv_bfloat16*)p; }

    const int eblocks = (int)((KV_ELEMS + 255) / 256);

    zero_ly_kernel<<<eblocks, 256>>>();
    split_kernel<<<(6291456 + 255) / 256, 256>>>(x, xh, xl, 6291456);
    split_kernel<<<(1179648 + 255) / 256, 256>>>(Wqkv, wqh, wql, 1179648);
    split_kernel<<<(589824 + 255) / 256, 256>>>(Wproj, wph, wpl, 589824);

    qkv_mma_kernel<<<dim3(TWO_C_ / 128, M_ROWS / 128), 256, GEMM_SMEM>>>(bqkv);
    mu_kernel<<<BH_, 256>>>();

    for (int it = 0; it < 6; ++it) {
        iter_pre_kernel<<<eblocks, 256>>>(it == 0 ? 1 : 0);
        if (it < 5) {
            flash_iter_kernel<<<dim3(N_ / 128, BH_), 256, FLASH_SMEM>>>();
        } else {
            final_flash_kernel<<<dim3(N_ / 128, BH_), 256, FLASH_SMEM>>>(attn);
        }
    }

    proj_mma_kernel<<<dim3(C_ / 128, M_ROWS / 128), 256, GEMM_SMEM>>>(bproj, out);
}

// round 7
// speedup vs baseline: 5.0059x; 1.1060x over previous
#include <cuda_runtime.h>
#include <cuda_bf16.h>
#include <cuda_fp16.h>
#include <math.h>
#include <stdint.h>

#define B_   8
#define N_   1024
#define C_   768
#define H_   12
#define HD_  64
#define BH_  (B_*H_)
#define TWO_C_ (2*C_)
#define M_ROWS (B_*N_)

static const size_t KV_ELEMS   = (size_t)BH_ * N_ * HD_;
static const size_t OUT_ELEMS  = (size_t)B_ * N_ * C_;
static const size_t ATTN_ELEMS = (size_t)BH_ * N_ * N_;

#define LAMBD_ 4.0f
// logits carried in log2 domain: S2 = (k2*QSC)·(k2*QSC)^T where QSC^2 = 0.125*log2(e)
#define QSC_ 0.42466089f

// ---------------- device scratch ----------------
__device__ float g_k [6291456];
__device__ float g_y [6291456];
__device__ float g_s [6291456];
__device__ __nv_bfloat16 g_k2h[6291456];
__device__ __nv_bfloat16 g_k2l[6291456];
__device__ __half g_vh [6291456];
__device__ __half g_vl [6291456];
__device__ __nv_bfloat16 g_xh [6291456];
__device__ __nv_bfloat16 g_xl [6291456];
__device__ __nv_bfloat16 g_wqh[1179648];
__device__ __nv_bfloat16 g_wql[1179648];
__device__ __nv_bfloat16 g_wph[589824];
__device__ __nv_bfloat16 g_wpl[589824];
__device__ __nv_bfloat16 g_och[6291456];
__device__ __nv_bfloat16 g_ocl[6291456];
__device__ float g_mu[96];
__device__ float g_attn_fallback[100663296];

// ---------------- helpers ----------------
__device__ __forceinline__ uint32_t smem_u32(const void* p) {
    uint32_t a;
    asm("{ .reg .u64 t; cvta.to.shared.u64 t, %1; cvt.u32.u64 %0, t; }" : "=r"(a) : "l"(p));
    return a;
}
__device__ __forceinline__ void ldsm4(uint32_t r[4], uint32_t addr) {
    asm volatile("ldmatrix.sync.aligned.m8n8.x4.shared.b16 {%0,%1,%2,%3}, [%4];"
        : "=r"(r[0]), "=r"(r[1]), "=r"(r[2]), "=r"(r[3]) : "r"(addr));
}
__device__ __forceinline__ void ldsm4t(uint32_t r[4], uint32_t addr) {
    asm volatile("ldmatrix.sync.aligned.m8n8.x4.trans.shared.b16 {%0,%1,%2,%3}, [%4];"
        : "=r"(r[0]), "=r"(r[1]), "=r"(r[2]), "=r"(r[3]) : "r"(addr));
}
__device__ __forceinline__ void mma_bf16(float c[4], const uint32_t a[4], const uint32_t* b) {
    asm volatile("mma.sync.aligned.m16n8k16.row.col.f32.bf16.bf16.f32 "
        "{%0,%1,%2,%3}, {%4,%5,%6,%7}, {%8,%9}, {%0,%1,%2,%3};"
        : "+f"(c[0]), "+f"(c[1]), "+f"(c[2]), "+f"(c[3])
        : "r"(a[0]), "r"(a[1]), "r"(a[2]), "r"(a[3]), "r"(b[0]), "r"(b[1]));
}
__device__ __forceinline__ void mma_f16(float c[4], const uint32_t a[4], const uint32_t* b) {
    asm volatile("mma.sync.aligned.m16n8k16.row.col.f32.f16.f16.f32 "
        "{%0,%1,%2,%3}, {%4,%5,%6,%7}, {%8,%9}, {%0,%1,%2,%3};"
        : "+f"(c[0]), "+f"(c[1]), "+f"(c[2]), "+f"(c[3])
        : "r"(a[0]), "r"(a[1]), "r"(a[2]), "r"(a[3]), "r"(b[0]), "r"(b[1]));
}
__device__ __forceinline__ void split2(float x, float y, uint32_t& hi, uint32_t& lo) {
    __nv_bfloat16 hx = __float2bfloat16(x), hy = __float2bfloat16(y);
    __nv_bfloat162 h2; h2.x = hx; h2.y = hy;
    __nv_bfloat162 l2;
    l2.x = __float2bfloat16(x - __bfloat162float(hx));
    l2.y = __float2bfloat16(y - __bfloat162float(hy));
    hi = *reinterpret_cast<uint32_t*>(&h2);
    lo = *reinterpret_cast<uint32_t*>(&l2);
}
__device__ __forceinline__ void split2h(float x, float y, uint32_t& hi, uint32_t& lo) {
    __half2 h = __floats2half2_rn(x, y);
    __half2 l = __floats2half2_rn(x - __half2float(h.x), y - __half2float(h.y));
    hi = *reinterpret_cast<uint32_t*>(&h);
    lo = *reinterpret_cast<uint32_t*>(&l);
}
__device__ __forceinline__ uint32_t pack_h2(float x, float y) {
    __half2 h = __floats2half2_rn(x, y);
    return *reinterpret_cast<uint32_t*>(&h);
}
__device__ __forceinline__ float ex2f(float x) {
    float y; asm("ex2.approx.f32 %0, %1;" : "=f"(y) : "f"(x)); return y;
}
__device__ __forceinline__ void cp16(uint32_t dst, const void* src) {
    asm volatile("cp.async.cg.shared.global [%0], [%1], 16;" :: "r"(dst), "l"(src));
}
#define CP_COMMIT() asm volatile("cp.async.commit_group;" ::: "memory")
#define CP_WAIT0()  asm volatile("cp.async.wait_group 0;" ::: "memory")

// ---------------- elementwise ----------------
__global__ void split_kernel(const float* __restrict__ src, __nv_bfloat16* __restrict__ h,
                             __nv_bfloat16* __restrict__ l, int n) {
    int i = blockIdx.x * 256 + threadIdx.x;
    if (i >= n) return;
    float v = src[i];
    __nv_bfloat16 hi = __float2bfloat16(v);
    h[i] = hi;
    l[i] = __float2bfloat16(v - __bfloat162float(hi));
}

// first-iteration k2 (l = y = 0)
__global__ void k2_init_kernel() {
    size_t i = (size_t)blockIdx.x * 256 + threadIdx.x;
    if (i >= KV_ELEMS) return;
    int bh = (int)(i / ((size_t)N_ * HD_));
    float mu = g_mu[bh];
    float kk = g_k[i];
    float lm = LAMBD_ * mu;
    float s  = (kk >= lm) ? (kk - lm) : ((kk <= -lm) ? (kk + lm) : 0.f);
    g_s[i] = s;
    g_y[i] = 0.f;
    float k2 = (kk - s) * QSC_;
    __nv_bfloat16 hi = __float2bfloat16(k2);
    g_k2h[i] = hi;
    g_k2l[i] = __float2bfloat16(k2 - __bfloat162float(hi));
}

__global__ void mu_kernel() {
    __shared__ float red[256];
    int bh = blockIdx.x;
    const float* p = g_k + (size_t)bh * N_ * HD_;
    float s = 0.f;
    for (int i = threadIdx.x; i < N_ * HD_; i += 256) s += fabsf(p[i]);
    red[threadIdx.x] = s;
    __syncthreads();
    for (int st = 128; st > 0; st >>= 1) {
        if (threadIdx.x < st) red[threadIdx.x] += red[threadIdx.x + st];
        __syncthreads();
    }
    if (threadIdx.x == 0) g_mu[bh] = ((float)N_ * (float)C_ / 4.0f) / red[0];
}

// =================== flash iteration (iters 0..4) + fused y/s/k2 update ===================
#define FSPAD 72
#define FA_H  0
#define FA_L  9216
#define FSTG  18432
#define FS_BH 0
#define FS_BL 9216
#define FS_VH 18432
#define FS_VL 27648

__global__ void __launch_bounds__(256, 1) flash_iter_kernel() {
    extern __shared__ __nv_bfloat16 fsm[];
    const int bh = blockIdx.y;
    const int i0 = blockIdx.x * 128;
    const int tid = threadIdx.x, wid = tid >> 5, lane = tid & 31;

    const size_t hbase = (size_t)bh * N_ * HD_;
    const __nv_bfloat16* Gh = g_k2h + hbase;
    const __nv_bfloat16* Gl = g_k2l + hbase;
    const __half* Vh = g_vh + hbase;
    const __half* Vl = g_vl + hbase;
    const float mu = g_mu[bh];

    #pragma unroll
    for (int i = 0; i < 8; i++) {
        int idx = tid + i * 256;
        int arr = idx >> 10, rem = idx & 1023, row = rem >> 3, c = rem & 7;
        const __nv_bfloat16* src = (arr ? Gl : Gh) + (size_t)(i0 + row) * HD_ + c * 8;
        *(uint4*)(fsm + (arr ? FA_L : FA_H) + row * FSPAD + c * 8) = *(const uint4*)src;
    }

    auto cp_tile = [&](int stage, int j) {
        int sbase = FSTG + stage * 36864;
        #pragma unroll
        for (int i = 0; i < 16; i++) {
            int idx = tid + i * 256;
            int arr = idx >> 10, rem = idx & 1023, row = rem >> 3, c = rem & 7;
            const void* src;
            int off;
            if      (arr == 0) { src = Gh + (size_t)(j * 128 + row) * HD_ + c * 8; off = FS_BH; }
            else if (arr == 1) { src = Gl + (size_t)(j * 128 + row) * HD_ + c * 8; off = FS_BL; }
            else if (arr == 2) { src = Vh + (size_t)(j * 128 + row) * HD_ + c * 8; off = FS_VH; }
            else               { src = Vl + (size_t)(j * 128 + row) * HD_ + c * 8; off = FS_VL; }
            cp16(smem_u32(fsm + sbase + off + row * FSPAD + c * 8), src);
        }
    };

    cp_tile(0, 0);
    CP_COMMIT(); CP_WAIT0();
    __syncthreads();

    float m0 = -1e30f, m1 = -1e30f, l0 = 0.f, l1 = 0.f;
    float acco[8][4] = {};

    for (int j = 0; j < 8; j++) {
        if (j < 7) { cp_tile((j + 1) & 1, j + 1); CP_COMMIT(); }
        const __nv_bfloat16* sb = fsm + FSTG + (j & 1) * 36864;

        float accs[16][4] = {};
        #pragma unroll
        for (int ks = 0; ks < 4; ks++) {
            uint32_t aH[4], aL[4];
            {
                int ar = wid * 16 + (lane & 15);
                int ac = ks * 16 + ((lane >> 4) << 3);
                ldsm4(aH, smem_u32(fsm + FA_H + ar * FSPAD + ac));
                ldsm4(aL, smem_u32(fsm + FA_L + ar * FSPAD + ac));
            }
            #pragma unroll
            for (int ng = 0; ng < 4; ng++) {
                uint32_t bh2[2][4], bl2[2][4];
                #pragma unroll
                for (int p = 0; p < 2; p++) {
                    int nr = ng * 32 + p * 16 + (lane & 7) + ((lane >> 4) << 3);
                    int kc = ks * 16 + (((lane >> 3) & 1) << 3);
                    ldsm4(bh2[p], smem_u32(sb + FS_BH + nr * FSPAD + kc));
                    ldsm4(bl2[p], smem_u32(sb + FS_BL + nr * FSPAD + kc));
                }
                #pragma unroll
                for (int t = 0; t < 4; t++) {
                    float* c = accs[ng * 4 + t];
                    const uint32_t* bhf = &bh2[t >> 1][(t & 1) * 2];
                    const uint32_t* blf = &bl2[t >> 1][(t & 1) * 2];
                    mma_bf16(c, aH, bhf);
                    mma_bf16(c, aH, blf);
                    mma_bf16(c, aL, bhf);
                }
            }
        }

        // online softmax in log2 domain (logits already scaled by QSC^2)
        float tm0 = -1e30f, tm1 = -1e30f;
        #pragma unroll
        for (int t = 0; t < 16; t++) {
            tm0 = fmaxf(tm0, fmaxf(accs[t][0], accs[t][1]));
            tm1 = fmaxf(tm1, fmaxf(accs[t][2], accs[t][3]));
        }
        tm0 = fmaxf(tm0, __shfl_xor_sync(0xFFFFFFFF, tm0, 1));
        tm0 = fmaxf(tm0, __shfl_xor_sync(0xFFFFFFFF, tm0, 2));
        tm1 = fmaxf(tm1, __shfl_xor_sync(0xFFFFFFFF, tm1, 1));
        tm1 = fmaxf(tm1, __shfl_xor_sync(0xFFFFFFFF, tm1, 2));
        float mn0 = fmaxf(m0, tm0), mn1 = fmaxf(m1, tm1);
        float sc0 = ex2f(m0 - mn0), sc1 = ex2f(m1 - mn1);
        m0 = mn0; m1 = mn1;
        float rs0 = 0.f, rs1 = 0.f;
        #pragma unroll
        for (int t = 0; t < 16; t++) {
            accs[t][0] = ex2f(accs[t][0] - m0);
            accs[t][1] = ex2f(accs[t][1] - m0);
            accs[t][2] = ex2f(accs[t][2] - m1);
            accs[t][3] = ex2f(accs[t][3] - m1);
            rs0 += accs[t][0] + accs[t][1];
            rs1 += accs[t][2] + accs[t][3];
        }
        rs0 += __shfl_xor_sync(0xFFFFFFFF, rs0, 1);
        rs0 += __shfl_xor_sync(0xFFFFFFFF, rs0, 2);
        rs1 += __shfl_xor_sync(0xFFFFFFFF, rs1, 1);
        rs1 += __shfl_xor_sync(0xFFFFFFFF, rs1, 2);
        l0 = l0 * sc0 + rs0;
        l1 = l1 * sc1 + rs1;
        #pragma unroll
        for (int o = 0; o < 8; o++) {
            acco[o][0] *= sc0; acco[o][1] *= sc0;
            acco[o][2] *= sc1; acco[o][3] *= sc1;
        }

        // PV: P fp16 x V (fp16 hi/lo), 2 products
        #pragma unroll
        for (int kt = 0; kt < 8; kt++) {
            uint32_t pH[4];
            pH[0] = pack_h2(accs[2*kt][0],   accs[2*kt][1]);
            pH[1] = pack_h2(accs[2*kt][2],   accs[2*kt][3]);
            pH[2] = pack_h2(accs[2*kt+1][0], accs[2*kt+1][1]);
            pH[3] = pack_h2(accs[2*kt+1][2], accs[2*kt+1][3]);
            #pragma unroll
            for (int vg = 0; vg < 2; vg++) {
                uint32_t vh2[2][4], vl2[2][4];
                #pragma unroll
                for (int q = 0; q < 2; q++) {
                    int vr = kt * 16 + (lane & 15);
                    int vc = vg * 32 + q * 16 + ((lane >> 4) << 3);
                    ldsm4t(vh2[q], smem_u32(sb + FS_VH + vr * FSPAD + vc));
                    ldsm4t(vl2[q], smem_u32(sb + FS_VL + vr * FSPAD + vc));
                }
                #pragma unroll
                for (int t = 0; t < 4; t++) {
                    float* o = acco[vg * 4 + t];
                    mma_f16(o, pH, &vh2[t >> 1][(t & 1) * 2]);
                    mma_f16(o, pH, &vl2[t >> 1][(t & 1) * 2]);
                }
            }
        }

        if (j < 7) CP_WAIT0();
        __syncthreads();
    }

    // ---- fused epilogue: l (in regs) -> y, s, k2 update for next iteration ----
    float inv0 = 1.f / l0, inv1 = 1.f / l1;
    float imu = 1.f / mu;
    float lm = LAMBD_ * mu;
    int row0 = i0 + wid * 16 + (lane >> 2);
    #pragma unroll
    for (int o = 0; o < 8; o++) {
        int col = o * 8 + (lane & 3) * 2;
        #pragma unroll
        for (int half = 0; half < 2; half++) {
            size_t ia = hbase + (size_t)(row0 + half * 8) * HD_ + col;
            float la = acco[o][half * 2]     * (half ? inv1 : inv0);
            float lb = acco[o][half * 2 + 1] * (half ? inv1 : inv0);
            float2 kv = *(const float2*)&g_k[ia];
            float2 yv = *(const float2*)&g_y[ia];
            float2 sv = *(const float2*)&g_s[ia];
            float yn0 = yv.x + mu * (kv.x - la - sv.x);
            float yn1 = yv.y + mu * (kv.y - lb - sv.y);
            float ym0 = yn0 * imu, ym1 = yn1 * imu;
            float t0 = kv.x - la + ym0, t1 = kv.y - lb + ym1;
            float sn0 = (t0 >= lm) ? (t0 - lm) : ((t0 <= -lm) ? (t0 + lm) : 0.f);
            float sn1 = (t1 >= lm) ? (t1 - lm) : ((t1 <= -lm) ? (t1 + lm) : 0.f);
            *(float2*)&g_y[ia] = make_float2(yn0, yn1);
            *(float2*)&g_s[ia] = make_float2(sn0, sn1);
            float k20 = (kv.x - sn0 - ym0) * QSC_;
            float k21 = (kv.y - sn1 - ym1) * QSC_;
            uint32_t h2, l2;
            split2(k20, k21, h2, l2);
            *(uint32_t*)&g_k2h[ia] = h2;
            *(uint32_t*)&g_k2l[ia] = l2;
        }
    }
}

// =================== final iteration: 2-pass flash, materializes attn + obnc ===================
__global__ void __launch_bounds__(256, 1) final_flash_kernel(float* __restrict__ attn) {
    extern __shared__ __nv_bfloat16 fsm[];
    const int bh = blockIdx.y;
    const int i0 = blockIdx.x * 128;
    const int tid = threadIdx.x, wid = tid >> 5, lane = tid & 31;

    const size_t hbase = (size_t)bh * N_ * HD_;
    const __nv_bfloat16* Gh = g_k2h + hbase;
    const __nv_bfloat16* Gl = g_k2l + hbase;
    const __half* Vh = g_vh + hbase;
    const __half* Vl = g_vl + hbase;

    #pragma unroll
    for (int i = 0; i < 8; i++) {
        int idx = tid + i * 256;
        int arr = idx >> 10, rem = idx & 1023, row = rem >> 3, c = rem & 7;
        const __nv_bfloat16* src = (arr ? Gl : Gh) + (size_t)(i0 + row) * HD_ + c * 8;
        *(uint4*)(fsm + (arr ? FA_L : FA_H) + row * FSPAD + c * 8) = *(const uint4*)src;
    }

    auto cp_tile = [&](int stage, int j, bool withV) {
        int sbase = FSTG + stage * 36864;
        #pragma unroll
        for (int i = 0; i < 16; i++) {
            int idx = tid + i * 256;
            int arr = idx >> 10, rem = idx & 1023, row = rem >> 3, c = rem & 7;
            if (!withV && arr >= 2) continue;
            const void* src;
            int off;
            if      (arr == 0) { src = Gh + (size_t)(j * 128 + row) * HD_ + c * 8; off = FS_BH; }
            else if (arr == 1) { src = Gl + (size_t)(j * 128 + row) * HD_ + c * 8; off = FS_BL; }
            else if (arr == 2) { src = Vh + (size_t)(j * 128 + row) * HD_ + c * 8; off = FS_VH; }
            else               { src = Vl + (size_t)(j * 128 + row) * HD_ + c * 8; off = FS_VL; }
            cp16(smem_u32(fsm + sbase + off + row * FSPAD + c * 8), src);
        }
    };

    auto compute_S = [&](const __nv_bfloat16* sb, float accs[16][4]) {
        #pragma unroll
        for (int ks = 0; ks < 4; ks++) {
            uint32_t aH[4], aL[4];
            {
                int ar = wid * 16 + (lane & 15);
                int ac = ks * 16 + ((lane >> 4) << 3);
                ldsm4(aH, smem_u32(fsm + FA_H + ar * FSPAD + ac));
                ldsm4(aL, smem_u32(fsm + FA_L + ar * FSPAD + ac));
            }
            #pragma unroll
            for (int ng = 0; ng < 4; ng++) {
                uint32_t bh2[2][4], bl2[2][4];
                #pragma unroll
                for (int p = 0; p < 2; p++) {
                    int nr = ng * 32 + p * 16 + (lane & 7) + ((lane >> 4) << 3);
                    int kc = ks * 16 + (((lane >> 3) & 1) << 3);
                    ldsm4(bh2[p], smem_u32(sb + FS_BH + nr * FSPAD + kc));
                    ldsm4(bl2[p], smem_u32(sb + FS_BL + nr * FSPAD + kc));
                }
                #pragma unroll
                for (int t = 0; t < 4; t++) {
                    float* c = accs[ng * 4 + t];
                    const uint32_t* bhf = &bh2[t >> 1][(t & 1) * 2];
                    const uint32_t* blf = &bl2[t >> 1][(t & 1) * 2];
                    mma_bf16(c, aH, bhf);
                    mma_bf16(c, aH, blf);
                    mma_bf16(c, aL, bhf);
                }
            }
        }
    };

    // ---------- PASS A: row stats ----------
    cp_tile(0, 0, false);
    CP_COMMIT(); CP_WAIT0();
    __syncthreads();

    float m0 = -1e30f, m1 = -1e30f, l0 = 0.f, l1 = 0.f;
    for (int j = 0; j < 8; j++) {
        if (j < 7) { cp_tile((j + 1) & 1, j + 1, false); CP_COMMIT(); }
        const __nv_bfloat16* sb = fsm + FSTG + (j & 1) * 36864;
        float accs[16][4] = {};
        compute_S(sb, accs);

        float tm0 = -1e30f, tm1 = -1e30f;
        #pragma unroll
        for (int t = 0; t < 16; t++) {
            tm0 = fmaxf(tm0, fmaxf(accs[t][0], accs[t][1]));
            tm1 = fmaxf(tm1, fmaxf(accs[t][2], accs[t][3]));
        }
        tm0 = fmaxf(tm0, __shfl_xor_sync(0xFFFFFFFF, tm0, 1));
        tm0 = fmaxf(tm0, __shfl_xor_sync(0xFFFFFFFF, tm0, 2));
        tm1 = fmaxf(tm1, __shfl_xor_sync(0xFFFFFFFF, tm1, 1));
        tm1 = fmaxf(tm1, __shfl_xor_sync(0xFFFFFFFF, tm1, 2));
        float mn0 = fmaxf(m0, tm0), mn1 = fmaxf(m1, tm1);
        float sc0 = ex2f(m0 - mn0), sc1 = ex2f(m1 - mn1);
        m0 = mn0; m1 = mn1;
        float rs0 = 0.f, rs1 = 0.f;
        #pragma unroll
        for (int t = 0; t < 16; t++) {
            rs0 += ex2f(accs[t][0] - m0) + ex2f(accs[t][1] - m0);
            rs1 += ex2f(accs[t][2] - m1) + ex2f(accs[t][3] - m1);
        }
        rs0 += __shfl_xor_sync(0xFFFFFFFF, rs0, 1);
        rs0 += __shfl_xor_sync(0xFFFFFFFF, rs0, 2);
        rs1 += __shfl_xor_sync(0xFFFFFFFF, rs1, 1);
        rs1 += __shfl_xor_sync(0xFFFFFFFF, rs1, 2);
        l0 = l0 * sc0 + rs0;
        l1 = l1 * sc1 + rs1;
        if (j < 7) CP_WAIT0();
        __syncthreads();
    }
    float inv0 = 1.f / l0, inv1 = 1.f / l1;

    // ---------- PASS B: normalized P -> attn, PV ----------
    cp_tile(0, 0, true);
    CP_COMMIT(); CP_WAIT0();
    __syncthreads();

    float* Sp = attn + (size_t)bh * N_ * N_;
    const int prow = i0 + wid * 16 + (lane >> 2);
    float acco[8][4] = {};

    for (int j = 0; j < 8; j++) {
        if (j < 7) { cp_tile((j + 1) & 1, j + 1, true); CP_COMMIT(); }
        const __nv_bfloat16* sb = fsm + FSTG + (j & 1) * 36864;
        float accs[16][4] = {};
        compute_S(sb, accs);

        #pragma unroll
        for (int t = 0; t < 16; t++) {
            accs[t][0] = ex2f(accs[t][0] - m0) * inv0;
            accs[t][1] = ex2f(accs[t][1] - m0) * inv0;
            accs[t][2] = ex2f(accs[t][2] - m1) * inv1;
            accs[t][3] = ex2f(accs[t][3] - m1) * inv1;
            int col = j * 128 + (t >> 2) * 32 + (t & 3) * 8 + (lane & 3) * 2;
            *(float2*)&Sp[(size_t)prow * N_ + col]       = make_float2(accs[t][0], accs[t][1]);
            *(float2*)&Sp[(size_t)(prow + 8) * N_ + col] = make_float2(accs[t][2], accs[t][3]);
        }

        #pragma unroll
        for (int kt = 0; kt < 8; kt++) {
            uint32_t pH[4];
            pH[0] = pack_h2(accs[2*kt][0],   accs[2*kt][1]);
            pH[1] = pack_h2(accs[2*kt][2],   accs[2*kt][3]);
            pH[2] = pack_h2(accs[2*kt+1][0], accs[2*kt+1][1]);
            pH[3] = pack_h2(accs[2*kt+1][2], accs[2*kt+1][3]);
            #pragma unroll
            for (int vg = 0; vg < 2; vg++) {
                uint32_t vh2[2][4], vl2[2][4];
                #pragma unroll
                for (int q = 0; q < 2; q++) {
                    int vr = kt * 16 + (lane & 15);
                    int vc = vg * 32 + q * 16 + ((lane >> 4) << 3);
                    ldsm4t(vh2[q], smem_u32(sb + FS_VH + vr * FSPAD + vc));
                    ldsm4t(vl2[q], smem_u32(sb + FS_VL + vr * FSPAD + vc));
                }
                #pragma unroll
                for (int t = 0; t < 4; t++) {
                    float* o = acco[vg * 4 + t];
                    mma_f16(o, pH, &vh2[t >> 1][(t & 1) * 2]);
                    mma_f16(o, pH, &vl2[t >> 1][(t & 1) * 2]);
                }
            }
        }

        if (j < 7) CP_WAIT0();
        __syncthreads();
    }

    int b = bh / H_, h = bh % H_;
    #pragma unroll
    for (int o = 0; o < 8; o++) {
        int col = o * 8 + (lane & 3) * 2;
        uint32_t h0, l0b, h1, l1b;
        split2(acco[o][0], acco[o][1], h0, l0b);
        split2(acco[o][2], acco[o][3], h1, l1b);
        size_t idx0 = ((size_t)(b * N_ + prow)) * C_ + h * HD_ + col;
        size_t idx1 = ((size_t)(b * N_ + prow + 8)) * C_ + h * HD_ + col;
        *(uint32_t*)&g_och[idx0] = h0;
        *(uint32_t*)&g_ocl[idx0] = l0b;
        *(uint32_t*)&g_och[idx1] = h1;
        *(uint32_t*)&g_ocl[idx1] = l1b;
    }
}

// =================== bf16x3 HMMA GEMM: qkv and proj ===================
#define QA_H 0
#define QA_L 9216
#define QB_H 18432
#define QB_L 27136
#define QSTG 35840
#define WPAD 136

template<int NCOLS, int KDIM>
__device__ __forceinline__ void mma_gemm_main(
    const __nv_bfloat16* __restrict__ Ah, const __nv_bfloat16* __restrict__ Al,
    const __nv_bfloat16* __restrict__ Wh, const __nv_bfloat16* __restrict__ Wl,
    __nv_bfloat16* sm, int by, int bx, float acc[4][4][4])
{
    const int tid = threadIdx.x, wid = tid >> 5, lane = tid & 31;
    const int wm = wid & 1, wn = wid >> 1;

    auto cp_stage = [&](int stage, int k0) {
        int sb = stage * QSTG;
        #pragma unroll
        for (int i = 0; i < 8; i++) {
            int idx = tid + i * 256;
            int arr = idx >> 10, rem = idx & 1023, row = rem >> 3, c = rem & 7;
            const __nv_bfloat16* src = (arr ? Al : Ah) + (size_t)(by + row) * KDIM + k0 + c * 8;
            cp16(smem_u32(sm + sb + (arr ? QA_L : QA_H) + row * FSPAD + c * 8), src);
        }
        #pragma unroll
        for (int i = 0; i < 8; i++) {
            int idx = tid + i * 256;
            int arr = idx >> 10, rem = idx & 1023, row = rem >> 4, c = rem & 15;
            const __nv_bfloat16* src = (arr ? Wl : Wh) + (size_t)(k0 + row) * NCOLS + bx + c * 8;
            cp16(smem_u32(sm + sb + (arr ? QB_L : QB_H) + row * WPAD + c * 8), src);
        }
    };

    cp_stage(0, 0);
    CP_COMMIT(); CP_WAIT0();
    __syncthreads();

    const int NCHUNK = KDIM / 64;
    for (int ch = 0; ch < NCHUNK; ch++) {
        if (ch < NCHUNK - 1) { cp_stage((ch + 1) & 1, (ch + 1) * 64); CP_COMMIT(); }
        __nv_bfloat16* sb = sm + (ch & 1) * QSTG;
        #pragma unroll
        for (int ks = 0; ks < 4; ks++) {
            uint32_t aH[4][4], aL[4][4];
            #pragma unroll
            for (int mt = 0; mt < 4; mt++) {
                int ar = wm * 64 + mt * 16 + (lane & 15);
                int ac = ks * 16 + ((lane >> 4) << 3);
                ldsm4(aH[mt], smem_u32(sb + QA_H + ar * FSPAD + ac));
                ldsm4(aL[mt], smem_u32(sb + QA_L + ar * FSPAD + ac));
            }
            uint32_t bh2[2][4], bl2[2][4];
            #pragma unroll
            for (int q = 0; q < 2; q++) {
                int vr = ks * 16 + (lane & 15);
                int vc = wn * 32 + q * 16 + ((lane >> 4) << 3);
                ldsm4t(bh2[q], smem_u32(sb + QB_H + vr * WPAD + vc));
                ldsm4t(bl2[q], smem_u32(sb + QB_L + vr * WPAD + vc));
            }
            #pragma unroll
            for (int mt = 0; mt < 4; mt++)
                #pragma unroll
                for (int nt = 0; nt < 4; nt++) {
                    const uint32_t* bhf = &bh2[nt >> 1][(nt & 1) * 2];
                    const uint32_t* blf = &bl2[nt >> 1][(nt & 1) * 2];
                    mma_bf16(acc[mt][nt], aH[mt], bhf);
                    mma_bf16(acc[mt][nt], aH[mt], blf);
                    mma_bf16(acc[mt][nt], aL[mt], bhf);
                }
        }
        if (ch < NCHUNK - 1) CP_WAIT0();
        __syncthreads();
    }
}

__global__ void __launch_bounds__(256, 1) qkv_mma_kernel(const float* __restrict__ bias) {
    extern __shared__ __nv_bfloat16 qsm[];
    const int bx = blockIdx.x * 128;
    const int by = blockIdx.y * 128;
    const int wid = threadIdx.x >> 5, lane = threadIdx.x & 31;
    const int wm = wid & 1, wn = wid >> 1;

    float acc[4][4][4] = {};
    mma_gemm_main<TWO_C_, C_>(g_xh, g_xl, g_wqh, g_wql, qsm, by, bx, acc);

    #pragma unroll
    for (int mt = 0; mt < 4; mt++) {
        int r0 = by + wm * 64 + mt * 16 + (lane >> 2);
        #pragma unroll
        for (int nt = 0; nt < 4; nt++) {
            int col = bx + wn * 32 + nt * 8 + (lane & 3) * 2;
            float b0 = bias[col], b1 = bias[col + 1];
            #pragma unroll
            for (int half = 0; half < 2; half++) {
                int r = r0 + half * 8;
                float v0 = acc[mt][nt][half * 2]     + b0;
                float v1 = acc[mt][nt][half * 2 + 1] + b1;
                int bb = r >> 10, n = r & 1023;
                int which = col >= C_;
                int cc = col - which * C_;
                int hh = cc / HD_, hd = cc % HD_;
                size_t idx = (((size_t)(bb * H_ + hh)) * N_ + n) * HD_ + hd;
                if (!which) {
                    *(float2*)&g_k[idx] = make_float2(v0, v1);
                } else {
                    uint32_t h2, l2;
                    split2h(v0, v1, h2, l2);
                    *(uint32_t*)&g_vh[idx] = h2;
                    *(uint32_t*)&g_vl[idx] = l2;
                }
            }
        }
    }
}

__global__ void __launch_bounds__(256, 1) proj_mma_kernel(const float* __restrict__ bias,
                                                          float* __restrict__ out) {
    extern __shared__ __nv_bfloat16 qsm[];
    const int bx = blockIdx.x * 128;
    const int by = blockIdx.y * 128;
    const int wid = threadIdx.x >> 5, lane = threadIdx.x & 31;
    const int wm = wid & 1, wn = wid >> 1;

    float acc[4][4][4] = {};
    mma_gemm_main<C_, C_>(g_och, g_ocl, g_wph, g_wpl, qsm, by, bx, acc);

    #pragma unroll
    for (int mt = 0; mt < 4; mt++) {
        int r0 = by + wm * 64 + mt * 16 + (lane >> 2);
        #pragma unroll
        for (int nt = 0; nt < 4; nt++) {
            int col = bx + wn * 32 + nt * 8 + (lane & 3) * 2;
            float b0 = bias[col], b1 = bias[col + 1];
            *(float2*)&out[(size_t)r0 * C_ + col] =
                make_float2(acc[mt][nt][0] + b0, acc[mt][nt][1] + b1);
            *(float2*)&out[(size_t)(r0 + 8) * C_ + col] =
                make_float2(acc[mt][nt][2] + b0, acc[mt][nt][3] + b1);
        }
    }
}

// ---------------- launch ----------------
extern "C" void kernel_launch(void* const* d_in, const int* in_sizes, int n_in,
                              void* d_out, int out_size) {
    const float* x     = (const float*)d_in[0];
    const float* Wqkv  = (const float*)d_in[1];
    const float* bqkv  = (const float*)d_in[2];
    const float* Wproj = (const float*)d_in[3];
    const float* bproj = (const float*)d_in[4];
    float* out = (float*)d_out;

    float* attn;
    if ((size_t)out_size >= OUT_ELEMS + ATTN_ELEMS) {
        attn = out + OUT_ELEMS;
    } else {
        void* p = nullptr;
        cudaGetSymbolAddress(&p, g_attn_fallback);
        attn = (float*)p;
    }

    const int FLASH_SMEM = (18432 + 2 * 36864) * 2;   // 184,320 B
    const int GEMM_SMEM  = 2 * QSTG * 2;              // 143,360 B
    cudaFuncSetAttribute(flash_iter_kernel, cudaFuncAttributeMaxDynamicSharedMemorySize, FLASH_SMEM);
    cudaFuncSetAttribute(final_flash_kernel, cudaFuncAttributeMaxDynamicSharedMemorySize, FLASH_SMEM);
    cudaFuncSetAttribute(qkv_mma_kernel, cudaFuncAttributeMaxDynamicSharedMemorySize, GEMM_SMEM);
    cudaFuncSetAttribute(proj_mma_kernel, cudaFuncAttributeMaxDynamicSharedMemorySize, GEMM_SMEM);

    __nv_bfloat16 *xh, *xl, *wqh, *wql, *wph, *wpl;
    { void* p; cudaGetSymbolAddress(&p, g_xh);  xh  = (__nv_bfloat16*)p; }
    { void* p; cudaGetSymbolAddress(&p, g_xl);  xl  = (__nv_bfloat16*)p; }
    { void* p; cudaGetSymbolAddress(&p, g_wqh); wqh = (__nv_bfloat16*)p; }
    { void* p; cudaGetSymbolAddress(&p, g_wql); wql = (__nv_bfloat16*)p; }
    { void* p; cudaGetSymbolAddress(&p, g_wph); wph = (__nv_bfloat16*)p; }
    { void* p; cudaGetSymbolAddress(&p, g_wpl); wpl = (__nv_bfloat16*)p; }

    const int eblocks = (int)((KV_ELEMS + 255) / 256);

    split_kernel<<<(6291456 + 255) / 256, 256>>>(x, xh, xl, 6291456);
    split_kernel<<<(1179648 + 255) / 256, 256>>>(Wqkv, wqh, wql, 1179648);
    split_kernel<<<(589824 + 255) / 256, 256>>>(Wproj, wph, wpl, 589824);

    qkv_mma_kernel<<<dim3(TWO_C_ / 128, M_ROWS / 128), 256, GEMM_SMEM>>>(bqkv);
    mu_kernel<<<BH_, 256>>>();
    k2_init_kernel<<<eblocks, 256>>>();

    for (int it = 0; it < 5; ++it)
        flash_iter_kernel<<<dim3(N_ / 128, BH_), 256, FLASH_SMEM>>>();

    final_flash_kernel<<<dim3(N_ / 128, BH_), 256, FLASH_SMEM>>>(attn);

    proj_mma_kernel<<<dim3(C_ / 128, M_ROWS / 128), 256, GEMM_SMEM>>>(bproj, out);
}

// round 9
// speedup vs baseline: 5.3021x; 1.0592x over previous
#include <cuda_runtime.h>
#include <cuda_bf16.h>
#include <cuda_fp16.h>
#include <math.h>
#include <stdint.h>

#define B_   8
#define N_   1024
#define C_   768
#define H_   12
#define HD_  64
#define BH_  (B_*H_)
#define TWO_C_ (2*C_)
#define M_ROWS (B_*N_)

static const size_t KV_ELEMS   = (size_t)BH_ * N_ * HD_;
static const size_t OUT_ELEMS  = (size_t)B_ * N_ * C_;
static const size_t ATTN_ELEMS = (size_t)BH_ * N_ * N_;

#define LAMBD_ 4.0f
// logits carried in log2 domain: S2 = (k2*QSC)·(k2*QSC)^T where QSC^2 = 0.125*log2(e)
#define QSC_ 0.42466089f

// ---------------- device scratch ----------------
__device__ float g_k [6291456];
__device__ float g_y [6291456];
__device__ float g_s [6291456];
// ping-pong k2 buffers (fixes cross-CTA iteration race)
__device__ __nv_bfloat16 g_k2h_a[6291456];
__device__ __nv_bfloat16 g_k2l_a[6291456];
__device__ __nv_bfloat16 g_k2h_b[6291456];
__device__ __nv_bfloat16 g_k2l_b[6291456];
__device__ __half g_vh [6291456];
__device__ __half g_vl [6291456];
__device__ __nv_bfloat16 g_xh [6291456];
__device__ __nv_bfloat16 g_xl [6291456];
__device__ __nv_bfloat16 g_wqh[1179648];
__device__ __nv_bfloat16 g_wql[1179648];
__device__ __nv_bfloat16 g_wph[589824];
__device__ __nv_bfloat16 g_wpl[589824];
__device__ __nv_bfloat16 g_och[6291456];
__device__ __nv_bfloat16 g_ocl[6291456];
__device__ float g_mu[96];
__device__ float g_attn_fallback[100663296];

// ---------------- helpers ----------------
__device__ __forceinline__ uint32_t smem_u32(const void* p) {
    uint32_t a;
    asm("{ .reg .u64 t; cvta.to.shared.u64 t, %1; cvt.u32.u64 %0, t; }" : "=r"(a) : "l"(p));
    return a;
}
__device__ __forceinline__ void ldsm4(uint32_t r[4], uint32_t addr) {
    asm volatile("ldmatrix.sync.aligned.m8n8.x4.shared.b16 {%0,%1,%2,%3}, [%4];"
        : "=r"(r[0]), "=r"(r[1]), "=r"(r[2]), "=r"(r[3]) : "r"(addr));
}
__device__ __forceinline__ void ldsm4t(uint32_t r[4], uint32_t addr) {
    asm volatile("ldmatrix.sync.aligned.m8n8.x4.trans.shared.b16 {%0,%1,%2,%3}, [%4];"
        : "=r"(r[0]), "=r"(r[1]), "=r"(r[2]), "=r"(r[3]) : "r"(addr));
}
__device__ __forceinline__ void mma_bf16(float c[4], const uint32_t a[4], const uint32_t* b) {
    asm volatile("mma.sync.aligned.m16n8k16.row.col.f32.bf16.bf16.f32 "
        "{%0,%1,%2,%3}, {%4,%5,%6,%7}, {%8,%9}, {%0,%1,%2,%3};"
        : "+f"(c[0]), "+f"(c[1]), "+f"(c[2]), "+f"(c[3])
        : "r"(a[0]), "r"(a[1]), "r"(a[2]), "r"(a[3]), "r"(b[0]), "r"(b[1]));
}
__device__ __forceinline__ void mma_f16(float c[4], const uint32_t a[4], const uint32_t* b) {
    asm volatile("mma.sync.aligned.m16n8k16.row.col.f32.f16.f16.f32 "
        "{%0,%1,%2,%3}, {%4,%5,%6,%7}, {%8,%9}, {%0,%1,%2,%3};"
        : "+f"(c[0]), "+f"(c[1]), "+f"(c[2]), "+f"(c[3])
        : "r"(a[0]), "r"(a[1]), "r"(a[2]), "r"(a[3]), "r"(b[0]), "r"(b[1]));
}
__device__ __forceinline__ void split2(float x, float y, uint32_t& hi, uint32_t& lo) {
    __nv_bfloat16 hx = __float2bfloat16(x), hy = __float2bfloat16(y);
    __nv_bfloat162 h2; h2.x = hx; h2.y = hy;
    __nv_bfloat162 l2;
    l2.x = __float2bfloat16(x - __bfloat162float(hx));
    l2.y = __float2bfloat16(y - __bfloat162float(hy));
    hi = *reinterpret_cast<uint32_t*>(&h2);
    lo = *reinterpret_cast<uint32_t*>(&l2);
}
__device__ __forceinline__ void split2h(float x, float y, uint32_t& hi, uint32_t& lo) {
    __half2 h = __floats2half2_rn(x, y);
    __half2 l = __floats2half2_rn(x - __half2float(h.x), y - __half2float(h.y));
    hi = *reinterpret_cast<uint32_t*>(&h);
    lo = *reinterpret_cast<uint32_t*>(&l);
}
__device__ __forceinline__ uint32_t pack_h2(float x, float y) {
    __half2 h = __floats2half2_rn(x, y);
    return *reinterpret_cast<uint32_t*>(&h);
}
__device__ __forceinline__ float ex2f(float x) {
    float y; asm("ex2.approx.f32 %0, %1;" : "=f"(y) : "f"(x)); return y;
}
__device__ __forceinline__ void cp16(uint32_t dst, const void* src) {
    asm volatile("cp.async.cg.shared.global [%0], [%1], 16;" :: "r"(dst), "l"(src));
}
#define CP_COMMIT() asm volatile("cp.async.commit_group;" ::: "memory")
#define CP_WAIT0()  asm volatile("cp.async.wait_group 0;" ::: "memory")

// ---------------- elementwise ----------------
__global__ void split_kernel(const float* __restrict__ src, __nv_bfloat16* __restrict__ h,
                             __nv_bfloat16* __restrict__ l, int n) {
    int i = blockIdx.x * 256 + threadIdx.x;
    if (i >= n) return;
    float v = src[i];
    __nv_bfloat16 hi = __float2bfloat16(v);
    h[i] = hi;
    l[i] = __float2bfloat16(v - __bfloat162float(hi));
}

__global__ void k2_init_kernel() {
    size_t i = (size_t)blockIdx.x * 256 + threadIdx.x;
    if (i >= KV_ELEMS) return;
    int bh = (int)(i / ((size_t)N_ * HD_));
    float mu = g_mu[bh];
    float kk = g_k[i];
    float lm = LAMBD_ * mu;
    float s  = (kk >= lm) ? (kk - lm) : ((kk <= -lm) ? (kk + lm) : 0.f);
    g_s[i] = s;
    g_y[i] = 0.f;
    float k2 = (kk - s) * QSC_;
    __nv_bfloat16 hi = __float2bfloat16(k2);
    g_k2h_a[i] = hi;
    g_k2l_a[i] = __float2bfloat16(k2 - __bfloat162float(hi));
}

__global__ void mu_kernel() {
    __shared__ float red[256];
    int bh = blockIdx.x;
    const float* p = g_k + (size_t)bh * N_ * HD_;
    float s = 0.f;
    for (int i = threadIdx.x; i < N_ * HD_; i += 256) s += fabsf(p[i]);
    red[threadIdx.x] = s;
    __syncthreads();
    for (int st = 128; st > 0; st >>= 1) {
        if (threadIdx.x < st) red[threadIdx.x] += red[threadIdx.x + st];
        __syncthreads();
    }
    if (threadIdx.x == 0) g_mu[bh] = ((float)N_ * (float)C_ / 4.0f) / red[0];
}

// =================== flash iteration (iters 0..4) + fused y/s/k2 update ===================
// KV tiles of 64 rows -> smem 110.6KB -> 2 CTAs/SM (16 warps).
// k2 is double-buffered: reads SRC (this iteration), writes DST (next iteration).
#define FSPAD 72
#define FA_H  0
#define FA_L  9216
#define FSTG0 18432
#define FSTGS 18432     // stage size in elems: 4 arrays x 64 x 72
#define FS_BH 0
#define FS_BL 4608
#define FS_VH 9216
#define FS_VL 13824

__global__ void __launch_bounds__(256, 2) flash_iter_kernel(
    const __nv_bfloat16* __restrict__ k2h_src, const __nv_bfloat16* __restrict__ k2l_src,
    __nv_bfloat16* __restrict__ k2h_dst, __nv_bfloat16* __restrict__ k2l_dst)
{
    extern __shared__ __nv_bfloat16 fsm[];
    const int bh = blockIdx.y;
    const int i0 = blockIdx.x * 128;
    const int tid = threadIdx.x, wid = tid >> 5, lane = tid & 31;

    const size_t hbase = (size_t)bh * N_ * HD_;
    const __nv_bfloat16* Gh = k2h_src + hbase;
    const __nv_bfloat16* Gl = k2l_src + hbase;
    const __half* Vh = g_vh + hbase;
    const __half* Vl = g_vl + hbase;
    const float mu = g_mu[bh];

    #pragma unroll
    for (int i = 0; i < 8; i++) {
        int idx = tid + i * 256;
        int arr = idx >> 10, rem = idx & 1023, row = rem >> 3, c = rem & 7;
        const __nv_bfloat16* src = (arr ? Gl : Gh) + (size_t)(i0 + row) * HD_ + c * 8;
        *(uint4*)(fsm + (arr ? FA_L : FA_H) + row * FSPAD + c * 8) = *(const uint4*)src;
    }

    auto cp_tile = [&](int stage, int j) {
        int sbase = FSTG0 + stage * FSTGS;
        #pragma unroll
        for (int i = 0; i < 8; i++) {
            int idx = tid + i * 256;           // 0..2047: 4 arrays x 64 rows x 8 chunks
            int arr = idx >> 9, rem = idx & 511, row = rem >> 3, c = rem & 7;
            const void* src;
            int off;
            if      (arr == 0) { src = Gh + (size_t)(j * 64 + row) * HD_ + c * 8; off = FS_BH; }
            else if (arr == 1) { src = Gl + (size_t)(j * 64 + row) * HD_ + c * 8; off = FS_BL; }
            else if (arr == 2) { src = Vh + (size_t)(j * 64 + row) * HD_ + c * 8; off = FS_VH; }
            else               { src = Vl + (size_t)(j * 64 + row) * HD_ + c * 8; off = FS_VL; }
            cp16(smem_u32(fsm + sbase + off + row * FSPAD + c * 8), src);
        }
    };

    cp_tile(0, 0);
    CP_COMMIT(); CP_WAIT0();
    __syncthreads();

    float m0 = -1e30f, m1 = -1e30f, l0 = 0.f, l1 = 0.f;
    float acco[8][4] = {};

    for (int j = 0; j < 16; j++) {
        if (j < 15) { cp_tile((j + 1) & 1, j + 1); CP_COMMIT(); }
        const __nv_bfloat16* sb = fsm + FSTG0 + (j & 1) * FSTGS;

        float accs[8][4] = {};
        #pragma unroll
        for (int ks = 0; ks < 4; ks++) {
            uint32_t aH[4], aL[4];
            {
                int ar = wid * 16 + (lane & 15);
                int ac = ks * 16 + ((lane >> 4) << 3);
                ldsm4(aH, smem_u32(fsm + FA_H + ar * FSPAD + ac));
                ldsm4(aL, smem_u32(fsm + FA_L + ar * FSPAD + ac));
            }
            #pragma unroll
            for (int ng = 0; ng < 2; ng++) {
                uint32_t bh2[2][4], bl2[2][4];
                #pragma unroll
                for (int p = 0; p < 2; p++) {
                    int nr = ng * 32 + p * 16 + (lane & 7) + ((lane >> 4) << 3);
                    int kc = ks * 16 + (((lane >> 3) & 1) << 3);
                    ldsm4(bh2[p], smem_u32(sb + FS_BH + nr * FSPAD + kc));
                    ldsm4(bl2[p], smem_u32(sb + FS_BL + nr * FSPAD + kc));
                }
                #pragma unroll
                for (int t = 0; t < 4; t++) {
                    float* c = accs[ng * 4 + t];
                    const uint32_t* bhf = &bh2[t >> 1][(t & 1) * 2];
                    const uint32_t* blf = &bl2[t >> 1][(t & 1) * 2];
                    mma_bf16(c, aH, bhf);
                    mma_bf16(c, aH, blf);
                    mma_bf16(c, aL, bhf);
                }
            }
        }

        // online softmax in log2 domain
        float tm0 = -1e30f, tm1 = -1e30f;
        #pragma unroll
        for (int t = 0; t < 8; t++) {
            tm0 = fmaxf(tm0, fmaxf(accs[t][0], accs[t][1]));
            tm1 = fmaxf(tm1, fmaxf(accs[t][2], accs[t][3]));
        }
        tm0 = fmaxf(tm0, __shfl_xor_sync(0xFFFFFFFF, tm0, 1));
        tm0 = fmaxf(tm0, __shfl_xor_sync(0xFFFFFFFF, tm0, 2));
        tm1 = fmaxf(tm1, __shfl_xor_sync(0xFFFFFFFF, tm1, 1));
        tm1 = fmaxf(tm1, __shfl_xor_sync(0xFFFFFFFF, tm1, 2));
        float mn0 = fmaxf(m0, tm0), mn1 = fmaxf(m1, tm1);
        float sc0 = ex2f(m0 - mn0), sc1 = ex2f(m1 - mn1);
        m0 = mn0; m1 = mn1;
        float rs0 = 0.f, rs1 = 0.f;
        #pragma unroll
        for (int t = 0; t < 8; t++) {
            accs[t][0] = ex2f(accs[t][0] - m0);
            accs[t][1] = ex2f(accs[t][1] - m0);
            accs[t][2] = ex2f(accs[t][2] - m1);
            accs[t][3] = ex2f(accs[t][3] - m1);
            rs0 += accs[t][0] + accs[t][1];
            rs1 += accs[t][2] + accs[t][3];
        }
        rs0 += __shfl_xor_sync(0xFFFFFFFF, rs0, 1);
        rs0 += __shfl_xor_sync(0xFFFFFFFF, rs0, 2);
        rs1 += __shfl_xor_sync(0xFFFFFFFF, rs1, 1);
        rs1 += __shfl_xor_sync(0xFFFFFFFF, rs1, 2);
        l0 = l0 * sc0 + rs0;
        l1 = l1 * sc1 + rs1;
        #pragma unroll
        for (int o = 0; o < 8; o++) {
            acco[o][0] *= sc0; acco[o][1] *= sc0;
            acco[o][2] *= sc1; acco[o][3] *= sc1;
        }

        // PV: P fp16 x V (fp16 hi/lo)
        #pragma unroll
        for (int kt = 0; kt < 4; kt++) {
            uint32_t pH[4];
            pH[0] = pack_h2(accs[2*kt][0],   accs[2*kt][1]);
            pH[1] = pack_h2(accs[2*kt][2],   accs[2*kt][3]);
            pH[2] = pack_h2(accs[2*kt+1][0], accs[2*kt+1][1]);
            pH[3] = pack_h2(accs[2*kt+1][2], accs[2*kt+1][3]);
            #pragma unroll
            for (int vg = 0; vg < 2; vg++) {
                uint32_t vh2[2][4], vl2[2][4];
                #pragma unroll
                for (int q = 0; q < 2; q++) {
                    int vr = kt * 16 + (lane & 15);
                    int vc = vg * 32 + q * 16 + ((lane >> 4) << 3);
                    ldsm4t(vh2[q], smem_u32(sb + FS_VH + vr * FSPAD + vc));
                    ldsm4t(vl2[q], smem_u32(sb + FS_VL + vr * FSPAD + vc));
                }
                #pragma unroll
                for (int t = 0; t < 4; t++) {
                    float* o = acco[vg * 4 + t];
                    mma_f16(o, pH, &vh2[t >> 1][(t & 1) * 2]);
                    mma_f16(o, pH, &vl2[t >> 1][(t & 1) * 2]);
                }
            }
        }

        if (j < 15) CP_WAIT0();
        __syncthreads();
    }

    // ---- fused epilogue: l (in regs) -> y, s, k2 update into DST buffer ----
    float inv0 = 1.f / l0, inv1 = 1.f / l1;
    float imu = 1.f / mu;
    float lm = LAMBD_ * mu;
    int row0 = i0 + wid * 16 + (lane >> 2);
    #pragma unroll
    for (int o = 0; o < 8; o++) {
        int col = o * 8 + (lane & 3) * 2;
        #pragma unroll
        for (int half = 0; half < 2; half++) {
            size_t ia = hbase + (size_t)(row0 + half * 8) * HD_ + col;
            float la = acco[o][half * 2]     * (half ? inv1 : inv0);
            float lb = acco[o][half * 2 + 1] * (half ? inv1 : inv0);
            float2 kv = *(const float2*)&g_k[ia];
            float2 yv = *(const float2*)&g_y[ia];
            float2 sv = *(const float2*)&g_s[ia];
            float yn0 = yv.x + mu * (kv.x - la - sv.x);
            float yn1 = yv.y + mu * (kv.y - lb - sv.y);
            float ym0 = yn0 * imu, ym1 = yn1 * imu;
            float t0 = kv.x - la + ym0, t1 = kv.y - lb + ym1;
            float sn0 = (t0 >= lm) ? (t0 - lm) : ((t0 <= -lm) ? (t0 + lm) : 0.f);
            float sn1 = (t1 >= lm) ? (t1 - lm) : ((t1 <= -lm) ? (t1 + lm) : 0.f);
            *(float2*)&g_y[ia] = make_float2(yn0, yn1);
            *(float2*)&g_s[ia] = make_float2(sn0, sn1);
            float k20 = (kv.x - sn0 - ym0) * QSC_;
            float k21 = (kv.y - sn1 - ym1) * QSC_;
            uint32_t h2, l2;
            split2(k20, k21, h2, l2);
            *(uint32_t*)&k2h_dst[ia] = h2;
            *(uint32_t*)&k2l_dst[ia] = l2;
        }
    }
}

// =================== final iteration: 2-pass flash, materializes attn + obnc ===================
__global__ void __launch_bounds__(256, 2) final_flash_kernel(
    float* __restrict__ attn,
    const __nv_bfloat16* __restrict__ k2h_src, const __nv_bfloat16* __restrict__ k2l_src)
{
    extern __shared__ __nv_bfloat16 fsm[];
    const int bh = blockIdx.y;
    const int i0 = blockIdx.x * 128;
    const int tid = threadIdx.x, wid = tid >> 5, lane = tid & 31;

    const size_t hbase = (size_t)bh * N_ * HD_;
    const __nv_bfloat16* Gh = k2h_src + hbase;
    const __nv_bfloat16* Gl = k2l_src + hbase;
    const __half* Vh = g_vh + hbase;
    const __half* Vl = g_vl + hbase;

    #pragma unroll
    for (int i = 0; i < 8; i++) {
        int idx = tid + i * 256;
        int arr = idx >> 10, rem = idx & 1023, row = rem >> 3, c = rem & 7;
        const __nv_bfloat16* src = (arr ? Gl : Gh) + (size_t)(i0 + row) * HD_ + c * 8;
        *(uint4*)(fsm + (arr ? FA_L : FA_H) + row * FSPAD + c * 8) = *(const uint4*)src;
    }

    auto cp_tile = [&](int stage, int j, bool withV) {
        int sbase = FSTG0 + stage * FSTGS;
        #pragma unroll
        for (int i = 0; i < 8; i++) {
            int idx = tid + i * 256;
            int arr = idx >> 9, rem = idx & 511, row = rem >> 3, c = rem & 7;
            if (!withV && arr >= 2) continue;
            const void* src;
            int off;
            if      (arr == 0) { src = Gh + (size_t)(j * 64 + row) * HD_ + c * 8; off = FS_BH; }
            else if (arr == 1) { src = Gl + (size_t)(j * 64 + row) * HD_ + c * 8; off = FS_BL; }
            else if (arr == 2) { src = Vh + (size_t)(j * 64 + row) * HD_ + c * 8; off = FS_VH; }
            else               { src = Vl + (size_t)(j * 64 + row) * HD_ + c * 8; off = FS_VL; }
            cp16(smem_u32(fsm + sbase + off + row * FSPAD + c * 8), src);
        }
    };

    auto compute_S = [&](const __nv_bfloat16* sb, float accs[8][4]) {
        #pragma unroll
        for (int ks = 0; ks < 4; ks++) {
            uint32_t aH[4], aL[4];
            {
                int ar = wid * 16 + (lane & 15);
                int ac = ks * 16 + ((lane >> 4) << 3);
                ldsm4(aH, smem_u32(fsm + FA_H + ar * FSPAD + ac));
                ldsm4(aL, smem_u32(fsm + FA_L + ar * FSPAD + ac));
            }
            #pragma unroll
            for (int ng = 0; ng < 2; ng++) {
                uint32_t bh2[2][4], bl2[2][4];
                #pragma unroll
                for (int p = 0; p < 2; p++) {
                    int nr = ng * 32 + p * 16 + (lane & 7) + ((lane >> 4) << 3);
                    int kc = ks * 16 + (((lane >> 3) & 1) << 3);
                    ldsm4(bh2[p], smem_u32(sb + FS_BH + nr * FSPAD + kc));
                    ldsm4(bl2[p], smem_u32(sb + FS_BL + nr * FSPAD + kc));
                }
                #pragma unroll
                for (int t = 0; t < 4; t++) {
                    float* c = accs[ng * 4 + t];
                    const uint32_t* bhf = &bh2[t >> 1][(t & 1) * 2];
                    const uint32_t* blf = &bl2[t >> 1][(t & 1) * 2];
                    mma_bf16(c, aH, bhf);
                    mma_bf16(c, aH, blf);
                    mma_bf16(c, aL, bhf);
                }
            }
        }
    };

    // ---------- PASS A: row stats ----------
    cp_tile(0, 0, false);
    CP_COMMIT(); CP_WAIT0();
    __syncthreads();

    float m0 = -1e30f, m1 = -1e30f, l0 = 0.f, l1 = 0.f;
    for (int j = 0; j < 16; j++) {
        if (j < 15) { cp_tile((j + 1) & 1, j + 1, false); CP_COMMIT(); }
        const __nv_bfloat16* sb = fsm + FSTG0 + (j & 1) * FSTGS;
        float accs[8][4] = {};
        compute_S(sb, accs);

        float tm0 = -1e30f, tm1 = -1e30f;
        #pragma unroll
        for (int t = 0; t < 8; t++) {
            tm0 = fmaxf(tm0, fmaxf(accs[t][0], accs[t][1]));
            tm1 = fmaxf(tm1, fmaxf(accs[t][2], accs[t][3]));
        }
        tm0 = fmaxf(tm0, __shfl_xor_sync(0xFFFFFFFF, tm0, 1));
        tm0 = fmaxf(tm0, __shfl_xor_sync(0xFFFFFFFF, tm0, 2));
        tm1 = fmaxf(tm1, __shfl_xor_sync(0xFFFFFFFF, tm1, 1));
        tm1 = fmaxf(tm1, __shfl_xor_sync(0xFFFFFFFF, tm1, 2));
        float mn0 = fmaxf(m0, tm0), mn1 = fmaxf(m1, tm1);
        float sc0 = ex2f(m0 - mn0), sc1 = ex2f(m1 - mn1);
        m0 = mn0; m1 = mn1;
        float rs0 = 0.f, rs1 = 0.f;
        #pragma unroll
        for (int t = 0; t < 8; t++) {
            rs0 += ex2f(accs[t][0] - m0) + ex2f(accs[t][1] - m0);
            rs1 += ex2f(accs[t][2] - m1) + ex2f(accs[t][3] - m1);
        }
        rs0 += __shfl_xor_sync(0xFFFFFFFF, rs0, 1);
        rs0 += __shfl_xor_sync(0xFFFFFFFF, rs0, 2);
        rs1 += __shfl_xor_sync(0xFFFFFFFF, rs1, 1);
        rs1 += __shfl_xor_sync(0xFFFFFFFF, rs1, 2);
        l0 = l0 * sc0 + rs0;
        l1 = l1 * sc1 + rs1;
        if (j < 15) CP_WAIT0();
        __syncthreads();
    }
    float inv0 = 1.f / l0, inv1 = 1.f / l1;

    // ---------- PASS B: normalized P -> attn, PV ----------
    cp_tile(0, 0, true);
    CP_COMMIT(); CP_WAIT0();
    __syncthreads();

    float* Sp = attn + (size_t)bh * N_ * N_;
    const int prow = i0 + wid * 16 + (lane >> 2);
    float acco[8][4] = {};

    for (int j = 0; j < 16; j++) {
        if (j < 15) { cp_tile((j + 1) & 1, j + 1, true); CP_COMMIT(); }
        const __nv_bfloat16* sb = fsm + FSTG0 + (j & 1) * FSTGS;
        float accs[8][4] = {};
        compute_S(sb, accs);

        #pragma unroll
        for (int t = 0; t < 8; t++) {
            accs[t][0] = ex2f(accs[t][0] - m0) * inv0;
            accs[t][1] = ex2f(accs[t][1] - m0) * inv0;
            accs[t][2] = ex2f(accs[t][2] - m1) * inv1;
            accs[t][3] = ex2f(accs[t][3] - m1) * inv1;
            int col = j * 64 + (t >> 2) * 32 + (t & 3) * 8 + (lane & 3) * 2;
            *(float2*)&Sp[(size_t)prow * N_ + col]       = make_float2(accs[t][0], accs[t][1]);
            *(float2*)&Sp[(size_t)(prow + 8) * N_ + col] = make_float2(accs[t][2], accs[t][3]);
        }

        #pragma unroll
        for (int kt = 0; kt < 4; kt++) {
            uint32_t pH[4];
            pH[0] = pack_h2(accs[2*kt][0],   accs[2*kt][1]);
            pH[1] = pack_h2(accs[2*kt][2],   accs[2*kt][3]);
            pH[2] = pack_h2(accs[2*kt+1][0], accs[2*kt+1][1]);
            pH[3] = pack_h2(accs[2*kt+1][2], accs[2*kt+1][3]);
            #pragma unroll
            for (int vg = 0; vg < 2; vg++) {
                uint32_t vh2[2][4], vl2[2][4];
                #pragma unroll
                for (int q = 0; q < 2; q++) {
                    int vr = kt * 16 + (lane & 15);
                    int vc = vg * 32 + q * 16 + ((lane >> 4) << 3);
                    ldsm4t(vh2[q], smem_u32(sb + FS_VH + vr * FSPAD + vc));
                    ldsm4t(vl2[q], smem_u32(sb + FS_VL + vr * FSPAD + vc));
                }
                #pragma unroll
                for (int t = 0; t < 4; t++) {
                    float* o = acco[vg * 4 + t];
                    mma_f16(o, pH, &vh2[t >> 1][(t & 1) * 2]);
                    mma_f16(o, pH, &vl2[t >> 1][(t & 1) * 2]);
                }
            }
        }

        if (j < 15) CP_WAIT0();
        __syncthreads();
    }

    int b = bh / H_, h = bh % H_;
    #pragma unroll
    for (int o = 0; o < 8; o++) {
        int col = o * 8 + (lane & 3) * 2;
        uint32_t h0, l0b, h1, l1b;
        split2(acco[o][0], acco[o][1], h0, l0b);
        split2(acco[o][2], acco[o][3], h1, l1b);
        size_t idx0 = ((size_t)(b * N_ + prow)) * C_ + h * HD_ + col;
        size_t idx1 = ((size_t)(b * N_ + prow + 8)) * C_ + h * HD_ + col;
        *(uint32_t*)&g_och[idx0] = h0;
        *(uint32_t*)&g_ocl[idx0] = l0b;
        *(uint32_t*)&g_och[idx1] = h1;
        *(uint32_t*)&g_ocl[idx1] = l1b;
    }
}

// =================== bf16x3 HMMA GEMM: qkv and proj ===================
#define QA_H 0
#define QA_L 9216
#define QB_H 18432
#define QB_L 27136
#define QSTG 35840
#define WPAD 136

template<int NCOLS, int KDIM>
__device__ __forceinline__ void mma_gemm_main(
    const __nv_bfloat16* __restrict__ Ah, const __nv_bfloat16* __restrict__ Al,
    const __nv_bfloat16* __restrict__ Wh, const __nv_bfloat16* __restrict__ Wl,
    __nv_bfloat16* sm, int by, int bx, float acc[4][4][4])
{
    const int tid = threadIdx.x, wid = tid >> 5, lane = tid & 31;
    const int wm = wid & 1, wn = wid >> 1;

    auto cp_stage = [&](int stage, int k0) {
        int sb = stage * QSTG;
        #pragma unroll
        for (int i = 0; i < 8; i++) {
            int idx = tid + i * 256;
            int arr = idx >> 10, rem = idx & 1023, row = rem >> 3, c = rem & 7;
            const __nv_bfloat16* src = (arr ? Al : Ah) + (size_t)(by + row) * KDIM + k0 + c * 8;
            cp16(smem_u32(sm + sb + (arr ? QA_L : QA_H) + row * FSPAD + c * 8), src);
        }
        #pragma unroll
        for (int i = 0; i < 8; i++) {
            int idx = tid + i * 256;
            int arr = idx >> 10, rem = idx & 1023, row = rem >> 4, c = rem & 15;
            const __nv_bfloat16* src = (arr ? Wl : Wh) + (size_t)(k0 + row) * NCOLS + bx + c * 8;
            cp16(smem_u32(sm + sb + (arr ? QB_L : QB_H) + row * WPAD + c * 8), src);
        }
    };

    cp_stage(0, 0);
    CP_COMMIT(); CP_WAIT0();
    __syncthreads();

    const int NCHUNK = KDIM / 64;
    for (int ch = 0; ch < NCHUNK; ch++) {
        if (ch < NCHUNK - 1) { cp_stage((ch + 1) & 1, (ch + 1) * 64); CP_COMMIT(); }
        __nv_bfloat16* sb = sm + (ch & 1) * QSTG;
        #pragma unroll
        for (int ks = 0; ks < 4; ks++) {
            uint32_t aH[4][4], aL[4][4];
            #pragma unroll
            for (int mt = 0; mt < 4; mt++) {
                int ar = wm * 64 + mt * 16 + (lane & 15);
                int ac = ks * 16 + ((lane >> 4) << 3);
                ldsm4(aH[mt], smem_u32(sb + QA_H + ar * FSPAD + ac));
                ldsm4(aL[mt], smem_u32(sb + QA_L + ar * FSPAD + ac));
            }
            uint32_t bh2[2][4], bl2[2][4];
            #pragma unroll
            for (int q = 0; q < 2; q++) {
                int vr = ks * 16 + (lane & 15);
                int vc = wn * 32 + q * 16 + ((lane >> 4) << 3);
                ldsm4t(bh2[q], smem_u32(sb + QB_H + vr * WPAD + vc));
                ldsm4t(bl2[q], smem_u32(sb + QB_L + vr * WPAD + vc));
            }
            #pragma unroll
            for (int mt = 0; mt < 4; mt++)
                #pragma unroll
                for (int nt = 0; nt < 4; nt++) {
                    const uint32_t* bhf = &bh2[nt >> 1][(nt & 1) * 2];
                    const uint32_t* blf = &bl2[nt >> 1][(nt & 1) * 2];
                    mma_bf16(acc[mt][nt], aH[mt], bhf);
                    mma_bf16(acc[mt][nt], aH[mt], blf);
                    mma_bf16(acc[mt][nt], aL[mt], bhf);
                }
        }
        if (ch < NCHUNK - 1) CP_WAIT0();
        __syncthreads();
    }
}

__global__ void __launch_bounds__(256, 1) qkv_mma_kernel(const float* __restrict__ bias) {
    extern __shared__ __nv_bfloat16 qsm[];
    const int bx = blockIdx.x * 128;
    const int by = blockIdx.y * 128;
    const int wid = threadIdx.x >> 5, lane = threadIdx.x & 31;
    const int wm = wid & 1, wn = wid >> 1;

    float acc[4][4][4] = {};
    mma_gemm_main<TWO_C_, C_>(g_xh, g_xl, g_wqh, g_wql, qsm, by, bx, acc);

    #pragma unroll
    for (int mt = 0; mt < 4; mt++) {
        int r0 = by + wm * 64 + mt * 16 + (lane >> 2);
        #pragma unroll
        for (int nt = 0; nt < 4; nt++) {
            int col = bx + wn * 32 + nt * 8 + (lane & 3) * 2;
            float b0 = bias[col], b1 = bias[col + 1];
            #pragma unroll
            for (int half = 0; half < 2; half++) {
                int r = r0 + half * 8;
                float v0 = acc[mt][nt][half * 2]     + b0;
                float v1 = acc[mt][nt][half * 2 + 1] + b1;
                int bb = r >> 10, n = r & 1023;
                int which = col >= C_;
                int cc = col - which * C_;
                int hh = cc / HD_, hd = cc % HD_;
                size_t idx = (((size_t)(bb * H_ + hh)) * N_ + n) * HD_ + hd;
                if (!which) {
                    *(float2*)&g_k[idx] = make_float2(v0, v1);
                } else {
                    uint32_t h2, l2;
                    split2h(v0, v1, h2, l2);
                    *(uint32_t*)&g_vh[idx] = h2;
                    *(uint32_t*)&g_vl[idx] = l2;
                }
            }
        }
    }
}

__global__ void __launch_bounds__(256, 1) proj_mma_kernel(const float* __restrict__ bias,
                                                          float* __restrict__ out) {
    extern __shared__ __nv_bfloat16 qsm[];
    const int bx = blockIdx.x * 128;
    const int by = blockIdx.y * 128;
    const int wid = threadIdx.x >> 5, lane = threadIdx.x & 31;
    const int wm = wid & 1, wn = wid >> 1;

    float acc[4][4][4] = {};
    mma_gemm_main<C_, C_>(g_och, g_ocl, g_wph, g_wpl, qsm, by, bx, acc);

    #pragma unroll
    for (int mt = 0; mt < 4; mt++) {
        int r0 = by + wm * 64 + mt * 16 + (lane >> 2);
        #pragma unroll
        for (int nt = 0; nt < 4; nt++) {
            int col = bx + wn * 32 + nt * 8 + (lane & 3) * 2;
            float b0 = bias[col], b1 = bias[col + 1];
            *(float2*)&out[(size_t)r0 * C_ + col] =
                make_float2(acc[mt][nt][0] + b0, acc[mt][nt][1] + b1);
            *(float2*)&out[(size_t)(r0 + 8) * C_ + col] =
                make_float2(acc[mt][nt][2] + b0, acc[mt][nt][3] + b1);
        }
    }
}

// ---------------- launch ----------------
extern "C" void kernel_launch(void* const* d_in, const int* in_sizes, int n_in,
                              void* d_out, int out_size) {
    const float* x     = (const float*)d_in[0];
    const float* Wqkv  = (const float*)d_in[1];
    const float* bqkv  = (const float*)d_in[2];
    const float* Wproj = (const float*)d_in[3];
    const float* bproj = (const float*)d_in[4];
    float* out = (float*)d_out;

    float* attn;
    if ((size_t)out_size >= OUT_ELEMS + ATTN_ELEMS) {
        attn = out + OUT_ELEMS;
    } else {
        void* p = nullptr;
        cudaGetSymbolAddress(&p, g_attn_fallback);
        attn = (float*)p;
    }

    const int FLASH_SMEM = (FSTG0 + 2 * FSTGS) * 2;   // 110,592 B
    const int GEMM_SMEM  = 2 * QSTG * 2;              // 143,360 B
    cudaFuncSetAttribute(flash_iter_kernel, cudaFuncAttributeMaxDynamicSharedMemorySize, FLASH_SMEM);
    cudaFuncSetAttribute(final_flash_kernel, cudaFuncAttributeMaxDynamicSharedMemorySize, FLASH_SMEM);
    cudaFuncSetAttribute(qkv_mma_kernel, cudaFuncAttributeMaxDynamicSharedMemorySize, GEMM_SMEM);
    cudaFuncSetAttribute(proj_mma_kernel, cudaFuncAttributeMaxDynamicSharedMemorySize, GEMM_SMEM);

    __nv_bfloat16 *xh, *xl, *wqh, *wql, *wph, *wpl;
    __nv_bfloat16 *k2h_a, *k2l_a, *k2h_b, *k2l_b;
    { void* p; cudaGetSymbolAddress(&p, g_xh);  xh  = (__nv_bfloat16*)p; }
    { void* p; cudaGetSymbolAddress(&p, g_xl);  xl  = (__nv_bfloat16*)p; }
    { void* p; cudaGetSymbolAddress(&p, g_wqh); wqh = (__nv_bfloat16*)p; }
    { void* p; cudaGetSymbolAddress(&p, g_wql); wql = (__nv_bfloat16*)p; }
    { void* p; cudaGetSymbolAddress(&p, g_wph); wph = (__nv_bfloat16*)p; }
    { void* p; cudaGetSymbolAddress(&p, g_wpl); wpl = (__nv_bfloat16*)p; }
    { void* p; cudaGetSymbolAddress(&p, g_k2h_a); k2h_a = (__nv_bfloat16*)p; }
    { void* p; cudaGetSymbolAddress(&p, g_k2l_a); k2l_a = (__nv_bfloat16*)p; }
    { void* p; cudaGetSymbolAddress(&p, g_k2h_b); k2h_b = (__nv_bfloat16*)p; }
    { void* p; cudaGetSymbolAddress(&p, g_k2l_b); k2l_b = (__nv_bfloat16*)p; }

    const int eblocks = (int)((KV_ELEMS + 255) / 256);

    split_kernel<<<(6291456 + 255) / 256, 256>>>(x, xh, xl, 6291456);
    split_kernel<<<(1179648 + 255) / 256, 256>>>(Wqkv, wqh, wql, 1179648);
    split_kernel<<<(589824 + 255) / 256, 256>>>(Wproj, wph, wpl, 589824);

    qkv_mma_kernel<<<dim3(TWO_C_ / 128, M_ROWS / 128), 256, GEMM_SMEM>>>(bqkv);
    mu_kernel<<<BH_, 256>>>();
    k2_init_kernel<<<eblocks, 256>>>();   // writes buffer A

    // ping-pong k2 buffers across iterations (fixes cross-CTA race)
    __nv_bfloat16* bufs_h[2] = {k2h_a, k2h_b};
    __nv_bfloat16* bufs_l[2] = {k2l_a, k2l_b};
    for (int it = 0; it < 5; ++it) {
        int s = it & 1, d = (it + 1) & 1;
        flash_iter_kernel<<<dim3(N_ / 128, BH_), 256, FLASH_SMEM>>>(
            bufs_h[s], bufs_l[s], bufs_h[d], bufs_l[d]);
    }
    // after 5 iterations, latest k2 lives in buffer (5&1)=1
    final_flash_kernel<<<dim3(N_ / 128, BH_), 256, FLASH_SMEM>>>(attn, bufs_h[1], bufs_l[1]);

    proj_mma_kernel<<<dim3(C_ / 128, M_ROWS / 128), 256, GEMM_SMEM>>>(bproj, out);
}

// round 10
// speedup vs baseline: 5.3664x; 1.0121x over previous
#include <cuda_runtime.h>
#include <cuda_bf16.h>
#include <cuda_fp16.h>
#include <math.h>
#include <stdint.h>

#define B_   8
#define N_   1024
#define C_   768
#define H_   12
#define HD_  64
#define BH_  (B_*H_)
#define TWO_C_ (2*C_)
#define M_ROWS (B_*N_)

static const size_t KV_ELEMS   = (size_t)BH_ * N_ * HD_;
static const size_t OUT_ELEMS  = (size_t)B_ * N_ * C_;
static const size_t ATTN_ELEMS = (size_t)BH_ * N_ * N_;

#define LAMBD_ 4.0f
// logits carried in log2 domain: S2 = (k2*QSC)·(k2*QSC)^T where QSC^2 = 0.125*log2(e)
#define QSC_ 0.42466089f

// ---------------- device scratch ----------------
__device__ float g_k [6291456];
__device__ float g_y [6291456];
__device__ float g_s [6291456];
// ping-pong k2 buffers (fixes cross-CTA iteration race)
__device__ __nv_bfloat16 g_k2h_a[6291456];
__device__ __nv_bfloat16 g_k2l_a[6291456];
__device__ __nv_bfloat16 g_k2h_b[6291456];
__device__ __nv_bfloat16 g_k2l_b[6291456];
__device__ __half g_vh [6291456];
__device__ __half g_vl [6291456];
__device__ __nv_bfloat16 g_xh [6291456];
__device__ __nv_bfloat16 g_xl [6291456];
__device__ __nv_bfloat16 g_wqh[1179648];
__device__ __nv_bfloat16 g_wql[1179648];
__device__ __nv_bfloat16 g_wph[589824];
__device__ __nv_bfloat16 g_wpl[589824];
__device__ __nv_bfloat16 g_och[6291456];
__device__ __nv_bfloat16 g_ocl[6291456];
__device__ float g_mu[96];
__device__ float g_attn_fallback[100663296];

// ---------------- helpers ----------------
__device__ __forceinline__ uint32_t smem_u32(const void* p) {
    uint32_t a;
    asm("{ .reg .u64 t; cvta.to.shared.u64 t, %1; cvt.u32.u64 %0, t; }" : "=r"(a) : "l"(p));
    return a;
}
__device__ __forceinline__ void ldsm4(uint32_t r[4], uint32_t addr) {
    asm volatile("ldmatrix.sync.aligned.m8n8.x4.shared.b16 {%0,%1,%2,%3}, [%4];"
        : "=r"(r[0]), "=r"(r[1]), "=r"(r[2]), "=r"(r[3]) : "r"(addr));
}
__device__ __forceinline__ void ldsm4t(uint32_t r[4], uint32_t addr) {
    asm volatile("ldmatrix.sync.aligned.m8n8.x4.trans.shared.b16 {%0,%1,%2,%3}, [%4];"
        : "=r"(r[0]), "=r"(r[1]), "=r"(r[2]), "=r"(r[3]) : "r"(addr));
}
__device__ __forceinline__ void mma_bf16(float c[4], const uint32_t a[4], const uint32_t* b) {
    asm volatile("mma.sync.aligned.m16n8k16.row.col.f32.bf16.bf16.f32 "
        "{%0,%1,%2,%3}, {%4,%5,%6,%7}, {%8,%9}, {%0,%1,%2,%3};"
        : "+f"(c[0]), "+f"(c[1]), "+f"(c[2]), "+f"(c[3])
        : "r"(a[0]), "r"(a[1]), "r"(a[2]), "r"(a[3]), "r"(b[0]), "r"(b[1]));
}
__device__ __forceinline__ void mma_f16(float c[4], const uint32_t a[4], const uint32_t* b) {
    asm volatile("mma.sync.aligned.m16n8k16.row.col.f32.f16.f16.f32 "
        "{%0,%1,%2,%3}, {%4,%5,%6,%7}, {%8,%9}, {%0,%1,%2,%3};"
        : "+f"(c[0]), "+f"(c[1]), "+f"(c[2]), "+f"(c[3])
        : "r"(a[0]), "r"(a[1]), "r"(a[2]), "r"(a[3]), "r"(b[0]), "r"(b[1]));
}
__device__ __forceinline__ void split2(float x, float y, uint32_t& hi, uint32_t& lo) {
    __nv_bfloat16 hx = __float2bfloat16(x), hy = __float2bfloat16(y);
    __nv_bfloat162 h2; h2.x = hx; h2.y = hy;
    __nv_bfloat162 l2;
    l2.x = __float2bfloat16(x - __bfloat162float(hx));
    l2.y = __float2bfloat16(y - __bfloat162float(hy));
    hi = *reinterpret_cast<uint32_t*>(&h2);
    lo = *reinterpret_cast<uint32_t*>(&l2);
}
__device__ __forceinline__ void split2h(float x, float y, uint32_t& hi, uint32_t& lo) {
    __half2 h = __floats2half2_rn(x, y);
    __half2 l = __floats2half2_rn(x - __half2float(h.x), y - __half2float(h.y));
    hi = *reinterpret_cast<uint32_t*>(&h);
    lo = *reinterpret_cast<uint32_t*>(&l);
}
__device__ __forceinline__ uint32_t pack_h2(float x, float y) {
    __half2 h = __floats2half2_rn(x, y);
    return *reinterpret_cast<uint32_t*>(&h);
}
__device__ __forceinline__ float ex2f(float x) {
    float y; asm("ex2.approx.f32 %0, %1;" : "=f"(y) : "f"(x)); return y;
}
__device__ __forceinline__ void cp16(uint32_t dst, const void* src) {
    asm volatile("cp.async.cg.shared.global [%0], [%1], 16;" :: "r"(dst), "l"(src));
}
#define CP_COMMIT() asm volatile("cp.async.commit_group;" ::: "memory")
#define CP_WAIT0()  asm volatile("cp.async.wait_group 0;" ::: "memory")

// ---------------- elementwise ----------------
__global__ void split_kernel(const float* __restrict__ src, __nv_bfloat16* __restrict__ h,
                             __nv_bfloat16* __restrict__ l, int n) {
    int i = blockIdx.x * 256 + threadIdx.x;
    if (i >= n) return;
    float v = src[i];
    __nv_bfloat16 hi = __float2bfloat16(v);
    h[i] = hi;
    l[i] = __float2bfloat16(v - __bfloat162float(hi));
}

__global__ void k2_init_kernel() {
    size_t i = (size_t)blockIdx.x * 256 + threadIdx.x;
    if (i >= KV_ELEMS) return;
    int bh = (int)(i / ((size_t)N_ * HD_));
    float mu = g_mu[bh];
    float kk = g_k[i];
    float lm = LAMBD_ * mu;
    float s  = (kk >= lm) ? (kk - lm) : ((kk <= -lm) ? (kk + lm) : 0.f);
    g_s[i] = s;
    g_y[i] = 0.f;
    float k2 = (kk - s) * QSC_;
    __nv_bfloat16 hi = __float2bfloat16(k2);
    g_k2h_a[i] = hi;
    g_k2l_a[i] = __float2bfloat16(k2 - __bfloat162float(hi));
}

__global__ void mu_kernel() {
    __shared__ float red[256];
    int bh = blockIdx.x;
    const float* p = g_k + (size_t)bh * N_ * HD_;
    float s = 0.f;
    for (int i = threadIdx.x; i < N_ * HD_; i += 256) s += fabsf(p[i]);
    red[threadIdx.x] = s;
    __syncthreads();
    for (int st = 128; st > 0; st >>= 1) {
        if (threadIdx.x < st) red[threadIdx.x] += red[threadIdx.x + st];
        __syncthreads();
    }
    if (threadIdx.x == 0) g_mu[bh] = ((float)N_ * (float)C_ / 4.0f) / red[0];
}

// =================== flash iteration (iters 0..4) + fused y/s/k2 update ===================
#define FSPAD 72
#define FA_H  0
#define FA_L  9216
#define FSTG0 18432
#define FSTGS 18432
#define FS_BH 0
#define FS_BL 4608
#define FS_VH 9216
#define FS_VL 13824

__global__ void __launch_bounds__(256, 2) flash_iter_kernel(
    const __nv_bfloat16* __restrict__ k2h_src, const __nv_bfloat16* __restrict__ k2l_src,
    __nv_bfloat16* __restrict__ k2h_dst, __nv_bfloat16* __restrict__ k2l_dst)
{
    extern __shared__ __nv_bfloat16 fsm[];
    const int bh = blockIdx.y;
    const int i0 = blockIdx.x * 128;
    const int tid = threadIdx.x, wid = tid >> 5, lane = tid & 31;

    const size_t hbase = (size_t)bh * N_ * HD_;
    const __nv_bfloat16* Gh = k2h_src + hbase;
    const __nv_bfloat16* Gl = k2l_src + hbase;
    const __half* Vh = g_vh + hbase;
    const __half* Vl = g_vl + hbase;
    const float mu = g_mu[bh];

    #pragma unroll
    for (int i = 0; i < 8; i++) {
        int idx = tid + i * 256;
        int arr = idx >> 10, rem = idx & 1023, row = rem >> 3, c = rem & 7;
        const __nv_bfloat16* src = (arr ? Gl : Gh) + (size_t)(i0 + row) * HD_ + c * 8;
        *(uint4*)(fsm + (arr ? FA_L : FA_H) + row * FSPAD + c * 8) = *(const uint4*)src;
    }

    auto cp_tile = [&](int stage, int j) {
        int sbase = FSTG0 + stage * FSTGS;
        #pragma unroll
        for (int i = 0; i < 8; i++) {
            int idx = tid + i * 256;
            int arr = idx >> 9, rem = idx & 511, row = rem >> 3, c = rem & 7;
            const void* src;
            int off;
            if      (arr == 0) { src = Gh + (size_t)(j * 64 + row) * HD_ + c * 8; off = FS_BH; }
            else if (arr == 1) { src = Gl + (size_t)(j * 64 + row) * HD_ + c * 8; off = FS_BL; }
            else if (arr == 2) { src = Vh + (size_t)(j * 64 + row) * HD_ + c * 8; off = FS_VH; }
            else               { src = Vl + (size_t)(j * 64 + row) * HD_ + c * 8; off = FS_VL; }
            cp16(smem_u32(fsm + sbase + off + row * FSPAD + c * 8), src);
        }
    };

    cp_tile(0, 0);
    CP_COMMIT(); CP_WAIT0();
    __syncthreads();

    float m0 = -1e30f, m1 = -1e30f, l0 = 0.f, l1 = 0.f;
    float acco[8][4] = {};

    for (int j = 0; j < 16; j++) {
        if (j < 15) { cp_tile((j + 1) & 1, j + 1); CP_COMMIT(); }
        const __nv_bfloat16* sb = fsm + FSTG0 + (j & 1) * FSTGS;

        float accs[8][4] = {};
        #pragma unroll
        for (int ks = 0; ks < 4; ks++) {
            uint32_t aH[4], aL[4];
            {
                int ar = wid * 16 + (lane & 15);
                int ac = ks * 16 + ((lane >> 4) << 3);
                ldsm4(aH, smem_u32(fsm + FA_H + ar * FSPAD + ac));
                ldsm4(aL, smem_u32(fsm + FA_L + ar * FSPAD + ac));
            }
            #pragma unroll
            for (int ng = 0; ng < 2; ng++) {
                uint32_t bh2[2][4], bl2[2][4];
                #pragma unroll
                for (int p = 0; p < 2; p++) {
                    int nr = ng * 32 + p * 16 + (lane & 7) + ((lane >> 4) << 3);
                    int kc = ks * 16 + (((lane >> 3) & 1) << 3);
                    ldsm4(bh2[p], smem_u32(sb + FS_BH + nr * FSPAD + kc));
                    ldsm4(bl2[p], smem_u32(sb + FS_BL + nr * FSPAD + kc));
                }
                #pragma unroll
                for (int t = 0; t < 4; t++) {
                    float* c = accs[ng * 4 + t];
                    const uint32_t* bhf = &bh2[t >> 1][(t & 1) * 2];
                    const uint32_t* blf = &bl2[t >> 1][(t & 1) * 2];
                    mma_bf16(c, aH, bhf);
                    mma_bf16(c, aH, blf);
                    mma_bf16(c, aL, bhf);
                }
            }
        }

        float tm0 = -1e30f, tm1 = -1e30f;
        #pragma unroll
        for (int t = 0; t < 8; t++) {
            tm0 = fmaxf(tm0, fmaxf(accs[t][0], accs[t][1]));
            tm1 = fmaxf(tm1, fmaxf(accs[t][2], accs[t][3]));
        }
        tm0 = fmaxf(tm0, __shfl_xor_sync(0xFFFFFFFF, tm0, 1));
        tm0 = fmaxf(tm0, __shfl_xor_sync(0xFFFFFFFF, tm0, 2));
        tm1 = fmaxf(tm1, __shfl_xor_sync(0xFFFFFFFF, tm1, 1));
        tm1 = fmaxf(tm1, __shfl_xor_sync(0xFFFFFFFF, tm1, 2));
        float mn0 = fmaxf(m0, tm0), mn1 = fmaxf(m1, tm1);
        float sc0 = ex2f(m0 - mn0), sc1 = ex2f(m1 - mn1);
        m0 = mn0; m1 = mn1;
        float rs0 = 0.f, rs1 = 0.f;
        #pragma unroll
        for (int t = 0; t < 8; t++) {
            accs[t][0] = ex2f(accs[t][0] - m0);
            accs[t][1] = ex2f(accs[t][1] - m0);
            accs[t][2] = ex2f(accs[t][2] - m1);
            accs[t][3] = ex2f(accs[t][3] - m1);
            rs0 += accs[t][0] + accs[t][1];
            rs1 += accs[t][2] + accs[t][3];
        }
        rs0 += __shfl_xor_sync(0xFFFFFFFF, rs0, 1);
        rs0 += __shfl_xor_sync(0xFFFFFFFF, rs0, 2);
        rs1 += __shfl_xor_sync(0xFFFFFFFF, rs1, 1);
        rs1 += __shfl_xor_sync(0xFFFFFFFF, rs1, 2);
        l0 = l0 * sc0 + rs0;
        l1 = l1 * sc1 + rs1;
        #pragma unroll
        for (int o = 0; o < 8; o++) {
            acco[o][0] *= sc0; acco[o][1] *= sc0;
            acco[o][2] *= sc1; acco[o][3] *= sc1;
        }

        #pragma unroll
        for (int kt = 0; kt < 4; kt++) {
            uint32_t pH[4];
            pH[0] = pack_h2(accs[2*kt][0],   accs[2*kt][1]);
            pH[1] = pack_h2(accs[2*kt][2],   accs[2*kt][3]);
            pH[2] = pack_h2(accs[2*kt+1][0], accs[2*kt+1][1]);
            pH[3] = pack_h2(accs[2*kt+1][2], accs[2*kt+1][3]);
            #pragma unroll
            for (int vg = 0; vg < 2; vg++) {
                uint32_t vh2[2][4], vl2[2][4];
                #pragma unroll
                for (int q = 0; q < 2; q++) {
                    int vr = kt * 16 + (lane & 15);
                    int vc = vg * 32 + q * 16 + ((lane >> 4) << 3);
                    ldsm4t(vh2[q], smem_u32(sb + FS_VH + vr * FSPAD + vc));
                    ldsm4t(vl2[q], smem_u32(sb + FS_VL + vr * FSPAD + vc));
                }
                #pragma unroll
                for (int t = 0; t < 4; t++) {
                    float* o = acco[vg * 4 + t];
                    mma_f16(o, pH, &vh2[t >> 1][(t & 1) * 2]);
                    mma_f16(o, pH, &vl2[t >> 1][(t & 1) * 2]);
                }
            }
        }

        if (j < 15) CP_WAIT0();
        __syncthreads();
    }

    float inv0 = 1.f / l0, inv1 = 1.f / l1;
    float imu = 1.f / mu;
    float lm = LAMBD_ * mu;
    int row0 = i0 + wid * 16 + (lane >> 2);
    #pragma unroll
    for (int o = 0; o < 8; o++) {
        int col = o * 8 + (lane & 3) * 2;
        #pragma unroll
        for (int half = 0; half < 2; half++) {
            size_t ia = hbase + (size_t)(row0 + half * 8) * HD_ + col;
            float la = acco[o][half * 2]     * (half ? inv1 : inv0);
            float lb = acco[o][half * 2 + 1] * (half ? inv1 : inv0);
            float2 kv = *(const float2*)&g_k[ia];
            float2 yv = *(const float2*)&g_y[ia];
            float2 sv = *(const float2*)&g_s[ia];
            float yn0 = yv.x + mu * (kv.x - la - sv.x);
            float yn1 = yv.y + mu * (kv.y - lb - sv.y);
            float ym0 = yn0 * imu, ym1 = yn1 * imu;
            float t0 = kv.x - la + ym0, t1 = kv.y - lb + ym1;
            float sn0 = (t0 >= lm) ? (t0 - lm) : ((t0 <= -lm) ? (t0 + lm) : 0.f);
            float sn1 = (t1 >= lm) ? (t1 - lm) : ((t1 <= -lm) ? (t1 + lm) : 0.f);
            *(float2*)&g_y[ia] = make_float2(yn0, yn1);
            *(float2*)&g_s[ia] = make_float2(sn0, sn1);
            float k20 = (kv.x - sn0 - ym0) * QSC_;
            float k21 = (kv.y - sn1 - ym1) * QSC_;
            uint32_t h2, l2;
            split2(k20, k21, h2, l2);
            *(uint32_t*)&k2h_dst[ia] = h2;
            *(uint32_t*)&k2l_dst[ia] = l2;
        }
    }
}

// =================== final iteration: 2-pass flash, materializes attn + obnc ===================
__global__ void __launch_bounds__(256, 2) final_flash_kernel(
    float* __restrict__ attn,
    const __nv_bfloat16* __restrict__ k2h_src, const __nv_bfloat16* __restrict__ k2l_src)
{
    extern __shared__ __nv_bfloat16 fsm[];
    const int bh = blockIdx.y;
    const int i0 = blockIdx.x * 128;
    const int tid = threadIdx.x, wid = tid >> 5, lane = tid & 31;

    const size_t hbase = (size_t)bh * N_ * HD_;
    const __nv_bfloat16* Gh = k2h_src + hbase;
    const __nv_bfloat16* Gl = k2l_src + hbase;
    const __half* Vh = g_vh + hbase;
    const __half* Vl = g_vl + hbase;

    #pragma unroll
    for (int i = 0; i < 8; i++) {
        int idx = tid + i * 256;
        int arr = idx >> 10, rem = idx & 1023, row = rem >> 3, c = rem & 7;
        const __nv_bfloat16* src = (arr ? Gl : Gh) + (size_t)(i0 + row) * HD_ + c * 8;
        *(uint4*)(fsm + (arr ? FA_L : FA_H) + row * FSPAD + c * 8) = *(const uint4*)src;
    }

    auto cp_tile = [&](int stage, int j, bool withV) {
        int sbase = FSTG0 + stage * FSTGS;
        #pragma unroll
        for (int i = 0; i < 8; i++) {
            int idx = tid + i * 256;
            int arr = idx >> 9, rem = idx & 511, row = rem >> 3, c = rem & 7;
            if (!withV && arr >= 2) continue;
            const void* src;
            int off;
            if      (arr == 0) { src = Gh + (size_t)(j * 64 + row) * HD_ + c * 8; off = FS_BH; }
            else if (arr == 1) { src = Gl + (size_t)(j * 64 + row) * HD_ + c * 8; off = FS_BL; }
            else if (arr == 2) { src = Vh + (size_t)(j * 64 + row) * HD_ + c * 8; off = FS_VH; }
            else               { src = Vl + (size_t)(j * 64 + row) * HD_ + c * 8; off = FS_VL; }
            cp16(smem_u32(fsm + sbase + off + row * FSPAD + c * 8), src);
        }
    };

    auto compute_S = [&](const __nv_bfloat16* sb, float accs[8][4]) {
        #pragma unroll
        for (int ks = 0; ks < 4; ks++) {
            uint32_t aH[4], aL[4];
            {
                int ar = wid * 16 + (lane & 15);
                int ac = ks * 16 + ((lane >> 4) << 3);
                ldsm4(aH, smem_u32(fsm + FA_H + ar * FSPAD + ac));
                ldsm4(aL, smem_u32(fsm + FA_L + ar * FSPAD + ac));
            }
            #pragma unroll
            for (int ng = 0; ng < 2; ng++) {
                uint32_t bh2[2][4], bl2[2][4];
                #pragma unroll
                for (int p = 0; p < 2; p++) {
                    int nr = ng * 32 + p * 16 + (lane & 7) + ((lane >> 4) << 3);
                    int kc = ks * 16 + (((lane >> 3) & 1) << 3);
                    ldsm4(bh2[p], smem_u32(sb + FS_BH + nr * FSPAD + kc));
                    ldsm4(bl2[p], smem_u32(sb + FS_BL + nr * FSPAD + kc));
                }
                #pragma unroll
                for (int t = 0; t < 4; t++) {
                    float* c = accs[ng * 4 + t];
                    const uint32_t* bhf = &bh2[t >> 1][(t & 1) * 2];
                    const uint32_t* blf = &bl2[t >> 1][(t & 1) * 2];
                    mma_bf16(c, aH, bhf);
                    mma_bf16(c, aH, blf);
                    mma_bf16(c, aL, bhf);
                }
            }
        }
    };

    // ---------- PASS A: row stats ----------
    cp_tile(0, 0, false);
    CP_COMMIT(); CP_WAIT0();
    __syncthreads();

    float m0 = -1e30f, m1 = -1e30f, l0 = 0.f, l1 = 0.f;
    for (int j = 0; j < 16; j++) {
        if (j < 15) { cp_tile((j + 1) & 1, j + 1, false); CP_COMMIT(); }
        const __nv_bfloat16* sb = fsm + FSTG0 + (j & 1) * FSTGS;
        float accs[8][4] = {};
        compute_S(sb, accs);

        float tm0 = -1e30f, tm1 = -1e30f;
        #pragma unroll
        for (int t = 0; t < 8; t++) {
            tm0 = fmaxf(tm0, fmaxf(accs[t][0], accs[t][1]));
            tm1 = fmaxf(tm1, fmaxf(accs[t][2], accs[t][3]));
        }
        tm0 = fmaxf(tm0, __shfl_xor_sync(0xFFFFFFFF, tm0, 1));
        tm0 = fmaxf(tm0, __shfl_xor_sync(0xFFFFFFFF, tm0, 2));
        tm1 = fmaxf(tm1, __shfl_xor_sync(0xFFFFFFFF, tm1, 1));
        tm1 = fmaxf(tm1, __shfl_xor_sync(0xFFFFFFFF, tm1, 2));
        float mn0 = fmaxf(m0, tm0), mn1 = fmaxf(m1, tm1);
        float sc0 = ex2f(m0 - mn0), sc1 = ex2f(m1 - mn1);
        m0 = mn0; m1 = mn1;
        float rs0 = 0.f, rs1 = 0.f;
        #pragma unroll
        for (int t = 0; t < 8; t++) {
            rs0 += ex2f(accs[t][0] - m0) + ex2f(accs[t][1] - m0);
            rs1 += ex2f(accs[t][2] - m1) + ex2f(accs[t][3] - m1);
        }
        rs0 += __shfl_xor_sync(0xFFFFFFFF, rs0, 1);
        rs0 += __shfl_xor_sync(0xFFFFFFFF, rs0, 2);
        rs1 += __shfl_xor_sync(0xFFFFFFFF, rs1, 1);
        rs1 += __shfl_xor_sync(0xFFFFFFFF, rs1, 2);
        l0 = l0 * sc0 + rs0;
        l1 = l1 * sc1 + rs1;
        if (j < 15) CP_WAIT0();
        __syncthreads();
    }
    float inv0 = 1.f / l0, inv1 = 1.f / l1;

    // ---------- PASS B: normalized P -> attn, PV ----------
    cp_tile(0, 0, true);
    CP_COMMIT(); CP_WAIT0();
    __syncthreads();

    float* Sp = attn + (size_t)bh * N_ * N_;
    const int prow = i0 + wid * 16 + (lane >> 2);
    float acco[8][4] = {};

    for (int j = 0; j < 16; j++) {
        if (j < 15) { cp_tile((j + 1) & 1, j + 1, true); CP_COMMIT(); }
        const __nv_bfloat16* sb = fsm + FSTG0 + (j & 1) * FSTGS;
        float accs[8][4] = {};
        compute_S(sb, accs);

        #pragma unroll
        for (int t = 0; t < 8; t++) {
            accs[t][0] = ex2f(accs[t][0] - m0) * inv0;
            accs[t][1] = ex2f(accs[t][1] - m0) * inv0;
            accs[t][2] = ex2f(accs[t][2] - m1) * inv1;
            accs[t][3] = ex2f(accs[t][3] - m1) * inv1;
            int col = j * 64 + (t >> 2) * 32 + (t & 3) * 8 + (lane & 3) * 2;
            *(float2*)&Sp[(size_t)prow * N_ + col]       = make_float2(accs[t][0], accs[t][1]);
            *(float2*)&Sp[(size_t)(prow + 8) * N_ + col] = make_float2(accs[t][2], accs[t][3]);
        }

        #pragma unroll
        for (int kt = 0; kt < 4; kt++) {
            uint32_t pH[4];
            pH[0] = pack_h2(accs[2*kt][0],   accs[2*kt][1]);
            pH[1] = pack_h2(accs[2*kt][2],   accs[2*kt][3]);
            pH[2] = pack_h2(accs[2*kt+1][0], accs[2*kt+1][1]);
            pH[3] = pack_h2(accs[2*kt+1][2], accs[2*kt+1][3]);
            #pragma unroll
            for (int vg = 0; vg < 2; vg++) {
                uint32_t vh2[2][4], vl2[2][4];
                #pragma unroll
                for (int q = 0; q < 2; q++) {
                    int vr = kt * 16 + (lane & 15);
                    int vc = vg * 32 + q * 16 + ((lane >> 4) << 3);
                    ldsm4t(vh2[q], smem_u32(sb + FS_VH + vr * FSPAD + vc));
                    ldsm4t(vl2[q], smem_u32(sb + FS_VL + vr * FSPAD + vc));
                }
                #pragma unroll
                for (int t = 0; t < 4; t++) {
                    float* o = acco[vg * 4 + t];
                    mma_f16(o, pH, &vh2[t >> 1][(t & 1) * 2]);
                    mma_f16(o, pH, &vl2[t >> 1][(t & 1) * 2]);
                }
            }
        }

        if (j < 15) CP_WAIT0();
        __syncthreads();
    }

    int b = bh / H_, h = bh % H_;
    #pragma unroll
    for (int o = 0; o < 8; o++) {
        int col = o * 8 + (lane & 3) * 2;
        uint32_t h0, l0b, h1, l1b;
        split2(acco[o][0], acco[o][1], h0, l0b);
        split2(acco[o][2], acco[o][3], h1, l1b);
        size_t idx0 = ((size_t)(b * N_ + prow)) * C_ + h * HD_ + col;
        size_t idx1 = ((size_t)(b * N_ + prow + 8)) * C_ + h * HD_ + col;
        *(uint32_t*)&g_och[idx0] = h0;
        *(uint32_t*)&g_ocl[idx0] = l0b;
        *(uint32_t*)&g_och[idx1] = h1;
        *(uint32_t*)&g_ocl[idx1] = l1b;
    }
}

// =================== bf16x3 HMMA GEMM: qkv and proj ===================
// CTA 128(M) x 64(N), 8 warps as 4x2 (warp tile 32x32), K chunk 64, double buffer.
// Stage: A 2x128x72 = 18432 elems, B 2x64x72 = 9216 elems -> 27648 elems = 55296 B.
// 2 stages = 110,592 B -> 2 CTAs/SM.
#define QA_H 0
#define QA_L 9216
#define QB_H 18432
#define QB_L 23040
#define QSTG 27648
#define WPAD 72

template<int NCOLS, int KDIM>
__device__ __forceinline__ void mma_gemm_main(
    const __nv_bfloat16* __restrict__ Ah, const __nv_bfloat16* __restrict__ Al,
    const __nv_bfloat16* __restrict__ Wh, const __nv_bfloat16* __restrict__ Wl,
    __nv_bfloat16* sm, int by, int bx, float acc[2][4][4])
{
    const int tid = threadIdx.x, wid = tid >> 5, lane = tid & 31;
    const int wm = wid & 3, wn = wid >> 2;

    auto cp_stage = [&](int stage, int k0) {
        int sb = stage * QSTG;
        #pragma unroll
        for (int i = 0; i < 8; i++) {     // A: 2 arrays x 128 rows x 8 chunks = 2048 / 256
            int idx = tid + i * 256;
            int arr = idx >> 10, rem = idx & 1023, row = rem >> 3, c = rem & 7;
            const __nv_bfloat16* src = (arr ? Al : Ah) + (size_t)(by + row) * KDIM + k0 + c * 8;
            cp16(smem_u32(sm + sb + (arr ? QA_L : QA_H) + row * FSPAD + c * 8), src);
        }
        #pragma unroll
        for (int i = 0; i < 4; i++) {     // B: 2 arrays x 64 rows x 8 chunks = 1024 / 256
            int idx = tid + i * 256;
            int arr = idx >> 9, rem = idx & 511, row = rem >> 3, c = rem & 7;
            const __nv_bfloat16* src = (arr ? Wl : Wh) + (size_t)(k0 + row) * NCOLS + bx + c * 8;
            cp16(smem_u32(sm + sb + (arr ? QB_L : QB_H) + row * WPAD + c * 8), src);
        }
    };

    cp_stage(0, 0);
    CP_COMMIT(); CP_WAIT0();
    __syncthreads();

    const int NCHUNK = KDIM / 64;
    for (int ch = 0; ch < NCHUNK; ch++) {
        if (ch < NCHUNK - 1) { cp_stage((ch + 1) & 1, (ch + 1) * 64); CP_COMMIT(); }
        __nv_bfloat16* sb = sm + (ch & 1) * QSTG;
        #pragma unroll
        for (int ks = 0; ks < 4; ks++) {
            uint32_t aH[2][4], aL[2][4];
            #pragma unroll
            for (int mt = 0; mt < 2; mt++) {
                int ar = wm * 32 + mt * 16 + (lane & 15);
                int ac = ks * 16 + ((lane >> 4) << 3);
                ldsm4(aH[mt], smem_u32(sb + QA_H + ar * FSPAD + ac));
                ldsm4(aL[mt], smem_u32(sb + QA_L + ar * FSPAD + ac));
            }
            uint32_t bh2[2][4], bl2[2][4];
            #pragma unroll
            for (int q = 0; q < 2; q++) {
                int vr = ks * 16 + (lane & 15);
                int vc = wn * 32 + q * 16 + ((lane >> 4) << 3);
                ldsm4t(bh2[q], smem_u32(sb + QB_H + vr * WPAD + vc));
                ldsm4t(bl2[q], smem_u32(sb + QB_L + vr * WPAD + vc));
            }
            #pragma unroll
            for (int mt = 0; mt < 2; mt++)
                #pragma unroll
                for (int nt = 0; nt < 4; nt++) {
                    const uint32_t* bhf = &bh2[nt >> 1][(nt & 1) * 2];
                    const uint32_t* blf = &bl2[nt >> 1][(nt & 1) * 2];
                    mma_bf16(acc[mt][nt], aH[mt], bhf);
                    mma_bf16(acc[mt][nt], aH[mt], blf);
                    mma_bf16(acc[mt][nt], aL[mt], bhf);
                }
        }
        if (ch < NCHUNK - 1) CP_WAIT0();
        __syncthreads();
    }
}

__global__ void __launch_bounds__(256, 2) qkv_mma_kernel(const float* __restrict__ bias) {
    extern __shared__ __nv_bfloat16 qsm[];
    const int bx = blockIdx.x * 64;
    const int by = blockIdx.y * 128;
    const int wid = threadIdx.x >> 5, lane = threadIdx.x & 31;
    const int wm = wid & 3, wn = wid >> 2;

    float acc[2][4][4] = {};
    mma_gemm_main<TWO_C_, C_>(g_xh, g_xl, g_wqh, g_wql, qsm, by, bx, acc);

    #pragma unroll
    for (int mt = 0; mt < 2; mt++) {
        int r0 = by + wm * 32 + mt * 16 + (lane >> 2);
        #pragma unroll
        for (int nt = 0; nt < 4; nt++) {
            int col = bx + wn * 32 + nt * 8 + (lane & 3) * 2;
            float b0 = bias[col], b1 = bias[col + 1];
            #pragma unroll
            for (int half = 0; half < 2; half++) {
                int r = r0 + half * 8;
                float v0 = acc[mt][nt][half * 2]     + b0;
                float v1 = acc[mt][nt][half * 2 + 1] + b1;
                int bb = r >> 10, n = r & 1023;
                int which = col >= C_;
                int cc = col - which * C_;
                int hh = cc / HD_, hd = cc % HD_;
                size_t idx = (((size_t)(bb * H_ + hh)) * N_ + n) * HD_ + hd;
                if (!which) {
                    *(float2*)&g_k[idx] = make_float2(v0, v1);
                } else {
                    uint32_t h2, l2;
                    split2h(v0, v1, h2, l2);
                    *(uint32_t*)&g_vh[idx] = h2;
                    *(uint32_t*)&g_vl[idx] = l2;
                }
            }
        }
    }
}

__global__ void __launch_bounds__(256, 2) proj_mma_kernel(const float* __restrict__ bias,
                                                          float* __restrict__ out) {
    extern __shared__ __nv_bfloat16 qsm[];
    const int bx = blockIdx.x * 64;
    const int by = blockIdx.y * 128;
    const int wid = threadIdx.x >> 5, lane = threadIdx.x & 31;
    const int wm = wid & 3, wn = wid >> 2;

    float acc[2][4][4] = {};
    mma_gemm_main<C_, C_>(g_och, g_ocl, g_wph, g_wpl, qsm, by, bx, acc);

    #pragma unroll
    for (int mt = 0; mt < 2; mt++) {
        int r0 = by + wm * 32 + mt * 16 + (lane >> 2);
        #pragma unroll
        for (int nt = 0; nt < 4; nt++) {
            int col = bx + wn * 32 + nt * 8 + (lane & 3) * 2;
            float b0 = bias[col], b1 = bias[col + 1];
            *(float2*)&out[(size_t)r0 * C_ + col] =
                make_float2(acc[mt][nt][0] + b0, acc[mt][nt][1] + b1);
            *(float2*)&out[(size_t)(r0 + 8) * C_ + col] =
                make_float2(acc[mt][nt][2] + b0, acc[mt][nt][3] + b1);
        }
    }
}

// ---------------- launch ----------------
extern "C" void kernel_launch(void* const* d_in, const int* in_sizes, int n_in,
                              void* d_out, int out_size) {
    const float* x     = (const float*)d_in[0];
    const float* Wqkv  = (const float*)d_in[1];
    const float* bqkv  = (const float*)d_in[2];
    const float* Wproj = (const float*)d_in[3];
    const float* bproj = (const float*)d_in[4];
    float* out = (float*)d_out;

    float* attn;
    if ((size_t)out_size >= OUT_ELEMS + ATTN_ELEMS) {
        attn = out + OUT_ELEMS;
    } else {
        void* p = nullptr;
        cudaGetSymbolAddress(&p, g_attn_fallback);
        attn = (float*)p;
    }

    const int FLASH_SMEM = (FSTG0 + 2 * FSTGS) * 2;   // 110,592 B
    const int GEMM_SMEM  = 2 * QSTG * 2;              // 110,592 B
    cudaFuncSetAttribute(flash_iter_kernel, cudaFuncAttributeMaxDynamicSharedMemorySize, FLASH_SMEM);
    cudaFuncSetAttribute(final_flash_kernel, cudaFuncAttributeMaxDynamicSharedMemorySize, FLASH_SMEM);
    cudaFuncSetAttribute(qkv_mma_kernel, cudaFuncAttributeMaxDynamicSharedMemorySize, GEMM_SMEM);
    cudaFuncSetAttribute(proj_mma_kernel, cudaFuncAttributeMaxDynamicSharedMemorySize, GEMM_SMEM);

    __nv_bfloat16 *xh, *xl, *wqh, *wql, *wph, *wpl;
    __nv_bfloat16 *k2h_a, *k2l_a, *k2h_b, *k2l_b;
    { void* p; cudaGetSymbolAddress(&p, g_xh);  xh  = (__nv_bfloat16*)p; }
    { void* p; cudaGetSymbolAddress(&p, g_xl);  xl  = (__nv_bfloat16*)p; }
    { void* p; cudaGetSymbolAddress(&p, g_wqh); wqh = (__nv_bfloat16*)p; }
    { void* p; cudaGetSymbolAddress(&p, g_wql); wql = (__nv_bfloat16*)p; }
    { void* p; cudaGetSymbolAddress(&p, g_wph); wph = (__nv_bfloat16*)p; }
    { void* p; cudaGetSymbolAddress(&p, g_wpl); wpl = (__nv_bfloat16*)p; }
    { void* p; cudaGetSymbolAddress(&p, g_k2h_a); k2h_a = (__nv_bfloat16*)p; }
    { void* p; cudaGetSymbolAddress(&p, g_k2l_a); k2l_a = (__nv_bfloat16*)p; }
    { void* p; cudaGetSymbolAddress(&p, g_k2h_b); k2h_b = (__nv_bfloat16*)p; }
    { void* p; cudaGetSymbolAddress(&p, g_k2l_b); k2l_b = (__nv_bfloat16*)p; }

    const int eblocks = (int)((KV_ELEMS + 255) / 256);

    split_kernel<<<(6291456 + 255) / 256, 256>>>(x, xh, xl, 6291456);
    split_kernel<<<(1179648 + 255) / 256, 256>>>(Wqkv, wqh, wql, 1179648);
    split_kernel<<<(589824 + 255) / 256, 256>>>(Wproj, wph, wpl, 589824);

    qkv_mma_kernel<<<dim3(TWO_C_ / 64, M_ROWS / 128), 256, GEMM_SMEM>>>(bqkv);
    mu_kernel<<<BH_, 256>>>();
    k2_init_kernel<<<eblocks, 256>>>();   // writes buffer A

    __nv_bfloat16* bufs_h[2] = {k2h_a, k2h_b};
    __nv_bfloat16* bufs_l[2] = {k2l_a, k2l_b};
    for (int it = 0; it < 5; ++it) {
        int s = it & 1, d = (it + 1) & 1;
        flash_iter_kernel<<<dim3(N_ / 128, BH_), 256, FLASH_SMEM>>>(
            bufs_h[s], bufs_l[s], bufs_h[d], bufs_l[d]);
    }
    final_flash_kernel<<<dim3(N_ / 128, BH_), 256, FLASH_SMEM>>>(attn, bufs_h[1], bufs_l[1]);

    proj_mma_kernel<<<dim3(C_ / 64, M_ROWS / 128), 256, GEMM_SMEM>>>(bproj, out);
}

// round 11
// speedup vs baseline: 6.0054x; 1.1191x over previous
#include <cuda_runtime.h>
#include <cuda_bf16.h>
#include <cuda_fp16.h>
#include <math.h>
#include <stdint.h>

#define B_   8
#define N_   1024
#define C_   768
#define H_   12
#define HD_  64
#define BH_  (B_*H_)
#define TWO_C_ (2*C_)
#define M_ROWS (B_*N_)

static const size_t KV_ELEMS   = (size_t)BH_ * N_ * HD_;
static const size_t OUT_ELEMS  = (size_t)B_ * N_ * C_;
static const size_t ATTN_ELEMS = (size_t)BH_ * N_ * N_;

#define LAMBD_ 4.0f
// logits carried in log2 domain: S2 = (k2*QSC)·(k2*QSC)^T where QSC^2 = 0.125*log2(e)
#define QSC_ 0.42466089f

// ---------------- device scratch ----------------
__device__ float g_k [6291456];
__device__ float g_y [6291456];
__device__ float g_s [6291456];
// ping-pong k2 buffers (fixes cross-CTA iteration race)
__device__ __nv_bfloat16 g_k2h_a[6291456];
__device__ __nv_bfloat16 g_k2l_a[6291456];
__device__ __nv_bfloat16 g_k2h_b[6291456];
__device__ __nv_bfloat16 g_k2l_b[6291456];
__device__ __half g_vh [6291456];
__device__ __half g_vl [6291456];
__device__ __nv_bfloat16 g_xh [6291456];
__device__ __nv_bfloat16 g_xl [6291456];
__device__ __nv_bfloat16 g_wqh[1179648];
__device__ __nv_bfloat16 g_wql[1179648];
__device__ __nv_bfloat16 g_wph[589824];
__device__ __nv_bfloat16 g_wpl[589824];
__device__ __nv_bfloat16 g_och[6291456];
__device__ __nv_bfloat16 g_ocl[6291456];
__device__ float g_mu[96];
__device__ float g_mu_part[768];
__device__ float g_attn_fallback[100663296];

// ---------------- helpers ----------------
__device__ __forceinline__ uint32_t smem_u32(const void* p) {
    uint32_t a;
    asm("{ .reg .u64 t; cvta.to.shared.u64 t, %1; cvt.u32.u64 %0, t; }" : "=r"(a) : "l"(p));
    return a;
}
__device__ __forceinline__ void ldsm4(uint32_t r[4], uint32_t addr) {
    asm volatile("ldmatrix.sync.aligned.m8n8.x4.shared.b16 {%0,%1,%2,%3}, [%4];"
        : "=r"(r[0]), "=r"(r[1]), "=r"(r[2]), "=r"(r[3]) : "r"(addr));
}
__device__ __forceinline__ void ldsm4t(uint32_t r[4], uint32_t addr) {
    asm volatile("ldmatrix.sync.aligned.m8n8.x4.trans.shared.b16 {%0,%1,%2,%3}, [%4];"
        : "=r"(r[0]), "=r"(r[1]), "=r"(r[2]), "=r"(r[3]) : "r"(addr));
}
__device__ __forceinline__ void mma_bf16(float c[4], const uint32_t a[4], const uint32_t* b) {
    asm volatile("mma.sync.aligned.m16n8k16.row.col.f32.bf16.bf16.f32 "
        "{%0,%1,%2,%3}, {%4,%5,%6,%7}, {%8,%9}, {%0,%1,%2,%3};"
        : "+f"(c[0]), "+f"(c[1]), "+f"(c[2]), "+f"(c[3])
        : "r"(a[0]), "r"(a[1]), "r"(a[2]), "r"(a[3]), "r"(b[0]), "r"(b[1]));
}
__device__ __forceinline__ void mma_f16(float c[4], const uint32_t a[4], const uint32_t* b) {
    asm volatile("mma.sync.aligned.m16n8k16.row.col.f32.f16.f16.f32 "
        "{%0,%1,%2,%3}, {%4,%5,%6,%7}, {%8,%9}, {%0,%1,%2,%3};"
        : "+f"(c[0]), "+f"(c[1]), "+f"(c[2]), "+f"(c[3])
        : "r"(a[0]), "r"(a[1]), "r"(a[2]), "r"(a[3]), "r"(b[0]), "r"(b[1]));
}
__device__ __forceinline__ void split2(float x, float y, uint32_t& hi, uint32_t& lo) {
    __nv_bfloat16 hx = __float2bfloat16(x), hy = __float2bfloat16(y);
    __nv_bfloat162 h2; h2.x = hx; h2.y = hy;
    __nv_bfloat162 l2;
    l2.x = __float2bfloat16(x - __bfloat162float(hx));
    l2.y = __float2bfloat16(y - __bfloat162float(hy));
    hi = *reinterpret_cast<uint32_t*>(&h2);
    lo = *reinterpret_cast<uint32_t*>(&l2);
}
__device__ __forceinline__ void split2h(float x, float y, uint32_t& hi, uint32_t& lo) {
    __half2 h = __floats2half2_rn(x, y);
    __half2 l = __floats2half2_rn(x - __half2float(h.x), y - __half2float(h.y));
    hi = *reinterpret_cast<uint32_t*>(&h);
    lo = *reinterpret_cast<uint32_t*>(&l);
}
__device__ __forceinline__ uint32_t pack_h2(float x, float y) {
    __half2 h = __floats2half2_rn(x, y);
    return *reinterpret_cast<uint32_t*>(&h);
}
__device__ __forceinline__ float ex2f(float x) {
    float y; asm("ex2.approx.f32 %0, %1;" : "=f"(y) : "f"(x)); return y;
}
__device__ __forceinline__ void cp16(uint32_t dst, const void* src) {
    asm volatile("cp.async.cg.shared.global [%0], [%1], 16;" :: "r"(dst), "l"(src));
}
#define CP_COMMIT() asm volatile("cp.async.commit_group;" ::: "memory")
#define CP_WAIT0()  asm volatile("cp.async.wait_group 0;" ::: "memory")

// ---------------- elementwise ----------------
__global__ void split_kernel(const float* __restrict__ src, __nv_bfloat16* __restrict__ h,
                             __nv_bfloat16* __restrict__ l, int n) {
    int i = blockIdx.x * 256 + threadIdx.x;
    if (i >= n) return;
    float v = src[i];
    __nv_bfloat16 hi = __float2bfloat16(v);
    h[i] = hi;
    l[i] = __float2bfloat16(v - __bfloat162float(hi));
}

__global__ void k2_init_kernel() {
    size_t i = (size_t)blockIdx.x * 256 + threadIdx.x;
    if (i >= KV_ELEMS) return;
    int bh = (int)(i / ((size_t)N_ * HD_));
    float mu = g_mu[bh];
    float kk = g_k[i];
    float lm = LAMBD_ * mu;
    float s  = (kk >= lm) ? (kk - lm) : ((kk <= -lm) ? (kk + lm) : 0.f);
    g_s[i] = s;
    g_y[i] = 0.f;
    float k2 = (kk - s) * QSC_;
    __nv_bfloat16 hi = __float2bfloat16(k2);
    g_k2h_a[i] = hi;
    g_k2l_a[i] = __float2bfloat16(k2 - __bfloat162float(hi));
}

// mu: 8 partial blocks per head (deterministic fixed slots) + finalize
__global__ void mu_part_kernel() {
    __shared__ float red[256];
    int bh = blockIdx.x >> 3;
    int sl = blockIdx.x & 7;
    const float* p = g_k + (size_t)bh * N_ * HD_ + sl * 8192;
    float s = 0.f;
    #pragma unroll
    for (int i = 0; i < 32; i++) s += fabsf(p[threadIdx.x + i * 256]);
    red[threadIdx.x] = s;
    __syncthreads();
    for (int st = 128; st > 0; st >>= 1) {
        if (threadIdx.x < st) red[threadIdx.x] += red[threadIdx.x + st];
        __syncthreads();
    }
    if (threadIdx.x == 0) g_mu_part[blockIdx.x] = red[0];
}
__global__ void mu_fin_kernel() {
    int bh = threadIdx.x;
    if (bh >= BH_) return;
    float s = 0.f;
    #pragma unroll
    for (int i = 0; i < 8; i++) s += g_mu_part[bh * 8 + i];
    g_mu[bh] = ((float)N_ * (float)C_ / 4.0f) / s;
}

// =================== flash iteration (iters 0..4) + fused y/s/k2 update ===================
// KV tiles of 64 rows, stage = {Bh, Bl, Vh} (single-product PV) -> smem 92.2KB -> 2 CTAs/SM.
#define FSPAD 72
#define FA_H  0
#define FA_L  9216
#define FSTG0 18432
#define FSTGS_I 13824    // iter stage: 3 arrays x 64 x 72
#define FSTGS_F 18432    // final stage: 4 arrays x 64 x 72
#define FS_BH 0
#define FS_BL 4608
#define FS_VH 9216
#define FS_VL 13824

__global__ void __launch_bounds__(256, 2) flash_iter_kernel(
    const __nv_bfloat16* __restrict__ k2h_src, const __nv_bfloat16* __restrict__ k2l_src,
    __nv_bfloat16* __restrict__ k2h_dst, __nv_bfloat16* __restrict__ k2l_dst)
{
    extern __shared__ __nv_bfloat16 fsm[];
    const int bh = blockIdx.y;
    const int i0 = blockIdx.x * 128;
    const int tid = threadIdx.x, wid = tid >> 5, lane = tid & 31;

    const size_t hbase = (size_t)bh * N_ * HD_;
    const __nv_bfloat16* Gh = k2h_src + hbase;
    const __nv_bfloat16* Gl = k2l_src + hbase;
    const __half* Vh = g_vh + hbase;
    const float mu = g_mu[bh];

    #pragma unroll
    for (int i = 0; i < 8; i++) {
        int idx = tid + i * 256;
        int arr = idx >> 10, rem = idx & 1023, row = rem >> 3, c = rem & 7;
        const __nv_bfloat16* src = (arr ? Gl : Gh) + (size_t)(i0 + row) * HD_ + c * 8;
        *(uint4*)(fsm + (arr ? FA_L : FA_H) + row * FSPAD + c * 8) = *(const uint4*)src;
    }

    auto cp_tile = [&](int stage, int j) {
        int sbase = FSTG0 + stage * FSTGS_I;
        #pragma unroll
        for (int i = 0; i < 6; i++) {
            int idx = tid + i * 256;           // 0..1535: 3 arrays x 64 rows x 8 chunks
            int arr = idx >> 9, rem = idx & 511, row = rem >> 3, c = rem & 7;
            const void* src;
            int off;
            if      (arr == 0) { src = Gh + (size_t)(j * 64 + row) * HD_ + c * 8; off = FS_BH; }
            else if (arr == 1) { src = Gl + (size_t)(j * 64 + row) * HD_ + c * 8; off = FS_BL; }
            else               { src = Vh + (size_t)(j * 64 + row) * HD_ + c * 8; off = FS_VH; }
            cp16(smem_u32(fsm + sbase + off + row * FSPAD + c * 8), src);
        }
    };

    cp_tile(0, 0);
    CP_COMMIT(); CP_WAIT0();
    __syncthreads();

    float m0 = -1e30f, m1 = -1e30f, l0 = 0.f, l1 = 0.f;
    float acco[8][4] = {};

    for (int j = 0; j < 16; j++) {
        if (j < 15) { cp_tile((j + 1) & 1, j + 1); CP_COMMIT(); }
        const __nv_bfloat16* sb = fsm + FSTG0 + (j & 1) * FSTGS_I;

        float accs[8][4] = {};
        #pragma unroll
        for (int ks = 0; ks < 4; ks++) {
            uint32_t aH[4], aL[4];
            {
                int ar = wid * 16 + (lane & 15);
                int ac = ks * 16 + ((lane >> 4) << 3);
                ldsm4(aH, smem_u32(fsm + FA_H + ar * FSPAD + ac));
                ldsm4(aL, smem_u32(fsm + FA_L + ar * FSPAD + ac));
            }
            #pragma unroll
            for (int ng = 0; ng < 2; ng++) {
                uint32_t bh2[2][4], bl2[2][4];
                #pragma unroll
                for (int p = 0; p < 2; p++) {
                    int nr = ng * 32 + p * 16 + (lane & 7) + ((lane >> 4) << 3);
                    int kc = ks * 16 + (((lane >> 3) & 1) << 3);
                    ldsm4(bh2[p], smem_u32(sb + FS_BH + nr * FSPAD + kc));
                    ldsm4(bl2[p], smem_u32(sb + FS_BL + nr * FSPAD + kc));
                }
                #pragma unroll
                for (int t = 0; t < 4; t++) {
                    float* c = accs[ng * 4 + t];
                    const uint32_t* bhf = &bh2[t >> 1][(t & 1) * 2];
                    const uint32_t* blf = &bl2[t >> 1][(t & 1) * 2];
                    mma_bf16(c, aH, bhf);
                    mma_bf16(c, aH, blf);
                    mma_bf16(c, aL, bhf);
                }
            }
        }

        float tm0 = -1e30f, tm1 = -1e30f;
        #pragma unroll
        for (int t = 0; t < 8; t++) {
            tm0 = fmaxf(tm0, fmaxf(accs[t][0], accs[t][1]));
            tm1 = fmaxf(tm1, fmaxf(accs[t][2], accs[t][3]));
        }
        tm0 = fmaxf(tm0, __shfl_xor_sync(0xFFFFFFFF, tm0, 1));
        tm0 = fmaxf(tm0, __shfl_xor_sync(0xFFFFFFFF, tm0, 2));
        tm1 = fmaxf(tm1, __shfl_xor_sync(0xFFFFFFFF, tm1, 1));
        tm1 = fmaxf(tm1, __shfl_xor_sync(0xFFFFFFFF, tm1, 2));
        float mn0 = fmaxf(m0, tm0), mn1 = fmaxf(m1, tm1);
        float sc0 = ex2f(m0 - mn0), sc1 = ex2f(m1 - mn1);
        m0 = mn0; m1 = mn1;
        float rs0 = 0.f, rs1 = 0.f;
        #pragma unroll
        for (int t = 0; t < 8; t++) {
            accs[t][0] = ex2f(accs[t][0] - m0);
            accs[t][1] = ex2f(accs[t][1] - m0);
            accs[t][2] = ex2f(accs[t][2] - m1);
            accs[t][3] = ex2f(accs[t][3] - m1);
            rs0 += accs[t][0] + accs[t][1];
            rs1 += accs[t][2] + accs[t][3];
        }
        rs0 += __shfl_xor_sync(0xFFFFFFFF, rs0, 1);
        rs0 += __shfl_xor_sync(0xFFFFFFFF, rs0, 2);
        rs1 += __shfl_xor_sync(0xFFFFFFFF, rs1, 1);
        rs1 += __shfl_xor_sync(0xFFFFFFFF, rs1, 2);
        l0 = l0 * sc0 + rs0;
        l1 = l1 * sc1 + rs1;
        #pragma unroll
        for (int o = 0; o < 8; o++) {
            acco[o][0] *= sc0; acco[o][1] *= sc0;
            acco[o][2] *= sc1; acco[o][3] *= sc1;
        }

        // PV: P fp16 x Vh (single product)
        #pragma unroll
        for (int kt = 0; kt < 4; kt++) {
            uint32_t pH[4];
            pH[0] = pack_h2(accs[2*kt][0],   accs[2*kt][1]);
            pH[1] = pack_h2(accs[2*kt][2],   accs[2*kt][3]);
            pH[2] = pack_h2(accs[2*kt+1][0], accs[2*kt+1][1]);
            pH[3] = pack_h2(accs[2*kt+1][2], accs[2*kt+1][3]);
            #pragma unroll
            for (int vg = 0; vg < 2; vg++) {
                uint32_t vh2[2][4];
                #pragma unroll
                for (int q = 0; q < 2; q++) {
                    int vr = kt * 16 + (lane & 15);
                    int vc = vg * 32 + q * 16 + ((lane >> 4) << 3);
                    ldsm4t(vh2[q], smem_u32(sb + FS_VH + vr * FSPAD + vc));
                }
                #pragma unroll
                for (int t = 0; t < 4; t++)
                    mma_f16(acco[vg * 4 + t], pH, &vh2[t >> 1][(t & 1) * 2]);
            }
        }

        if (j < 15) CP_WAIT0();
        __syncthreads();
    }

    float inv0 = 1.f / l0, inv1 = 1.f / l1;
    float imu = 1.f / mu;
    float lm = LAMBD_ * mu;
    int row0 = i0 + wid * 16 + (lane >> 2);
    #pragma unroll
    for (int o = 0; o < 8; o++) {
        int col = o * 8 + (lane & 3) * 2;
        #pragma unroll
        for (int half = 0; half < 2; half++) {
            size_t ia = hbase + (size_t)(row0 + half * 8) * HD_ + col;
            float la = acco[o][half * 2]     * (half ? inv1 : inv0);
            float lb = acco[o][half * 2 + 1] * (half ? inv1 : inv0);
            float2 kv = *(const float2*)&g_k[ia];
            float2 yv = *(const float2*)&g_y[ia];
            float2 sv = *(const float2*)&g_s[ia];
            float yn0 = yv.x + mu * (kv.x - la - sv.x);
            float yn1 = yv.y + mu * (kv.y - lb - sv.y);
            float ym0 = yn0 * imu, ym1 = yn1 * imu;
            float t0 = kv.x - la + ym0, t1 = kv.y - lb + ym1;
            float sn0 = (t0 >= lm) ? (t0 - lm) : ((t0 <= -lm) ? (t0 + lm) : 0.f);
            float sn1 = (t1 >= lm) ? (t1 - lm) : ((t1 <= -lm) ? (t1 + lm) : 0.f);
            *(float2*)&g_y[ia] = make_float2(yn0, yn1);
            *(float2*)&g_s[ia] = make_float2(sn0, sn1);
            float k20 = (kv.x - sn0 - ym0) * QSC_;
            float k21 = (kv.y - sn1 - ym1) * QSC_;
            uint32_t h2, l2;
            split2(k20, k21, h2, l2);
            *(uint32_t*)&k2h_dst[ia] = h2;
            *(uint32_t*)&k2l_dst[ia] = l2;
        }
    }
}

// =================== final iteration: 2-pass flash, materializes attn + obnc ===================
__global__ void __launch_bounds__(256, 2) final_flash_kernel(
    float* __restrict__ attn,
    const __nv_bfloat16* __restrict__ k2h_src, const __nv_bfloat16* __restrict__ k2l_src)
{
    extern __shared__ __nv_bfloat16 fsm[];
    const int bh = blockIdx.y;
    const int i0 = blockIdx.x * 128;
    const int tid = threadIdx.x, wid = tid >> 5, lane = tid & 31;

    const size_t hbase = (size_t)bh * N_ * HD_;
    const __nv_bfloat16* Gh = k2h_src + hbase;
    const __nv_bfloat16* Gl = k2l_src + hbase;
    const __half* Vh = g_vh + hbase;
    const __half* Vl = g_vl + hbase;

    #pragma unroll
    for (int i = 0; i < 8; i++) {
        int idx = tid + i * 256;
        int arr = idx >> 10, rem = idx & 1023, row = rem >> 3, c = rem & 7;
        const __nv_bfloat16* src = (arr ? Gl : Gh) + (size_t)(i0 + row) * HD_ + c * 8;
        *(uint4*)(fsm + (arr ? FA_L : FA_H) + row * FSPAD + c * 8) = *(const uint4*)src;
    }

    auto cp_tile = [&](int stage, int j, bool withV) {
        int sbase = FSTG0 + stage * FSTGS_F;
        #pragma unroll
        for (int i = 0; i < 8; i++) {
            int idx = tid + i * 256;
            int arr = idx >> 9, rem = idx & 511, row = rem >> 3, c = rem & 7;
            if (!withV && arr >= 2) continue;
            const void* src;
            int off;
            if      (arr == 0) { src = Gh + (size_t)(j * 64 + row) * HD_ + c * 8; off = FS_BH; }
            else if (arr == 1) { src = Gl + (size_t)(j * 64 + row) * HD_ + c * 8; off = FS_BL; }
            else if (arr == 2) { src = Vh + (size_t)(j * 64 + row) * HD_ + c * 8; off = FS_VH; }
            else               { src = Vl + (size_t)(j * 64 + row) * HD_ + c * 8; off = FS_VL; }
            cp16(smem_u32(fsm + sbase + off + row * FSPAD + c * 8), src);
        }
    };

    auto compute_S = [&](const __nv_bfloat16* sb, float accs[8][4]) {
        #pragma unroll
        for (int ks = 0; ks < 4; ks++) {
            uint32_t aH[4], aL[4];
            {
                int ar = wid * 16 + (lane & 15);
                int ac = ks * 16 + ((lane >> 4) << 3);
                ldsm4(aH, smem_u32(fsm + FA_H + ar * FSPAD + ac));
                ldsm4(aL, smem_u32(fsm + FA_L + ar * FSPAD + ac));
            }
            #pragma unroll
            for (int ng = 0; ng < 2; ng++) {
                uint32_t bh2[2][4], bl2[2][4];
                #pragma unroll
                for (int p = 0; p < 2; p++) {
                    int nr = ng * 32 + p * 16 + (lane & 7) + ((lane >> 4) << 3);
                    int kc = ks * 16 + (((lane >> 3) & 1) << 3);
                    ldsm4(bh2[p], smem_u32(sb + FS_BH + nr * FSPAD + kc));
                    ldsm4(bl2[p], smem_u32(sb + FS_BL + nr * FSPAD + kc));
                }
                #pragma unroll
                for (int t = 0; t < 4; t++) {
                    float* c = accs[ng * 4 + t];
                    const uint32_t* bhf = &bh2[t >> 1][(t & 1) * 2];
                    const uint32_t* blf = &bl2[t >> 1][(t & 1) * 2];
                    mma_bf16(c, aH, bhf);
                    mma_bf16(c, aH, blf);
                    mma_bf16(c, aL, bhf);
                }
            }
        }
    };

    // ---------- PASS A: row stats ----------
    cp_tile(0, 0, false);
    CP_COMMIT(); CP_WAIT0();
    __syncthreads();

    float m0 = -1e30f, m1 = -1e30f, l0 = 0.f, l1 = 0.f;
    for (int j = 0; j < 16; j++) {
        if (j < 15) { cp_tile((j + 1) & 1, j + 1, false); CP_COMMIT(); }
        const __nv_bfloat16* sb = fsm + FSTG0 + (j & 1) * FSTGS_F;
        float accs[8][4] = {};
        compute_S(sb, accs);

        float tm0 = -1e30f, tm1 = -1e30f;
        #pragma unroll
        for (int t = 0; t < 8; t++) {
            tm0 = fmaxf(tm0, fmaxf(accs[t][0], accs[t][1]));
            tm1 = fmaxf(tm1, fmaxf(accs[t][2], accs[t][3]));
        }
        tm0 = fmaxf(tm0, __shfl_xor_sync(0xFFFFFFFF, tm0, 1));
        tm0 = fmaxf(tm0, __shfl_xor_sync(0xFFFFFFFF, tm0, 2));
        tm1 = fmaxf(tm1, __shfl_xor_sync(0xFFFFFFFF, tm1, 1));
        tm1 = fmaxf(tm1, __shfl_xor_sync(0xFFFFFFFF, tm1, 2));
        float mn0 = fmaxf(m0, tm0), mn1 = fmaxf(m1, tm1);
        float sc0 = ex2f(m0 - mn0), sc1 = ex2f(m1 - mn1);
        m0 = mn0; m1 = mn1;
        float rs0 = 0.f, rs1 = 0.f;
        #pragma unroll
        for (int t = 0; t < 8; t++) {
            rs0 += ex2f(accs[t][0] - m0) + ex2f(accs[t][1] - m0);
            rs1 += ex2f(accs[t][2] - m1) + ex2f(accs[t][3] - m1);
        }
        rs0 += __shfl_xor_sync(0xFFFFFFFF, rs0, 1);
        rs0 += __shfl_xor_sync(0xFFFFFFFF, rs0, 2);
        rs1 += __shfl_xor_sync(0xFFFFFFFF, rs1, 1);
        rs1 += __shfl_xor_sync(0xFFFFFFFF, rs1, 2);
        l0 = l0 * sc0 + rs0;
        l1 = l1 * sc1 + rs1;
        if (j < 15) CP_WAIT0();
        __syncthreads();
    }
    float inv0 = 1.f / l0, inv1 = 1.f / l1;

    // ---------- PASS B: normalized P -> attn, PV ----------
    cp_tile(0, 0, true);
    CP_COMMIT(); CP_WAIT0();
    __syncthreads();

    float* Sp = attn + (size_t)bh * N_ * N_;
    const int prow = i0 + wid * 16 + (lane >> 2);
    float acco[8][4] = {};

    for (int j = 0; j < 16; j++) {
        if (j < 15) { cp_tile((j + 1) & 1, j + 1, true); CP_COMMIT(); }
        const __nv_bfloat16* sb = fsm + FSTG0 + (j & 1) * FSTGS_F;
        float accs[8][4] = {};
        compute_S(sb, accs);

        #pragma unroll
        for (int t = 0; t < 8; t++) {
            accs[t][0] = ex2f(accs[t][0] - m0) * inv0;
            accs[t][1] = ex2f(accs[t][1] - m0) * inv0;
            accs[t][2] = ex2f(accs[t][2] - m1) * inv1;
            accs[t][3] = ex2f(accs[t][3] - m1) * inv1;
            int col = j * 64 + (t >> 2) * 32 + (t & 3) * 8 + (lane & 3) * 2;
            *(float2*)&Sp[(size_t)prow * N_ + col]       = make_float2(accs[t][0], accs[t][1]);
            *(float2*)&Sp[(size_t)(prow + 8) * N_ + col] = make_float2(accs[t][2], accs[t][3]);
        }

        #pragma unroll
        for (int kt = 0; kt < 4; kt++) {
            uint32_t pH[4];
            pH[0] = pack_h2(accs[2*kt][0],   accs[2*kt][1]);
            pH[1] = pack_h2(accs[2*kt][2],   accs[2*kt][3]);
            pH[2] = pack_h2(accs[2*kt+1][0], accs[2*kt+1][1]);
            pH[3] = pack_h2(accs[2*kt+1][2], accs[2*kt+1][3]);
            #pragma unroll
            for (int vg = 0; vg < 2; vg++) {
                uint32_t vh2[2][4], vl2[2][4];
                #pragma unroll
                for (int q = 0; q < 2; q++) {
                    int vr = kt * 16 + (lane & 15);
                    int vc = vg * 32 + q * 16 + ((lane >> 4) << 3);
                    ldsm4t(vh2[q], smem_u32(sb + FS_VH + vr * FSPAD + vc));
                    ldsm4t(vl2[q], smem_u32(sb + FS_VL + vr * FSPAD + vc));
                }
                #pragma unroll
                for (int t = 0; t < 4; t++) {
                    float* o = acco[vg * 4 + t];
                    mma_f16(o, pH, &vh2[t >> 1][(t & 1) * 2]);
                    mma_f16(o, pH, &vl2[t >> 1][(t & 1) * 2]);
                }
            }
        }

        if (j < 15) CP_WAIT0();
        __syncthreads();
    }

    int b = bh / H_, h = bh % H_;
    #pragma unroll
    for (int o = 0; o < 8; o++) {
        int col = o * 8 + (lane & 3) * 2;
        uint32_t h0, l0b, h1, l1b;
        split2(acco[o][0], acco[o][1], h0, l0b);
        split2(acco[o][2], acco[o][3], h1, l1b);
        size_t idx0 = ((size_t)(b * N_ + prow)) * C_ + h * HD_ + col;
        size_t idx1 = ((size_t)(b * N_ + prow + 8)) * C_ + h * HD_ + col;
        *(uint32_t*)&g_och[idx0] = h0;
        *(uint32_t*)&g_ocl[idx0] = l0b;
        *(uint32_t*)&g_och[idx1] = h1;
        *(uint32_t*)&g_ocl[idx1] = l1b;
    }
}

// =================== bf16x3 HMMA GEMM: qkv and proj ===================
// CTA 128(M) x 64(N), 8 warps as 4x2 (warp tile 32x32), K chunk 64, double buffer.
#define QA_H 0
#define QA_L 9216
#define QB_H 18432
#define QB_L 23040
#define QSTG 27648
#define WPAD 72

template<int NCOLS, int KDIM>
__device__ __forceinline__ void mma_gemm_main(
    const __nv_bfloat16* __restrict__ Ah, const __nv_bfloat16* __restrict__ Al,
    const __nv_bfloat16* __restrict__ Wh, const __nv_bfloat16* __restrict__ Wl,
    __nv_bfloat16* sm, int by, int bx, float acc[2][4][4])
{
    const int tid = threadIdx.x, wid = tid >> 5, lane = tid & 31;
    const int wm = wid & 3, wn = wid >> 2;

    auto cp_stage = [&](int stage, int k0) {
        int sb = stage * QSTG;
        #pragma unroll
        for (int i = 0; i < 8; i++) {
            int idx = tid + i * 256;
            int arr = idx >> 10, rem = idx & 1023, row = rem >> 3, c = rem & 7;
            const __nv_bfloat16* src = (arr ? Al : Ah) + (size_t)(by + row) * KDIM + k0 + c * 8;
            cp16(smem_u32(sm + sb + (arr ? QA_L : QA_H) + row * FSPAD + c * 8), src);
        }
        #pragma unroll
        for (int i = 0; i < 4; i++) {
            int idx = tid + i * 256;
            int arr = idx >> 9, rem = idx & 511, row = rem >> 3, c = rem & 7;
            const __nv_bfloat16* src = (arr ? Wl : Wh) + (size_t)(k0 + row) * NCOLS + bx + c * 8;
            cp16(smem_u32(sm + sb + (arr ? QB_L : QB_H) + row * WPAD + c * 8), src);
        }
    };

    cp_stage(0, 0);
    CP_COMMIT(); CP_WAIT0();
    __syncthreads();

    const int NCHUNK = KDIM / 64;
    for (int ch = 0; ch < NCHUNK; ch++) {
        if (ch < NCHUNK - 1) { cp_stage((ch + 1) & 1, (ch + 1) * 64); CP_COMMIT(); }
        __nv_bfloat16* sb = sm + (ch & 1) * QSTG;
        #pragma unroll
        for (int ks = 0; ks < 4; ks++) {
            uint32_t aH[2][4], aL[2][4];
            #pragma unroll
            for (int mt = 0; mt < 2; mt++) {
                int ar = wm * 32 + mt * 16 + (lane & 15);
                int ac = ks * 16 + ((lane >> 4) << 3);
                ldsm4(aH[mt], smem_u32(sb + QA_H + ar * FSPAD + ac));
                ldsm4(aL[mt], smem_u32(sb + QA_L + ar * FSPAD + ac));
            }
            uint32_t bh2[2][4], bl2[2][4];
            #pragma unroll
            for (int q = 0; q < 2; q++) {
                int vr = ks * 16 + (lane & 15);
                int vc = wn * 32 + q * 16 + ((lane >> 4) << 3);
                ldsm4t(bh2[q], smem_u32(sb + QB_H + vr * WPAD + vc));
                ldsm4t(bl2[q], smem_u32(sb + QB_L + vr * WPAD + vc));
            }
            #pragma unroll
            for (int mt = 0; mt < 2; mt++)
                #pragma unroll
                for (int nt = 0; nt < 4; nt++) {
                    const uint32_t* bhf = &bh2[nt >> 1][(nt & 1) * 2];
                    const uint32_t* blf = &bl2[nt >> 1][(nt & 1) * 2];
                    mma_bf16(acc[mt][nt], aH[mt], bhf);
                    mma_bf16(acc[mt][nt], aH[mt], blf);
                    mma_bf16(acc[mt][nt], aL[mt], bhf);
                }
        }
        if (ch < NCHUNK - 1) CP_WAIT0();
        __syncthreads();
    }
}

__global__ void __launch_bounds__(256, 2) qkv_mma_kernel(const float* __restrict__ bias) {
    extern __shared__ __nv_bfloat16 qsm[];
    const int bx = blockIdx.x * 64;
    const int by = blockIdx.y * 128;
    const int wid = threadIdx.x >> 5, lane = threadIdx.x & 31;
    const int wm = wid & 3, wn = wid >> 2;

    float acc[2][4][4] = {};
    mma_gemm_main<TWO_C_, C_>(g_xh, g_xl, g_wqh, g_wql, qsm, by, bx, acc);

    #pragma unroll
    for (int mt = 0; mt < 2; mt++) {
        int r0 = by + wm * 32 + mt * 16 + (lane >> 2);
        #pragma unroll
        for (int nt = 0; nt < 4; nt++) {
            int col = bx + wn * 32 + nt * 8 + (lane & 3) * 2;
            float b0 = bias[col], b1 = bias[col + 1];
            #pragma unroll
            for (int half = 0; half < 2; half++) {
                int r = r0 + half * 8;
                float v0 = acc[mt][nt][half * 2]     + b0;
                float v1 = acc[mt][nt][half * 2 + 1] + b1;
                int bb = r >> 10, n = r & 1023;
                int which = col >= C_;
                int cc = col - which * C_;
                int hh = cc / HD_, hd = cc % HD_;
                size_t idx = (((size_t)(bb * H_ + hh)) * N_ + n) * HD_ + hd;
                if (!which) {
                    *(float2*)&g_k[idx] = make_float2(v0, v1);
                } else {
                    uint32_t h2, l2;
                    split2h(v0, v1, h2, l2);
                    *(uint32_t*)&g_vh[idx] = h2;
                    *(uint32_t*)&g_vl[idx] = l2;
                }
            }
        }
    }
}

__global__ void __launch_bounds__(256, 2) proj_mma_kernel(const float* __restrict__ bias,
                                                          float* __restrict__ out) {
    extern __shared__ __nv_bfloat16 qsm[];
    const int bx = blockIdx.x * 64;
    const int by = blockIdx.y * 128;
    const int wid = threadIdx.x >> 5, lane = threadIdx.x & 31;
    const int wm = wid & 3, wn = wid >> 2;

    float acc[2][4][4] = {};
    mma_gemm_main<C_, C_>(g_och, g_ocl, g_wph, g_wpl, qsm, by, bx, acc);

    #pragma unroll
    for (int mt = 0; mt < 2; mt++) {
        int r0 = by + wm * 32 + mt * 16 + (lane >> 2);
        #pragma unroll
        for (int nt = 0; nt < 4; nt++) {
            int col = bx + wn * 32 + nt * 8 + (lane & 3) * 2;
            float b0 = bias[col], b1 = bias[col + 1];
            *(float2*)&out[(size_t)r0 * C_ + col] =
                make_float2(acc[mt][nt][0] + b0, acc[mt][nt][1] + b1);
            *(float2*)&out[(size_t)(r0 + 8) * C_ + col] =
                make_float2(acc[mt][nt][2] + b0, acc[mt][nt][3] + b1);
        }
    }
}

// ---------------- launch ----------------
extern "C" void kernel_launch(void* const* d_in, const int* in_sizes, int n_in,
                              void* d_out, int out_size) {
    const float* x     = (const float*)d_in[0];
    const float* Wqkv  = (const float*)d_in[1];
    const float* bqkv  = (const float*)d_in[2];
    const float* Wproj = (const float*)d_in[3];
    const float* bproj = (const float*)d_in[4];
    float* out = (float*)d_out;

    float* attn;
    if ((size_t)out_size >= OUT_ELEMS + ATTN_ELEMS) {
        attn = out + OUT_ELEMS;
    } else {
        void* p = nullptr;
        cudaGetSymbolAddress(&p, g_attn_fallback);
        attn = (float*)p;
    }

    const int FLASH_SMEM_I = (FSTG0 + 2 * FSTGS_I) * 2;   // 92,160 B
    const int FLASH_SMEM_F = (FSTG0 + 2 * FSTGS_F) * 2;   // 110,592 B
    const int GEMM_SMEM    = 2 * QSTG * 2;                // 110,592 B
    cudaFuncSetAttribute(flash_iter_kernel, cudaFuncAttributeMaxDynamicSharedMemorySize, FLASH_SMEM_I);
    cudaFuncSetAttribute(final_flash_kernel, cudaFuncAttributeMaxDynamicSharedMemorySize, FLASH_SMEM_F);
    cudaFuncSetAttribute(qkv_mma_kernel, cudaFuncAttributeMaxDynamicSharedMemorySize, GEMM_SMEM);
    cudaFuncSetAttribute(proj_mma_kernel, cudaFuncAttributeMaxDynamicSharedMemorySize, GEMM_SMEM);

    __nv_bfloat16 *xh, *xl, *wqh, *wql, *wph, *wpl;
    __nv_bfloat16 *k2h_a, *k2l_a, *k2h_b, *k2l_b;
    { void* p; cudaGetSymbolAddress(&p, g_xh);  xh  = (__nv_bfloat16*)p; }
    { void* p; cudaGetSymbolAddress(&p, g_xl);  xl  = (__nv_bfloat16*)p; }
    { void* p; cudaGetSymbolAddress(&p, g_wqh); wqh = (__nv_bfloat16*)p; }
    { void* p; cudaGetSymbolAddress(&p, g_wql); wql = (__nv_bfloat16*)p; }
    { void* p; cudaGetSymbolAddress(&p, g_wph); wph = (__nv_bfloat16*)p; }
    { void* p; cudaGetSymbolAddress(&p, g_wpl); wpl = (__nv_bfloat16*)p; }
    { void* p; cudaGetSymbolAddress(&p, g_k2h_a); k2h_a = (__nv_bfloat16*)p; }
    { void* p; cudaGetSymbolAddress(&p, g_k2l_a); k2l_a = (__nv_bfloat16*)p; }
    { void* p; cudaGetSymbolAddress(&p, g_k2h_b); k2h_b = (__nv_bfloat16*)p; }
    { void* p; cudaGetSymbolAddress(&p, g_k2l_b); k2l_b = (__nv_bfloat16*)p; }

    const int eblocks = (int)((KV_ELEMS + 255) / 256);

    split_kernel<<<(6291456 + 255) / 256, 256>>>(x, xh, xl, 6291456);
    split_kernel<<<(1179648 + 255) / 256, 256>>>(Wqkv, wqh, wql, 1179648);
    split_kernel<<<(589824 + 255) / 256, 256>>>(Wproj, wph, wpl, 589824);

    qkv_mma_kernel<<<dim3(TWO_C_ / 64, M_ROWS / 128), 256, GEMM_SMEM>>>(bqkv);
    mu_part_kernel<<<BH_ * 8, 256>>>();
    mu_fin_kernel<<<1, 128>>>();
    k2_init_kernel<<<eblocks, 256>>>();   // writes buffer A

    __nv_bfloat16* bufs_h[2] = {k2h_a, k2h_b};
    __nv_bfloat16* bufs_l[2] = {k2l_a, k2l_b};
    for (int it = 0; it < 5; ++it) {
        int s = it & 1, d = (it + 1) & 1;
        flash_iter_kernel<<<dim3(N_ / 128, BH_), 256, FLASH_SMEM_I>>>(
            bufs_h[s], bufs_l[s], bufs_h[d], bufs_l[d]);
    }
    final_flash_kernel<<<dim3(N_ / 128, BH_), 256, FLASH_SMEM_F>>>(attn, bufs_h[1], bufs_l[1]);

    proj_mma_kernel<<<dim3(C_ / 64, M_ROWS / 128), 256, GEMM_SMEM>>>(bproj, out);
}

// round 12
// speedup vs baseline: 6.0118x; 1.0011x over previous
#include <cuda_runtime.h>
#include <cuda_bf16.h>
#include <cuda_fp16.h>
#include <math.h>
#include <stdint.h>

#define B_   8
#define N_   1024
#define C_   768
#define H_   12
#define HD_  64
#define BH_  (B_*H_)
#define TWO_C_ (2*C_)
#define M_ROWS (B_*N_)

static const size_t KV_ELEMS   = (size_t)BH_ * N_ * HD_;
static const size_t OUT_ELEMS  = (size_t)B_ * N_ * C_;
static const size_t ATTN_ELEMS = (size_t)BH_ * N_ * N_;

#define LAMBD_ 4.0f
// logits carried in log2 domain: S2 = (k2*QSC)·(k2*QSC)^T where QSC^2 = 0.125*log2(e)
#define QSC_ 0.42466089f

// ---------------- device scratch ----------------
__device__ float g_k [6291456];
__device__ float g_y [6291456];
__device__ float g_s [6291456];
__device__ __nv_bfloat16 g_k2h_a[6291456];
__device__ __nv_bfloat16 g_k2l_a[6291456];
__device__ __nv_bfloat16 g_k2h_b[6291456];
__device__ __nv_bfloat16 g_k2l_b[6291456];
__device__ __half g_vh [6291456];
__device__ __half g_vl [6291456];
__device__ __nv_bfloat16 g_xh [6291456];
__device__ __nv_bfloat16 g_xl [6291456];
__device__ __nv_bfloat16 g_wqh[1179648];
__device__ __nv_bfloat16 g_wql[1179648];
__device__ __nv_bfloat16 g_wph[589824];
__device__ __nv_bfloat16 g_wpl[589824];
__device__ __nv_bfloat16 g_och[6291456];
__device__ __nv_bfloat16 g_ocl[6291456];
__device__ float g_mu[96];
__device__ float g_mu_part[768];
__device__ float g_attn_fallback[100663296];

// ---------------- helpers ----------------
__device__ __forceinline__ uint32_t smem_u32(const void* p) {
    uint32_t a;
    asm("{ .reg .u64 t; cvta.to.shared.u64 t, %1; cvt.u32.u64 %0, t; }" : "=r"(a) : "l"(p));
    return a;
}
__device__ __forceinline__ void ldsm4(uint32_t r[4], uint32_t addr) {
    asm volatile("ldmatrix.sync.aligned.m8n8.x4.shared.b16 {%0,%1,%2,%3}, [%4];"
        : "=r"(r[0]), "=r"(r[1]), "=r"(r[2]), "=r"(r[3]) : "r"(addr));
}
__device__ __forceinline__ void ldsm4t(uint32_t r[4], uint32_t addr) {
    asm volatile("ldmatrix.sync.aligned.m8n8.x4.trans.shared.b16 {%0,%1,%2,%3}, [%4];"
        : "=r"(r[0]), "=r"(r[1]), "=r"(r[2]), "=r"(r[3]) : "r"(addr));
}
__device__ __forceinline__ void mma_bf16(float c[4], const uint32_t a[4], const uint32_t* b) {
    asm volatile("mma.sync.aligned.m16n8k16.row.col.f32.bf16.bf16.f32 "
        "{%0,%1,%2,%3}, {%4,%5,%6,%7}, {%8,%9}, {%0,%1,%2,%3};"
        : "+f"(c[0]), "+f"(c[1]), "+f"(c[2]), "+f"(c[3])
        : "r"(a[0]), "r"(a[1]), "r"(a[2]), "r"(a[3]), "r"(b[0]), "r"(b[1]));
}
__device__ __forceinline__ void mma_f16(float c[4], const uint32_t a[4], const uint32_t* b) {
    asm volatile("mma.sync.aligned.m16n8k16.row.col.f32.f16.f16.f32 "
        "{%0,%1,%2,%3}, {%4,%5,%6,%7}, {%8,%9}, {%0,%1,%2,%3};"
        : "+f"(c[0]), "+f"(c[1]), "+f"(c[2]), "+f"(c[3])
        : "r"(a[0]), "r"(a[1]), "r"(a[2]), "r"(a[3]), "r"(b[0]), "r"(b[1]));
}
__device__ __forceinline__ void split2(float x, float y, uint32_t& hi, uint32_t& lo) {
    __nv_bfloat16 hx = __float2bfloat16(x), hy = __float2bfloat16(y);
    __nv_bfloat162 h2; h2.x = hx; h2.y = hy;
    __nv_bfloat162 l2;
    l2.x = __float2bfloat16(x - __bfloat162float(hx));
    l2.y = __float2bfloat16(y - __bfloat162float(hy));
    hi = *reinterpret_cast<uint32_t*>(&h2);
    lo = *reinterpret_cast<uint32_t*>(&l2);
}
__device__ __forceinline__ void split2h(float x, float y, uint32_t& hi, uint32_t& lo) {
    __half2 h = __floats2half2_rn(x, y);
    __half2 l = __floats2half2_rn(x - __half2float(h.x), y - __half2float(h.y));
    hi = *reinterpret_cast<uint32_t*>(&h);
    lo = *reinterpret_cast<uint32_t*>(&l);
}
__device__ __forceinline__ uint32_t pack_h2(float x, float y) {
    __half2 h = __floats2half2_rn(x, y);
    return *reinterpret_cast<uint32_t*>(&h);
}
__device__ __forceinline__ float ex2f(float x) {
    float y; asm("ex2.approx.f32 %0, %1;" : "=f"(y) : "f"(x)); return y;
}
__device__ __forceinline__ void cp16(uint32_t dst, const void* src) {
    asm volatile("cp.async.cg.shared.global [%0], [%1], 16;" :: "r"(dst), "l"(src));
}
#define CP_COMMIT() asm volatile("cp.async.commit_group;" ::: "memory")
#define CP_WAIT0()  asm volatile("cp.async.wait_group 0;" ::: "memory")

// ---------------- elementwise ----------------
// vectorized: 2 elems/thread
__global__ void split_kernel(const float* __restrict__ src, __nv_bfloat16* __restrict__ h,
                             __nv_bfloat16* __restrict__ l, int n2) {
    int i = blockIdx.x * 256 + threadIdx.x;
    if (i >= n2) return;
    float2 v = ((const float2*)src)[i];
    uint32_t hh, ll;
    split2(v.x, v.y, hh, ll);
    ((uint32_t*)h)[i] = hh;
    ((uint32_t*)l)[i] = ll;
}

__global__ void k2_init_kernel() {
    size_t i2 = (size_t)blockIdx.x * 256 + threadIdx.x;   // pair index
    if (i2 >= KV_ELEMS / 2) return;
    size_t i = i2 * 2;
    int bh = (int)(i / ((size_t)N_ * HD_));
    float mu = g_mu[bh];
    float lm = LAMBD_ * mu;
    float2 kk = *(const float2*)&g_k[i];
    float s0 = (kk.x >= lm) ? (kk.x - lm) : ((kk.x <= -lm) ? (kk.x + lm) : 0.f);
    float s1 = (kk.y >= lm) ? (kk.y - lm) : ((kk.y <= -lm) ? (kk.y + lm) : 0.f);
    *(float2*)&g_s[i] = make_float2(s0, s1);
    *(float2*)&g_y[i] = make_float2(0.f, 0.f);
    uint32_t hh, ll;
    split2((kk.x - s0) * QSC_, (kk.y - s1) * QSC_, hh, ll);
    *(uint32_t*)&g_k2h_a[i] = hh;
    *(uint32_t*)&g_k2l_a[i] = ll;
}

__global__ void mu_part_kernel() {
    __shared__ float red[256];
    int bh = blockIdx.x >> 3;
    int sl = blockIdx.x & 7;
    const float* p = g_k + (size_t)bh * N_ * HD_ + sl * 8192;
    float s = 0.f;
    #pragma unroll
    for (int i = 0; i < 32; i++) s += fabsf(p[threadIdx.x + i * 256]);
    red[threadIdx.x] = s;
    __syncthreads();
    for (int st = 128; st > 0; st >>= 1) {
        if (threadIdx.x < st) red[threadIdx.x] += red[threadIdx.x + st];
        __syncthreads();
    }
    if (threadIdx.x == 0) g_mu_part[blockIdx.x] = red[0];
}
__global__ void mu_fin_kernel() {
    int bh = threadIdx.x;
    if (bh >= BH_) return;
    float s = 0.f;
    #pragma unroll
    for (int i = 0; i < 8; i++) s += g_mu_part[bh * 8 + i];
    g_mu[bh] = ((float)N_ * (float)C_ / 4.0f) / s;
}

// =================== flash iteration (iters 0..4) + fused y/s/k2 update ===================
#define FSPAD 72
#define FA_H  0
#define FA_L  9216
#define FSTG0 18432
#define FSTGS_I 13824    // iter stage: {Bh,Bl,Vh} x 64 x 72
#define FSTGS_F 18432    // final stage: pass A {Bh,Bl} x 128 x 72 OR pass B {Bh,Bl,Vh,Vl} x 64 x 72
#define FS_BH 0
#define FS_BL 4608
#define FS_VH 9216
#define FS_VL 13824
#define FA_BL 9216       // pass A (128-row): Bl offset

__global__ void __launch_bounds__(256, 2) flash_iter_kernel(
    const __nv_bfloat16* __restrict__ k2h_src, const __nv_bfloat16* __restrict__ k2l_src,
    __nv_bfloat16* __restrict__ k2h_dst, __nv_bfloat16* __restrict__ k2l_dst)
{
    extern __shared__ __nv_bfloat16 fsm[];
    const int bh = blockIdx.y;
    const int i0 = blockIdx.x * 128;
    const int tid = threadIdx.x, wid = tid >> 5, lane = tid & 31;

    const size_t hbase = (size_t)bh * N_ * HD_;
    const __nv_bfloat16* Gh = k2h_src + hbase;
    const __nv_bfloat16* Gl = k2l_src + hbase;
    const __half* Vh = g_vh + hbase;
    const float mu = g_mu[bh];

    #pragma unroll
    for (int i = 0; i < 8; i++) {
        int idx = tid + i * 256;
        int arr = idx >> 10, rem = idx & 1023, row = rem >> 3, c = rem & 7;
        const __nv_bfloat16* src = (arr ? Gl : Gh) + (size_t)(i0 + row) * HD_ + c * 8;
        *(uint4*)(fsm + (arr ? FA_L : FA_H) + row * FSPAD + c * 8) = *(const uint4*)src;
    }

    auto cp_tile = [&](int stage, int j) {
        int sbase = FSTG0 + stage * FSTGS_I;
        #pragma unroll
        for (int i = 0; i < 6; i++) {
            int idx = tid + i * 256;
            int arr = idx >> 9, rem = idx & 511, row = rem >> 3, c = rem & 7;
            const void* src;
            int off;
            if      (arr == 0) { src = Gh + (size_t)(j * 64 + row) * HD_ + c * 8; off = FS_BH; }
            else if (arr == 1) { src = Gl + (size_t)(j * 64 + row) * HD_ + c * 8; off = FS_BL; }
            else               { src = Vh + (size_t)(j * 64 + row) * HD_ + c * 8; off = FS_VH; }
            cp16(smem_u32(fsm + sbase + off + row * FSPAD + c * 8), src);
        }
    };

    cp_tile(0, 0);
    CP_COMMIT(); CP_WAIT0();
    __syncthreads();

    float m0 = -1e30f, m1 = -1e30f, l0 = 0.f, l1 = 0.f;
    float acco[8][4] = {};

    for (int j = 0; j < 16; j++) {
        if (j < 15) { cp_tile((j + 1) & 1, j + 1); CP_COMMIT(); }
        const __nv_bfloat16* sb = fsm + FSTG0 + (j & 1) * FSTGS_I;

        float accs[8][4] = {};
        #pragma unroll
        for (int ks = 0; ks < 4; ks++) {
            uint32_t aH[4], aL[4];
            {
                int ar = wid * 16 + (lane & 15);
                int ac = ks * 16 + ((lane >> 4) << 3);
                ldsm4(aH, smem_u32(fsm + FA_H + ar * FSPAD + ac));
                ldsm4(aL, smem_u32(fsm + FA_L + ar * FSPAD + ac));
            }
            #pragma unroll
            for (int ng = 0; ng < 2; ng++) {
                uint32_t bh2[2][4], bl2[2][4];
                #pragma unroll
                for (int p = 0; p < 2; p++) {
                    int nr = ng * 32 + p * 16 + (lane & 7) + ((lane >> 4) << 3);
                    int kc = ks * 16 + (((lane >> 3) & 1) << 3);
                    ldsm4(bh2[p], smem_u32(sb + FS_BH + nr * FSPAD + kc));
                    ldsm4(bl2[p], smem_u32(sb + FS_BL + nr * FSPAD + kc));
                }
                #pragma unroll
                for (int t = 0; t < 4; t++) {
                    float* c = accs[ng * 4 + t];
                    const uint32_t* bhf = &bh2[t >> 1][(t & 1) * 2];
                    const uint32_t* blf = &bl2[t >> 1][(t & 1) * 2];
                    mma_bf16(c, aH, bhf);
                    mma_bf16(c, aH, blf);
                    mma_bf16(c, aL, bhf);
                }
            }
        }

        float tm0 = -1e30f, tm1 = -1e30f;
        #pragma unroll
        for (int t = 0; t < 8; t++) {
            tm0 = fmaxf(tm0, fmaxf(accs[t][0], accs[t][1]));
            tm1 = fmaxf(tm1, fmaxf(accs[t][2], accs[t][3]));
        }
        tm0 = fmaxf(tm0, __shfl_xor_sync(0xFFFFFFFF, tm0, 1));
        tm0 = fmaxf(tm0, __shfl_xor_sync(0xFFFFFFFF, tm0, 2));
        tm1 = fmaxf(tm1, __shfl_xor_sync(0xFFFFFFFF, tm1, 1));
        tm1 = fmaxf(tm1, __shfl_xor_sync(0xFFFFFFFF, tm1, 2));
        float mn0 = fmaxf(m0, tm0), mn1 = fmaxf(m1, tm1);
        float sc0 = ex2f(m0 - mn0), sc1 = ex2f(m1 - mn1);
        m0 = mn0; m1 = mn1;
        float rs0 = 0.f, rs1 = 0.f;
        #pragma unroll
        for (int t = 0; t < 8; t++) {
            accs[t][0] = ex2f(accs[t][0] - m0);
            accs[t][1] = ex2f(accs[t][1] - m0);
            accs[t][2] = ex2f(accs[t][2] - m1);
            accs[t][3] = ex2f(accs[t][3] - m1);
            rs0 += accs[t][0] + accs[t][1];
            rs1 += accs[t][2] + accs[t][3];
        }
        rs0 += __shfl_xor_sync(0xFFFFFFFF, rs0, 1);
        rs0 += __shfl_xor_sync(0xFFFFFFFF, rs0, 2);
        rs1 += __shfl_xor_sync(0xFFFFFFFF, rs1, 1);
        rs1 += __shfl_xor_sync(0xFFFFFFFF, rs1, 2);
        l0 = l0 * sc0 + rs0;
        l1 = l1 * sc1 + rs1;
        #pragma unroll
        for (int o = 0; o < 8; o++) {
            acco[o][0] *= sc0; acco[o][1] *= sc0;
            acco[o][2] *= sc1; acco[o][3] *= sc1;
        }

        // PV: P fp16 x Vh (single product)
        #pragma unroll
        for (int kt = 0; kt < 4; kt++) {
            uint32_t pH[4];
            pH[0] = pack_h2(accs[2*kt][0],   accs[2*kt][1]);
            pH[1] = pack_h2(accs[2*kt][2],   accs[2*kt][3]);
            pH[2] = pack_h2(accs[2*kt+1][0], accs[2*kt+1][1]);
            pH[3] = pack_h2(accs[2*kt+1][2], accs[2*kt+1][3]);
            #pragma unroll
            for (int vg = 0; vg < 2; vg++) {
                uint32_t vh2[2][4];
                #pragma unroll
                for (int q = 0; q < 2; q++) {
                    int vr = kt * 16 + (lane & 15);
                    int vc = vg * 32 + q * 16 + ((lane >> 4) << 3);
                    ldsm4t(vh2[q], smem_u32(sb + FS_VH + vr * FSPAD + vc));
                }
                #pragma unroll
                for (int t = 0; t < 4; t++)
                    mma_f16(acco[vg * 4 + t], pH, &vh2[t >> 1][(t & 1) * 2]);
            }
        }

        if (j < 15) CP_WAIT0();
        __syncthreads();
    }

    float inv0 = 1.f / l0, inv1 = 1.f / l1;
    float imu = 1.f / mu;
    float lm = LAMBD_ * mu;
    int row0 = i0 + wid * 16 + (lane >> 2);
    #pragma unroll
    for (int o = 0; o < 8; o++) {
        int col = o * 8 + (lane & 3) * 2;
        #pragma unroll
        for (int half = 0; half < 2; half++) {
            size_t ia = hbase + (size_t)(row0 + half * 8) * HD_ + col;
            float la = acco[o][half * 2]     * (half ? inv1 : inv0);
            float lb = acco[o][half * 2 + 1] * (half ? inv1 : inv0);
            float2 kv = *(const float2*)&g_k[ia];
            float2 yv = *(const float2*)&g_y[ia];
            float2 sv = *(const float2*)&g_s[ia];
            float yn0 = yv.x + mu * (kv.x - la - sv.x);
            float yn1 = yv.y + mu * (kv.y - lb - sv.y);
            float ym0 = yn0 * imu, ym1 = yn1 * imu;
            float t0 = kv.x - la + ym0, t1 = kv.y - lb + ym1;
            float sn0 = (t0 >= lm) ? (t0 - lm) : ((t0 <= -lm) ? (t0 + lm) : 0.f);
            float sn1 = (t1 >= lm) ? (t1 - lm) : ((t1 <= -lm) ? (t1 + lm) : 0.f);
            *(float2*)&g_y[ia] = make_float2(yn0, yn1);
            *(float2*)&g_s[ia] = make_float2(sn0, sn1);
            float k20 = (kv.x - sn0 - ym0) * QSC_;
            float k21 = (kv.y - sn1 - ym1) * QSC_;
            uint32_t h2, l2;
            split2(k20, k21, h2, l2);
            *(uint32_t*)&k2h_dst[ia] = h2;
            *(uint32_t*)&k2l_dst[ia] = l2;
        }
    }
}

// =================== final iteration: 2-pass flash, materializes attn + obnc ===================
__global__ void __launch_bounds__(256, 2) final_flash_kernel(
    float* __restrict__ attn,
    const __nv_bfloat16* __restrict__ k2h_src, const __nv_bfloat16* __restrict__ k2l_src)
{
    extern __shared__ __nv_bfloat16 fsm[];
    const int bh = blockIdx.y;
    const int i0 = blockIdx.x * 128;
    const int tid = threadIdx.x, wid = tid >> 5, lane = tid & 31;

    const size_t hbase = (size_t)bh * N_ * HD_;
    const __nv_bfloat16* Gh = k2h_src + hbase;
    const __nv_bfloat16* Gl = k2l_src + hbase;
    const __half* Vh = g_vh + hbase;
    const __half* Vl = g_vl + hbase;

    #pragma unroll
    for (int i = 0; i < 8; i++) {
        int idx = tid + i * 256;
        int arr = idx >> 10, rem = idx & 1023, row = rem >> 3, c = rem & 7;
        const __nv_bfloat16* src = (arr ? Gl : Gh) + (size_t)(i0 + row) * HD_ + c * 8;
        *(uint4*)(fsm + (arr ? FA_L : FA_H) + row * FSPAD + c * 8) = *(const uint4*)src;
    }

    // pass A tiles: 128 rows, {Bh, Bl} only
    auto cp_tileA = [&](int stage, int j) {
        int sbase = FSTG0 + stage * FSTGS_F;
        #pragma unroll
        for (int i = 0; i < 8; i++) {
            int idx = tid + i * 256;        // 0..2047: 2 arrays x 128 rows x 8 chunks
            int arr = idx >> 10, rem = idx & 1023, row = rem >> 3, c = rem & 7;
            const __nv_bfloat16* src = (arr ? Gl : Gh) + (size_t)(j * 128 + row) * HD_ + c * 8;
            cp16(smem_u32(fsm + sbase + (arr ? FA_BL : FS_BH) + row * FSPAD + c * 8), src);
        }
    };
    // pass B tiles: 64 rows, {Bh, Bl, Vh, Vl}
    auto cp_tileB = [&](int stage, int j) {
        int sbase = FSTG0 + stage * FSTGS_F;
        #pragma unroll
        for (int i = 0; i < 8; i++) {
            int idx = tid + i * 256;
            int arr = idx >> 9, rem = idx & 511, row = rem >> 3, c = rem & 7;
            const void* src;
            int off;
            if      (arr == 0) { src = Gh + (size_t)(j * 64 + row) * HD_ + c * 8; off = FS_BH; }
            else if (arr == 1) { src = Gl + (size_t)(j * 64 + row) * HD_ + c * 8; off = FS_BL; }
            else if (arr == 2) { src = Vh + (size_t)(j * 64 + row) * HD_ + c * 8; off = FS_VH; }
            else               { src = Vl + (size_t)(j * 64 + row) * HD_ + c * 8; off = FS_VL; }
            cp16(smem_u32(fsm + sbase + off + row * FSPAD + c * 8), src);
        }
    };

    // ---------- PASS A: row stats over 128-wide tiles ----------
    cp_tileA(0, 0);
    CP_COMMIT(); CP_WAIT0();
    __syncthreads();

    float m0 = -1e30f, m1 = -1e30f, l0 = 0.f, l1 = 0.f;
    for (int j = 0; j < 8; j++) {
        if (j < 7) { cp_tileA((j + 1) & 1, j + 1); CP_COMMIT(); }
        const __nv_bfloat16* sb = fsm + FSTG0 + (j & 1) * FSTGS_F;
        float accs[16][4] = {};
        #pragma unroll
        for (int ks = 0; ks < 4; ks++) {
            uint32_t aH[4], aL[4];
            {
                int ar = wid * 16 + (lane & 15);
                int ac = ks * 16 + ((lane >> 4) << 3);
                ldsm4(aH, smem_u32(fsm + FA_H + ar * FSPAD + ac));
                ldsm4(aL, smem_u32(fsm + FA_L + ar * FSPAD + ac));
            }
            #pragma unroll
            for (int ng = 0; ng < 4; ng++) {
                uint32_t bh2[2][4], bl2[2][4];
                #pragma unroll
                for (int p = 0; p < 2; p++) {
                    int nr = ng * 32 + p * 16 + (lane & 7) + ((lane >> 4) << 3);
                    int kc = ks * 16 + (((lane >> 3) & 1) << 3);
                    ldsm4(bh2[p], smem_u32(sb + FS_BH + nr * FSPAD + kc));
                    ldsm4(bl2[p], smem_u32(sb + FA_BL + nr * FSPAD + kc));
                }
                #pragma unroll
                for (int t = 0; t < 4; t++) {
                    float* c = accs[ng * 4 + t];
                    const uint32_t* bhf = &bh2[t >> 1][(t & 1) * 2];
                    const uint32_t* blf = &bl2[t >> 1][(t & 1) * 2];
                    mma_bf16(c, aH, bhf);
                    mma_bf16(c, aH, blf);
                    mma_bf16(c, aL, bhf);
                }
            }
        }

        float tm0 = -1e30f, tm1 = -1e30f;
        #pragma unroll
        for (int t = 0; t < 16; t++) {
            tm0 = fmaxf(tm0, fmaxf(accs[t][0], accs[t][1]));
            tm1 = fmaxf(tm1, fmaxf(accs[t][2], accs[t][3]));
        }
        tm0 = fmaxf(tm0, __shfl_xor_sync(0xFFFFFFFF, tm0, 1));
        tm0 = fmaxf(tm0, __shfl_xor_sync(0xFFFFFFFF, tm0, 2));
        tm1 = fmaxf(tm1, __shfl_xor_sync(0xFFFFFFFF, tm1, 1));
        tm1 = fmaxf(tm1, __shfl_xor_sync(0xFFFFFFFF, tm1, 2));
        float mn0 = fmaxf(m0, tm0), mn1 = fmaxf(m1, tm1);
        float sc0 = ex2f(m0 - mn0), sc1 = ex2f(m1 - mn1);
        m0 = mn0; m1 = mn1;
        float rs0 = 0.f, rs1 = 0.f;
        #pragma unroll
        for (int t = 0; t < 16; t++) {
            rs0 += ex2f(accs[t][0] - m0) + ex2f(accs[t][1] - m0);
            rs1 += ex2f(accs[t][2] - m1) + ex2f(accs[t][3] - m1);
        }
        rs0 += __shfl_xor_sync(0xFFFFFFFF, rs0, 1);
        rs0 += __shfl_xor_sync(0xFFFFFFFF, rs0, 2);
        rs1 += __shfl_xor_sync(0xFFFFFFFF, rs1, 1);
        rs1 += __shfl_xor_sync(0xFFFFFFFF, rs1, 2);
        l0 = l0 * sc0 + rs0;
        l1 = l1 * sc1 + rs1;
        if (j < 7) CP_WAIT0();
        __syncthreads();
    }
    float inv0 = 1.f / l0, inv1 = 1.f / l1;

    // ---------- PASS B: normalized P -> attn, PV (64-wide tiles) ----------
    cp_tileB(0, 0);
    CP_COMMIT(); CP_WAIT0();
    __syncthreads();

    float* Sp = attn + (size_t)bh * N_ * N_;
    const int prow = i0 + wid * 16 + (lane >> 2);
    float acco[8][4] = {};

    for (int j = 0; j < 16; j++) {
        if (j < 15) { cp_tileB((j + 1) & 1, j + 1); CP_COMMIT(); }
        const __nv_bfloat16* sb = fsm + FSTG0 + (j & 1) * FSTGS_F;
        float accs[8][4] = {};
        #pragma unroll
        for (int ks = 0; ks < 4; ks++) {
            uint32_t aH[4], aL[4];
            {
                int ar = wid * 16 + (lane & 15);
                int ac = ks * 16 + ((lane >> 4) << 3);
                ldsm4(aH, smem_u32(fsm + FA_H + ar * FSPAD + ac));
                ldsm4(aL, smem_u32(fsm + FA_L + ar * FSPAD + ac));
            }
            #pragma unroll
            for (int ng = 0; ng < 2; ng++) {
                uint32_t bh2[2][4], bl2[2][4];
                #pragma unroll
                for (int p = 0; p < 2; p++) {
                    int nr = ng * 32 + p * 16 + (lane & 7) + ((lane >> 4) << 3);
                    int kc = ks * 16 + (((lane >> 3) & 1) << 3);
                    ldsm4(bh2[p], smem_u32(sb + FS_BH + nr * FSPAD + kc));
                    ldsm4(bl2[p], smem_u32(sb + FS_BL + nr * FSPAD + kc));
                }
                #pragma unroll
                for (int t = 0; t < 4; t++) {
                    float* c = accs[ng * 4 + t];
                    const uint32_t* bhf = &bh2[t >> 1][(t & 1) * 2];
                    const uint32_t* blf = &bl2[t >> 1][(t & 1) * 2];
                    mma_bf16(c, aH, bhf);
                    mma_bf16(c, aH, blf);
                    mma_bf16(c, aL, bhf);
                }
            }
        }

        #pragma unroll
        for (int t = 0; t < 8; t++) {
            accs[t][0] = ex2f(accs[t][0] - m0) * inv0;
            accs[t][1] = ex2f(accs[t][1] - m0) * inv0;
            accs[t][2] = ex2f(accs[t][2] - m1) * inv1;
            accs[t][3] = ex2f(accs[t][3] - m1) * inv1;
            int col = j * 64 + (t >> 2) * 32 + (t & 3) * 8 + (lane & 3) * 2;
            *(float2*)&Sp[(size_t)prow * N_ + col]       = make_float2(accs[t][0], accs[t][1]);
            *(float2*)&Sp[(size_t)(prow + 8) * N_ + col] = make_float2(accs[t][2], accs[t][3]);
        }

        #pragma unroll
        for (int kt = 0; kt < 4; kt++) {
            uint32_t pH[4];
            pH[0] = pack_h2(accs[2*kt][0],   accs[2*kt][1]);
            pH[1] = pack_h2(accs[2*kt][2],   accs[2*kt][3]);
            pH[2] = pack_h2(accs[2*kt+1][0], accs[2*kt+1][1]);
            pH[3] = pack_h2(accs[2*kt+1][2], accs[2*kt+1][3]);
            #pragma unroll
            for (int vg = 0; vg < 2; vg++) {
                uint32_t vh2[2][4], vl2[2][4];
                #pragma unroll
                for (int q = 0; q < 2; q++) {
                    int vr = kt * 16 + (lane & 15);
                    int vc = vg * 32 + q * 16 + ((lane >> 4) << 3);
                    ldsm4t(vh2[q], smem_u32(sb + FS_VH + vr * FSPAD + vc));
                    ldsm4t(vl2[q], smem_u32(sb + FS_VL + vr * FSPAD + vc));
                }
                #pragma unroll
                for (int t = 0; t < 4; t++) {
                    float* o = acco[vg * 4 + t];
                    mma_f16(o, pH, &vh2[t >> 1][(t & 1) * 2]);
                    mma_f16(o, pH, &vl2[t >> 1][(t & 1) * 2]);
                }
            }
        }

        if (j < 15) CP_WAIT0();
        __syncthreads();
    }

    int b = bh / H_, h = bh % H_;
    #pragma unroll
    for (int o = 0; o < 8; o++) {
        int col = o * 8 + (lane & 3) * 2;
        uint32_t h0, l0b, h1, l1b;
        split2(acco[o][0], acco[o][1], h0, l0b);
        split2(acco[o][2], acco[o][3], h1, l1b);
        size_t idx0 = ((size_t)(b * N_ + prow)) * C_ + h * HD_ + col;
        size_t idx1 = ((size_t)(b * N_ + prow + 8)) * C_ + h * HD_ + col;
        *(uint32_t*)&g_och[idx0] = h0;
        *(uint32_t*)&g_ocl[idx0] = l0b;
        *(uint32_t*)&g_och[idx1] = h1;
        *(uint32_t*)&g_ocl[idx1] = l1b;
    }
}

// =================== bf16x3 HMMA GEMM: qkv and proj ===================
#define QA_H 0
#define QA_L 9216
#define QB_H 18432
#define QB_L 23040
#define QSTG 27648
#define WPAD 72

template<int NCOLS, int KDIM>
__device__ __forceinline__ void mma_gemm_main(
    const __nv_bfloat16* __restrict__ Ah, const __nv_bfloat16* __restrict__ Al,
    const __nv_bfloat16* __restrict__ Wh, const __nv_bfloat16* __restrict__ Wl,
    __nv_bfloat16* sm, int by, int bx, float acc[2][4][4])
{
    const int tid = threadIdx.x, wid = tid >> 5, lane = tid & 31;
    const int wm = wid & 3, wn = wid >> 2;

    auto cp_stage = [&](int stage, int k0) {
        int sb = stage * QSTG;
        #pragma unroll
        for (int i = 0; i < 8; i++) {
            int idx = tid + i * 256;
            int arr = idx >> 10, rem = idx & 1023, row = rem >> 3, c = rem & 7;
            const __nv_bfloat16* src = (arr ? Al : Ah) + (size_t)(by + row) * KDIM + k0 + c * 8;
            cp16(smem_u32(sm + sb + (arr ? QA_L : QA_H) + row * FSPAD + c * 8), src);
        }
        #pragma unroll
        for (int i = 0; i < 4; i++) {
            int idx = tid + i * 256;
            int arr = idx >> 9, rem = idx & 511, row = rem >> 3, c = rem & 7;
            const __nv_bfloat16* src = (arr ? Wl : Wh) + (size_t)(k0 + row) * NCOLS + bx + c * 8;
            cp16(smem_u32(sm + sb + (arr ? QB_L : QB_H) + row * WPAD + c * 8), src);
        }
    };

    cp_stage(0, 0);
    CP_COMMIT(); CP_WAIT0();
    __syncthreads();

    const int NCHUNK = KDIM / 64;
    for (int ch = 0; ch < NCHUNK; ch++) {
        if (ch < NCHUNK - 1) { cp_stage((ch + 1) & 1, (ch + 1) * 64); CP_COMMIT(); }
        __nv_bfloat16* sb = sm + (ch & 1) * QSTG;
        #pragma unroll
        for (int ks = 0; ks < 4; ks++) {
            uint32_t aH[2][4], aL[2][4];
            #pragma unroll
            for (int mt = 0; mt < 2; mt++) {
                int ar = wm * 32 + mt * 16 + (lane & 15);
                int ac = ks * 16 + ((lane >> 4) << 3);
                ldsm4(aH[mt], smem_u32(sb + QA_H + ar * FSPAD + ac));
                ldsm4(aL[mt], smem_u32(sb + QA_L + ar * FSPAD + ac));
            }
            uint32_t bh2[2][4], bl2[2][4];
            #pragma unroll
            for (int q = 0; q < 2; q++) {
                int vr = ks * 16 + (lane & 15);
                int vc = wn * 32 + q * 16 + ((lane >> 4) << 3);
                ldsm4t(bh2[q], smem_u32(sb + QB_H + vr * WPAD + vc));
                ldsm4t(bl2[q], smem_u32(sb + QB_L + vr * WPAD + vc));
            }
            #pragma unroll
            for (int mt = 0; mt < 2; mt++)
                #pragma unroll
                for (int nt = 0; nt < 4; nt++) {
                    const uint32_t* bhf = &bh2[nt >> 1][(nt & 1) * 2];
                    const uint32_t* blf = &bl2[nt >> 1][(nt & 1) * 2];
                    mma_bf16(acc[mt][nt], aH[mt], bhf);
                    mma_bf16(acc[mt][nt], aH[mt], blf);
                    mma_bf16(acc[mt][nt], aL[mt], bhf);
                }
        }
        if (ch < NCHUNK - 1) CP_WAIT0();
        __syncthreads();
    }
}

__global__ void __launch_bounds__(256, 2) qkv_mma_kernel(const float* __restrict__ bias) {
    extern __shared__ __nv_bfloat16 qsm[];
    const int bx = blockIdx.x * 64;
    const int by = blockIdx.y * 128;
    const int wid = threadIdx.x >> 5, lane = threadIdx.x & 31;
    const int wm = wid & 3, wn = wid >> 2;

    float acc[2][4][4] = {};
    mma_gemm_main<TWO_C_, C_>(g_xh, g_xl, g_wqh, g_wql, qsm, by, bx, acc);

    #pragma unroll
    for (int mt = 0; mt < 2; mt++) {
        int r0 = by + wm * 32 + mt * 16 + (lane >> 2);
        #pragma unroll
        for (int nt = 0; nt < 4; nt++) {
            int col = bx + wn * 32 + nt * 8 + (lane & 3) * 2;
            float b0 = bias[col], b1 = bias[col + 1];
            #pragma unroll
            for (int half = 0; half < 2; half++) {
                int r = r0 + half * 8;
                float v0 = acc[mt][nt][half * 2]     + b0;
                float v1 = acc[mt][nt][half * 2 + 1] + b1;
                int bb = r >> 10, n = r & 1023;
                int which = col >= C_;
                int cc = col - which * C_;
                int hh = cc / HD_, hd = cc % HD_;
                size_t idx = (((size_t)(bb * H_ + hh)) * N_ + n) * HD_ + hd;
                if (!which) {
                    *(float2*)&g_k[idx] = make_float2(v0, v1);
                } else {
                    uint32_t h2, l2;
                    split2h(v0, v1, h2, l2);
                    *(uint32_t*)&g_vh[idx] = h2;
                    *(uint32_t*)&g_vl[idx] = l2;
                }
            }
        }
    }
}

__global__ void __launch_bounds__(256, 2) proj_mma_kernel(const float* __restrict__ bias,
                                                          float* __restrict__ out) {
    extern __shared__ __nv_bfloat16 qsm[];
    const int bx = blockIdx.x * 64;
    const int by = blockIdx.y * 128;
    const int wid = threadIdx.x >> 5, lane = threadIdx.x & 31;
    const int wm = wid & 3, wn = wid >> 2;

    float acc[2][4][4] = {};
    mma_gemm_main<C_, C_>(g_och, g_ocl, g_wph, g_wpl, qsm, by, bx, acc);

    #pragma unroll
    for (int mt = 0; mt < 2; mt++) {
        int r0 = by + wm * 32 + mt * 16 + (lane >> 2);
        #pragma unroll
        for (int nt = 0; nt < 4; nt++) {
            int col = bx + wn * 32 + nt * 8 + (lane & 3) * 2;
            float b0 = bias[col], b1 = bias[col + 1];
            *(float2*)&out[(size_t)r0 * C_ + col] =
                make_float2(acc[mt][nt][0] + b0, acc[mt][nt][1] + b1);
            *(float2*)&out[(size_t)(r0 + 8) * C_ + col] =
                make_float2(acc[mt][nt][2] + b0, acc[mt][nt][3] + b1);
        }
    }
}

// ---------------- launch ----------------
extern "C" void kernel_launch(void* const* d_in, const int* in_sizes, int n_in,
                              void* d_out, int out_size) {
    const float* x     = (const float*)d_in[0];
    const float* Wqkv  = (const float*)d_in[1];
    const float* bqkv  = (const float*)d_in[2];
    const float* Wproj = (const float*)d_in[3];
    const float* bproj = (const float*)d_in[4];
    float* out = (float*)d_out;

    float* attn;
    if ((size_t)out_size >= OUT_ELEMS + ATTN_ELEMS) {
        attn = out + OUT_ELEMS;
    } else {
        void* p = nullptr;
        cudaGetSymbolAddress(&p, g_attn_fallback);
        attn = (float*)p;
    }

    const int FLASH_SMEM_I = (FSTG0 + 2 * FSTGS_I) * 2;   // 92,160 B
    const int FLASH_SMEM_F = (FSTG0 + 2 * FSTGS_F) * 2;   // 110,592 B
    const int GEMM_SMEM    = 2 * QSTG * 2;                // 110,592 B
    cudaFuncSetAttribute(flash_iter_kernel, cudaFuncAttributeMaxDynamicSharedMemorySize, FLASH_SMEM_I);
    cudaFuncSetAttribute(final_flash_kernel, cudaFuncAttributeMaxDynamicSharedMemorySize, FLASH_SMEM_F);
    cudaFuncSetAttribute(qkv_mma_kernel, cudaFuncAttributeMaxDynamicSharedMemorySize, GEMM_SMEM);
    cudaFuncSetAttribute(proj_mma_kernel, cudaFuncAttributeMaxDynamicSharedMemorySize, GEMM_SMEM);

    __nv_bfloat16 *xh, *xl, *wqh, *wql, *wph, *wpl;
    __nv_bfloat16 *k2h_a, *k2l_a, *k2h_b, *k2l_b;
    { void* p; cudaGetSymbolAddress(&p, g_xh);  xh  = (__nv_bfloat16*)p; }
    { void* p; cudaGetSymbolAddress(&p, g_xl);  xl  = (__nv_bfloat16*)p; }
    { void* p; cudaGetSymbolAddress(&p, g_wqh); wqh = (__nv_bfloat16*)p; }
    { void* p; cudaGetSymbolAddress(&p, g_wql); wql = (__nv_bfloat16*)p; }
    { void* p; cudaGetSymbolAddress(&p, g_wph); wph = (__nv_bfloat16*)p; }
    { void* p; cudaGetSymbolAddress(&p, g_wpl); wpl = (__nv_bfloat16*)p; }
    { void* p; cudaGetSymbolAddress(&p, g_k2h_a); k2h_a = (__nv_bfloat16*)p; }
    { void* p; cudaGetSymbolAddress(&p, g_k2l_a); k2l_a = (__nv_bfloat16*)p; }
    { void* p; cudaGetSymbolAddress(&p, g_k2h_b); k2h_b = (__nv_bfloat16*)p; }
    { void* p; cudaGetSymbolAddress(&p, g_k2l_b); k2l_b = (__nv_bfloat16*)p; }

    split_kernel<<<(3145728 + 255) / 256, 256>>>(x, xh, xl, 3145728);
    split_kernel<<<(589824 + 255) / 256, 256>>>(Wqkv, wqh, wql, 589824);
    split_kernel<<<(294912 + 255) / 256, 256>>>(Wproj, wph, wpl, 294912);

    qkv_mma_kernel<<<dim3(TWO_C_ / 64, M_ROWS / 128), 256, GEMM_SMEM>>>(bqkv);
    mu_part_kernel<<<BH_ * 8, 256>>>();
    mu_fin_kernel<<<1, 128>>>();
    k2_init_kernel<<<(int)((KV_ELEMS / 2 + 255) / 256), 256>>>();   // writes buffer A

    __nv_bfloat16* bufs_h[2] = {k2h_a, k2h_b};
    __nv_bfloat16* bufs_l[2] = {k2l_a, k2l_b};
    for (int it = 0; it < 5; ++it) {
        int s = it & 1, d = (it + 1) & 1;
        flash_iter_kernel<<<dim3(N_ / 128, BH_), 256, FLASH_SMEM_I>>>(
            bufs_h[s], bufs_l[s], bufs_h[d], bufs_l[d]);
    }
    final_flash_kernel<<<dim3(N_ / 128, BH_), 256, FLASH_SMEM_F>>>(attn, bufs_h[1], bufs_l[1]);

    proj_mma_kernel<<<dim3(C_ / 64, M_ROWS / 128), 256, GEMM_SMEM>>>(bproj, out);
}